// round 1
// baseline (speedup 1.0000x reference)
#include <cuda_runtime.h>
#include <cuda_bf16.h>
#include <math.h>

// ---------------------------------------------------------------------------
// FractalAttention3D — fused implementation
//   NR=13824 range blocks, ND=1728 domain blocks, E=512, A=256, H=128
//   Feature layout (concatenated, 512 wide): [0:256) repr | [256:384) con | [384:512) off
// ---------------------------------------------------------------------------

#define NR 13824
#define ND 1728
#define E_DIM 512
#define F_DIM 512           // 256 + 128 + 128
#define DF_W 64             // 4*4*4 pooled block
#define LOGIT_SCALE 0.25f   // 1/(sqrt(256)*0.25)
#define INV_SQRT_H 0.08838834764831843f  // 1/sqrt(128)
#define MAX_CONTRAST 1.8f
#define EXP_SHIFT 30.0f

// -------- device scratch (static allocation; no cudaMalloc allowed) --------
__device__ __align__(16) float g_Wr[F_DIM * F_DIM];  // [E][512] range concat weights (scale folded)
__device__ __align__(16) float g_Wd[F_DIM * F_DIM];  // [E][512] domain concat weights
__device__ __align__(16) float g_br[F_DIM];
__device__ __align__(16) float g_bd[F_DIM];
__device__ __align__(16) float g_RF[(size_t)NR * F_DIM];   // range features  [NR][512]
__device__ __align__(16) float g_DT[(size_t)F_DIM * ND];   // domain features [512][ND] (feature-major)

// ---------------------------------------------------------------------------
// Kernel 0: build concatenated weight matrices + biases
// ---------------------------------------------------------------------------
__global__ void prep_weights(
    const float* __restrict__ Wrp, const float* __restrict__ brp,
    const float* __restrict__ Wdp, const float* __restrict__ bdp,
    const float* __restrict__ Wrc, const float* __restrict__ brc,
    const float* __restrict__ Wdc, const float* __restrict__ bdc,
    const float* __restrict__ Wro, const float* __restrict__ bro,
    const float* __restrict__ Wdo, const float* __restrict__ bdo)
{
    int e = blockIdx.x;      // 0..511
    int j = threadIdx.x;     // 0..511
    float wr, wd;
    if (j < 256)      { wr = Wrp[e * 256 + j] * LOGIT_SCALE; wd = Wdp[e * 256 + j]; }
    else if (j < 384) { wr = Wrc[e * 128 + (j - 256)];       wd = Wdc[e * 128 + (j - 256)]; }
    else              { wr = Wro[e * 128 + (j - 384)];       wd = Wdo[e * 128 + (j - 384)]; }
    g_Wr[e * F_DIM + j] = wr;
    g_Wd[e * F_DIM + j] = wd;
    if (e == 0) {
        float br, bd;
        if (j < 256)      { br = brp[j] * LOGIT_SCALE; bd = bdp[j]; }
        else if (j < 384) { br = brc[j - 256];         bd = bdc[j - 256]; }
        else              { br = bro[j - 384];         bd = bdo[j - 384]; }
        g_br[j] = br;
        g_bd[j] = bd;
    }
}

// ---------------------------------------------------------------------------
// Kernel 1: feature GEMM   C[M,512] = (lat + pos)[M,512] @ Wcat[512,512] + bcat
//   RANGE=true : write g_RF[m][n]        (row-major)
//   RANGE=false: write g_DT[n][m]        (feature-major / transposed)
// Tiling: BM=64, BN=64, BK=16, 256 threads, 4x4 micro-tile
// ---------------------------------------------------------------------------
template <bool RANGE>
__global__ void __launch_bounds__(256) feat_gemm(
    const float* __restrict__ lat, const float* __restrict__ pos)
{
    __shared__ float sA[64][17];
    __shared__ float sB[16][64];

    const float* __restrict__ W    = RANGE ? g_Wr : g_Wd;
    const float* __restrict__ bias = RANGE ? g_br : g_bd;

    const int t  = threadIdx.x;
    const int m0 = blockIdx.x * 64;
    const int n0 = blockIdx.y * 64;
    const int ty = t >> 4, tx = t & 15;
    const int arow = t >> 2, ac4 = (t & 3) << 2;
    const int brow = t >> 4, bc4 = (t & 15) << 2;

    float acc[4][4];
#pragma unroll
    for (int i = 0; i < 4; i++)
#pragma unroll
        for (int j = 0; j < 4; j++) acc[i][j] = 0.0f;

    for (int kt = 0; kt < 32; ++kt) {
        const int k0 = kt << 4;
        __syncthreads();
        {
            size_t off = (size_t)(m0 + arow) * E_DIM + k0 + ac4;
            float4 lv = *(const float4*)(lat + off);
            float4 pv = *(const float4*)(pos + off);
            sA[arow][ac4 + 0] = lv.x + pv.x;
            sA[arow][ac4 + 1] = lv.y + pv.y;
            sA[arow][ac4 + 2] = lv.z + pv.z;
            sA[arow][ac4 + 3] = lv.w + pv.w;
            *(float4*)&sB[brow][bc4] =
                *(const float4*)(W + (size_t)(k0 + brow) * F_DIM + n0 + bc4);
        }
        __syncthreads();
#pragma unroll
        for (int k = 0; k < 16; ++k) {
            float a0 = sA[ty * 4 + 0][k], a1 = sA[ty * 4 + 1][k];
            float a2 = sA[ty * 4 + 2][k], a3 = sA[ty * 4 + 3][k];
            float b0 = sB[k][tx * 4 + 0], b1 = sB[k][tx * 4 + 1];
            float b2 = sB[k][tx * 4 + 2], b3 = sB[k][tx * 4 + 3];
            acc[0][0] = fmaf(a0, b0, acc[0][0]); acc[0][1] = fmaf(a0, b1, acc[0][1]);
            acc[0][2] = fmaf(a0, b2, acc[0][2]); acc[0][3] = fmaf(a0, b3, acc[0][3]);
            acc[1][0] = fmaf(a1, b0, acc[1][0]); acc[1][1] = fmaf(a1, b1, acc[1][1]);
            acc[1][2] = fmaf(a1, b2, acc[1][2]); acc[1][3] = fmaf(a1, b3, acc[1][3]);
            acc[2][0] = fmaf(a2, b0, acc[2][0]); acc[2][1] = fmaf(a2, b1, acc[2][1]);
            acc[2][2] = fmaf(a2, b2, acc[2][2]); acc[2][3] = fmaf(a2, b3, acc[2][3]);
            acc[3][0] = fmaf(a3, b0, acc[3][0]); acc[3][1] = fmaf(a3, b1, acc[3][1]);
            acc[3][2] = fmaf(a3, b2, acc[3][2]); acc[3][3] = fmaf(a3, b3, acc[3][3]);
        }
    }

    float bj[4];
#pragma unroll
    for (int j = 0; j < 4; j++) bj[j] = bias[n0 + tx * 4 + j];

    if (RANGE) {
#pragma unroll
        for (int i = 0; i < 4; i++) {
            float4 v;
            v.x = acc[i][0] + bj[0];
            v.y = acc[i][1] + bj[1];
            v.z = acc[i][2] + bj[2];
            v.w = acc[i][3] + bj[3];
            *(float4*)(g_RF + (size_t)(m0 + ty * 4 + i) * F_DIM + n0 + tx * 4) = v;
        }
    } else {
#pragma unroll
        for (int j = 0; j < 4; j++)
#pragma unroll
            for (int i = 0; i < 4; i++)
                g_DT[(size_t)(n0 + tx * 4 + j) * ND + (m0 + ty * 4 + i)] = acc[i][j] + bj[j];
    }
}

// ---------------------------------------------------------------------------
// Kernel 2: fused attention
//   Per CTA: 64 range rows. Loop over 27 ND-tiles of 64:
//     - 64x64x512 GEMM (3 phase-separated accumulators: repr k<256, con 256..383, off 384..511)
//     - postproc: w = exp(l-30), con = tanh*1.8, off = tanh; wc -> smem
//     - epilogue GEMM: out_acc[64][64] += wc @ domain_flat tile
//   Final: row sums via shfl, out = (acc + sum(w*off)) / sum(w)
// ---------------------------------------------------------------------------
__device__ __forceinline__ void attn_gemm_phase(
    float (&acc)[4][4], int kt0, int kt1, int m0, int n0, int t,
    float (*sA)[17], float (*sB)[64])
{
    const int ty = t >> 4, tx = t & 15;
    const int arow = t >> 2, ac4 = (t & 3) << 2;
    const int brow = t >> 4, bc4 = (t & 15) << 2;

    for (int kt = kt0; kt < kt1; ++kt) {
        const int k0 = kt << 4;
        __syncthreads();
        {
            float4 av = *(const float4*)(g_RF + (size_t)(m0 + arow) * F_DIM + k0 + ac4);
            sA[arow][ac4 + 0] = av.x;
            sA[arow][ac4 + 1] = av.y;
            sA[arow][ac4 + 2] = av.z;
            sA[arow][ac4 + 3] = av.w;
            *(float4*)&sB[brow][bc4] =
                *(const float4*)(g_DT + (size_t)(k0 + brow) * ND + n0 + bc4);
        }
        __syncthreads();
#pragma unroll
        for (int k = 0; k < 16; ++k) {
            float a0 = sA[ty * 4 + 0][k], a1 = sA[ty * 4 + 1][k];
            float a2 = sA[ty * 4 + 2][k], a3 = sA[ty * 4 + 3][k];
            float b0 = sB[k][tx * 4 + 0], b1 = sB[k][tx * 4 + 1];
            float b2 = sB[k][tx * 4 + 2], b3 = sB[k][tx * 4 + 3];
            acc[0][0] = fmaf(a0, b0, acc[0][0]); acc[0][1] = fmaf(a0, b1, acc[0][1]);
            acc[0][2] = fmaf(a0, b2, acc[0][2]); acc[0][3] = fmaf(a0, b3, acc[0][3]);
            acc[1][0] = fmaf(a1, b0, acc[1][0]); acc[1][1] = fmaf(a1, b1, acc[1][1]);
            acc[1][2] = fmaf(a1, b2, acc[1][2]); acc[1][3] = fmaf(a1, b3, acc[1][3]);
            acc[2][0] = fmaf(a2, b0, acc[2][0]); acc[2][1] = fmaf(a2, b1, acc[2][1]);
            acc[2][2] = fmaf(a2, b2, acc[2][2]); acc[2][3] = fmaf(a2, b3, acc[2][3]);
            acc[3][0] = fmaf(a3, b0, acc[3][0]); acc[3][1] = fmaf(a3, b1, acc[3][1]);
            acc[3][2] = fmaf(a3, b2, acc[3][2]); acc[3][3] = fmaf(a3, b3, acc[3][3]);
        }
    }
}

__global__ void __launch_bounds__(256, 1) attention_kernel(
    const float* __restrict__ pooled, float* __restrict__ out)
{
    __shared__ float sA[64][17];
    __shared__ float sB[16][64];
    __shared__ float sWC[64][65];
    __shared__ float sDF[64][64];
    __shared__ float sRowW[64];
    __shared__ float sRowWO[64];

    const int t  = threadIdx.x;
    const int m0 = blockIdx.x * 64;
    const int ty = t >> 4, tx = t & 15;
    const int er = t >> 2, ecb = (t & 3) << 4;   // epilogue row / col base

    float out_acc[16];
#pragma unroll
    for (int j = 0; j < 16; j++) out_acc[j] = 0.0f;
    float pw[4]  = {0.f, 0.f, 0.f, 0.f};
    float pwo[4] = {0.f, 0.f, 0.f, 0.f};

    for (int nt = 0; nt < ND / 64; ++nt) {
        const int n0 = nt * 64;

        float accR[4][4], accC[4][4], accO[4][4];
#pragma unroll
        for (int i = 0; i < 4; i++)
#pragma unroll
            for (int j = 0; j < 4; j++) { accR[i][j] = 0.f; accC[i][j] = 0.f; accO[i][j] = 0.f; }

        attn_gemm_phase(accR, 0, 16, m0, n0, t, sA, sB);   // repr  (k 0..255)
        attn_gemm_phase(accC, 16, 24, m0, n0, t, sA, sB);  // con   (k 256..383)
        attn_gemm_phase(accO, 24, 32, m0, n0, t, sA, sB);  // off   (k 384..511)

        // ---- postproc: exp / tanh, stage w*con to smem, accumulate row sums
#pragma unroll
        for (int i = 0; i < 4; i++) {
#pragma unroll
            for (int j = 0; j < 4; j++) {
                float w   = expf(accR[i][j] - EXP_SHIFT);
                float con = tanhf(accC[i][j] * INV_SQRT_H) * MAX_CONTRAST;
                float off = tanhf(accO[i][j] * INV_SQRT_H);
                pw[i]  += w;
                pwo[i] += w * off;
                sWC[ty * 4 + i][tx * 4 + j] = w * con;
            }
        }

        // ---- load domain_flat tile [64][64]
        {
            const float4* src = (const float4*)(pooled + (size_t)(n0 + (t >> 2)) * DF_W + ((t & 3) << 4));
            float4* dst = (float4*)&sDF[t >> 2][(t & 3) << 4];
            dst[0] = src[0]; dst[1] = src[1]; dst[2] = src[2]; dst[3] = src[3];
        }
        __syncthreads();

        // ---- epilogue GEMM: out_acc += wc @ df
        for (int n = 0; n < 64; ++n) {
            float wc = sWC[er][n];
#pragma unroll
            for (int j = 0; j < 16; ++j)
                out_acc[j] = fmaf(wc, sDF[n][ecb + j], out_acc[j]);
        }
        // next iteration's leading __syncthreads (inside attn_gemm_phase)
        // guards sWC/sDF reuse.
    }

    // ---- reduce per-row sums across the 16 threads covering each row
#pragma unroll
    for (int i = 0; i < 4; i++) {
#pragma unroll
        for (int m = 8; m; m >>= 1) {
            pw[i]  += __shfl_xor_sync(0xffffffffu, pw[i], m);
            pwo[i] += __shfl_xor_sync(0xffffffffu, pwo[i], m);
        }
    }
    if (tx == 0) {
#pragma unroll
        for (int i = 0; i < 4; i++) {
            sRowW[ty * 4 + i]  = pw[i];
            sRowWO[ty * 4 + i] = pwo[i];
        }
    }
    __syncthreads();

    const float sw  = sRowW[er];
    const float swo = sRowWO[er];
    const float inv = 1.0f / sw;
#pragma unroll
    for (int j4 = 0; j4 < 4; j4++) {
        float4 v;
        v.x = (out_acc[j4 * 4 + 0] + swo) * inv;
        v.y = (out_acc[j4 * 4 + 1] + swo) * inv;
        v.z = (out_acc[j4 * 4 + 2] + swo) * inv;
        v.w = (out_acc[j4 * 4 + 3] + swo) * inv;
        *(float4*)(out + (size_t)(m0 + er) * DF_W + ecb + j4 * 4) = v;
    }
}

// ---------------------------------------------------------------------------
// kernel_launch
// Input order (metadata): 0 pooled_domains, 1 range_latents, 2 domain_latents,
//   3 range_positional, 4 domain_positional, 5 W_rproj, 6 b_rproj, 7 W_dproj,
//   8 b_dproj, 9 W_rcon, 10 b_rcon, 11 W_dcon, 12 b_dcon, 13 W_roff, 14 b_roff,
//   15 W_doff, 16 b_doff
// ---------------------------------------------------------------------------
extern "C" void kernel_launch(void* const* d_in, const int* in_sizes, int n_in,
                              void* d_out, int out_size)
{
    const float* pooled = (const float*)d_in[0];
    const float* rl     = (const float*)d_in[1];
    const float* dl     = (const float*)d_in[2];
    const float* rp     = (const float*)d_in[3];
    const float* dp     = (const float*)d_in[4];
    const float* Wrp    = (const float*)d_in[5];
    const float* brp    = (const float*)d_in[6];
    const float* Wdp    = (const float*)d_in[7];
    const float* bdp    = (const float*)d_in[8];
    const float* Wrc    = (const float*)d_in[9];
    const float* brc    = (const float*)d_in[10];
    const float* Wdc    = (const float*)d_in[11];
    const float* bdc    = (const float*)d_in[12];
    const float* Wro    = (const float*)d_in[13];
    const float* bro    = (const float*)d_in[14];
    const float* Wdo    = (const float*)d_in[15];
    const float* bdo    = (const float*)d_in[16];
    float* out = (float*)d_out;

    prep_weights<<<512, 512>>>(Wrp, brp, Wdp, bdp, Wrc, brc, Wdc, bdc,
                               Wro, bro, Wdo, bdo);

    dim3 gridD(ND / 64, F_DIM / 64);   // 27 x 8
    feat_gemm<false><<<gridD, 256>>>(dl, dp);

    dim3 gridR(NR / 64, F_DIM / 64);   // 216 x 8
    feat_gemm<true><<<gridR, 256>>>(rl, rp);

    attention_kernel<<<NR / 64, 256>>>(pooled, out);
}

// round 2
// speedup vs baseline: 1.9317x; 1.9317x over previous
#include <cuda_runtime.h>
#include <cuda_bf16.h>
#include <math.h>

// ---------------------------------------------------------------------------
// FractalAttention3D — fused, double-buffered SIMT v2
//   NR=13824, ND=1728, E=512, A=256, H=128
//   Concat feature layout (512): [0:256) repr*0.25 | [256:384) con | [384:512) off
// ---------------------------------------------------------------------------

#define NR 13824
#define ND 1728
#define E_DIM 512
#define F_DIM 512
#define DF_W 64
#define LOGIT_SCALE 0.25f
#define INV_SQRT_H 0.08838834764831843f
#define MAX_CONTRAST 1.8f
#define EXP_SHIFT 30.0f
#define BM_AT 96          // attention M tile -> 13824/96 = 144 CTAs = 1 wave

// -------- device scratch (static; no cudaMalloc allowed) --------
__device__ __align__(16) float g_Wr[F_DIM * F_DIM];
__device__ __align__(16) float g_Wd[F_DIM * F_DIM];
__device__ __align__(16) float g_br[F_DIM];
__device__ __align__(16) float g_bd[F_DIM];
__device__ __align__(16) float g_RF[(size_t)NR * F_DIM];   // range features  [NR][512]
__device__ __align__(16) float g_DT[(size_t)F_DIM * ND];   // domain features [512][ND]

__device__ __forceinline__ float fast_tanh(float x) {
    // tanh(x) = 2/(1+e^{-2x}) - 1 ; MUFU-based, rel err ~1e-6
    float e = __expf(-2.0f * x);
    return __fdividef(2.0f, e + 1.0f) - 1.0f;
}

// ---------------------------------------------------------------------------
// Kernel 0: build concatenated weight matrices + biases
// ---------------------------------------------------------------------------
__global__ void prep_weights(
    const float* __restrict__ Wrp, const float* __restrict__ brp,
    const float* __restrict__ Wdp, const float* __restrict__ bdp,
    const float* __restrict__ Wrc, const float* __restrict__ brc,
    const float* __restrict__ Wdc, const float* __restrict__ bdc,
    const float* __restrict__ Wro, const float* __restrict__ bro,
    const float* __restrict__ Wdo, const float* __restrict__ bdo)
{
    int e = blockIdx.x;      // 0..511
    int j = threadIdx.x;     // 0..511
    float wr, wd;
    if (j < 256)      { wr = Wrp[e * 256 + j] * LOGIT_SCALE; wd = Wdp[e * 256 + j]; }
    else if (j < 384) { wr = Wrc[e * 128 + (j - 256)];       wd = Wdc[e * 128 + (j - 256)]; }
    else              { wr = Wro[e * 128 + (j - 384)];       wd = Wdo[e * 128 + (j - 384)]; }
    g_Wr[e * F_DIM + j] = wr;
    g_Wd[e * F_DIM + j] = wd;
    if (e == 0) {
        float br, bd;
        if (j < 256)      { br = brp[j] * LOGIT_SCALE; bd = bdp[j]; }
        else if (j < 384) { br = brc[j - 256];         bd = bdc[j - 256]; }
        else              { br = bro[j - 384];         bd = bdo[j - 384]; }
        g_br[j] = br;
        g_bd[j] = bd;
    }
}

// ---------------------------------------------------------------------------
// Kernel 1: feature GEMM (double-buffered, k-major smem A)
//   C[M,512] = (lat+pos)[M,512] @ Wcat[512,512] + bcat
// ---------------------------------------------------------------------------
template <bool RANGE>
__global__ void __launch_bounds__(256) feat_gemm(
    const float* __restrict__ lat, const float* __restrict__ pos)
{
    __shared__ float sA[2][16][64];   // k-major
    __shared__ float sB[2][16][64];

    const float* __restrict__ W    = RANGE ? g_Wr : g_Wd;
    const float* __restrict__ bias = RANGE ? g_br : g_bd;

    const int t  = threadIdx.x;
    const int m0 = blockIdx.x * 64;
    const int n0 = blockIdx.y * 64;
    const int ty4 = (t >> 4) * 4, tx4 = (t & 15) * 4;
    const int ar = t >> 2, ak = (t & 3) << 2;
    const int br = t >> 4, bc = (t & 15) << 2;

    const float* aL = lat + (size_t)(m0 + ar) * E_DIM + ak;
    const float* aP = pos + (size_t)(m0 + ar) * E_DIM + ak;
    const float* bW = W + (size_t)br * F_DIM + n0 + bc;

    float acc[4][4];
#pragma unroll
    for (int i = 0; i < 4; i++)
#pragma unroll
        for (int j = 0; j < 4; j++) acc[i][j] = 0.0f;

    // prologue
    float4 la = *(const float4*)aL;
    float4 pa = *(const float4*)aP;
    float4 bv = *(const float4*)bW;
    sA[0][ak + 0][ar] = la.x + pa.x;
    sA[0][ak + 1][ar] = la.y + pa.y;
    sA[0][ak + 2][ar] = la.z + pa.z;
    sA[0][ak + 3][ar] = la.w + pa.w;
    *(float4*)&sB[0][br][bc] = bv;
    __syncthreads();

    int buf = 0;
#pragma unroll 1
    for (int kt = 0; kt < 32; ++kt) {
        if (kt < 31) {
            la = *(const float4*)(aL + (kt + 1) * 16);
            pa = *(const float4*)(aP + (kt + 1) * 16);
            bv = *(const float4*)(bW + (size_t)(kt + 1) * 16 * F_DIM);
        }
#pragma unroll
        for (int k = 0; k < 16; ++k) {
            float4 a = *(const float4*)&sA[buf][k][ty4];
            float4 b = *(const float4*)&sB[buf][k][tx4];
            acc[0][0] = fmaf(a.x, b.x, acc[0][0]); acc[0][1] = fmaf(a.x, b.y, acc[0][1]);
            acc[0][2] = fmaf(a.x, b.z, acc[0][2]); acc[0][3] = fmaf(a.x, b.w, acc[0][3]);
            acc[1][0] = fmaf(a.y, b.x, acc[1][0]); acc[1][1] = fmaf(a.y, b.y, acc[1][1]);
            acc[1][2] = fmaf(a.y, b.z, acc[1][2]); acc[1][3] = fmaf(a.y, b.w, acc[1][3]);
            acc[2][0] = fmaf(a.z, b.x, acc[2][0]); acc[2][1] = fmaf(a.z, b.y, acc[2][1]);
            acc[2][2] = fmaf(a.z, b.z, acc[2][2]); acc[2][3] = fmaf(a.z, b.w, acc[2][3]);
            acc[3][0] = fmaf(a.w, b.x, acc[3][0]); acc[3][1] = fmaf(a.w, b.y, acc[3][1]);
            acc[3][2] = fmaf(a.w, b.z, acc[3][2]); acc[3][3] = fmaf(a.w, b.w, acc[3][3]);
        }
        if (kt < 31) {
            int nb = buf ^ 1;
            sA[nb][ak + 0][ar] = la.x + pa.x;
            sA[nb][ak + 1][ar] = la.y + pa.y;
            sA[nb][ak + 2][ar] = la.z + pa.z;
            sA[nb][ak + 3][ar] = la.w + pa.w;
            *(float4*)&sB[nb][br][bc] = bv;
        }
        buf ^= 1;
        __syncthreads();
    }

    float bj[4];
#pragma unroll
    for (int j = 0; j < 4; j++) bj[j] = bias[n0 + tx4 + j];

    if (RANGE) {
#pragma unroll
        for (int i = 0; i < 4; i++) {
            float4 v;
            v.x = acc[i][0] + bj[0];
            v.y = acc[i][1] + bj[1];
            v.z = acc[i][2] + bj[2];
            v.w = acc[i][3] + bj[3];
            *(float4*)(g_RF + (size_t)(m0 + ty4 + i) * F_DIM + n0 + tx4) = v;
        }
    } else {
#pragma unroll
        for (int j = 0; j < 4; j++)
#pragma unroll
            for (int i = 0; i < 4; i++)
                g_DT[(size_t)(n0 + tx4 + j) * ND + (m0 + ty4 + i)] = acc[i][j] + bj[j];
    }
}

// ---------------------------------------------------------------------------
// Kernel 2: fused attention, BM=96 x BN=64, double-buffered, phase-sequential
// ---------------------------------------------------------------------------
struct AttnSmem {
    float sA[2][16][BM_AT];   // k-major range features
    float sB[2][16][64];      // k-major domain features
    float sC[BM_AT][65];      // con -> then w*con (epilogue operand)
    float sO[BM_AT][65];      // off
    float sDF[64][64];        // pooled domain tile
};

__device__ __forceinline__ void gemm_tile96(
    float (&acc)[6][4], AttnSmem* s,
    const float* __restrict__ aBase, const float* __restrict__ bBase,
    int nkt, int t)
{
    const int ty6 = (t >> 4) * 6, tx4 = (t & 15) * 4;
    const int rA = t >> 3, kq = (t & 7) * 2;          // A loader: rows rA,rA+32,rA+64 @ k kq,kq+1
    const int brB = t >> 4, bcB = (t & 15) * 4;       // B loader

    float2 a0 = *(const float2*)aBase;
    float2 a1 = *(const float2*)(aBase + (size_t)32 * F_DIM);
    float2 a2 = *(const float2*)(aBase + (size_t)64 * F_DIM);
    float4 bv = *(const float4*)bBase;
    s->sA[0][kq][rA]      = a0.x;  s->sA[0][kq + 1][rA]      = a0.y;
    s->sA[0][kq][rA + 32] = a1.x;  s->sA[0][kq + 1][rA + 32] = a1.y;
    s->sA[0][kq][rA + 64] = a2.x;  s->sA[0][kq + 1][rA + 64] = a2.y;
    *(float4*)&s->sB[0][brB][bcB] = bv;
    __syncthreads();

    int buf = 0;
#pragma unroll 1
    for (int kt = 0; kt < nkt; ++kt) {
        if (kt + 1 < nkt) {
            const float* ap = aBase + (kt + 1) * 16;
            a0 = *(const float2*)ap;
            a1 = *(const float2*)(ap + (size_t)32 * F_DIM);
            a2 = *(const float2*)(ap + (size_t)64 * F_DIM);
            bv = *(const float4*)(bBase + (size_t)(kt + 1) * 16 * ND);
        }
#pragma unroll
        for (int k = 0; k < 16; ++k) {
            float4 b  = *(const float4*)&s->sB[buf][k][tx4];
            float2 x0 = *(const float2*)&s->sA[buf][k][ty6];
            float2 x1 = *(const float2*)&s->sA[buf][k][ty6 + 2];
            float2 x2 = *(const float2*)&s->sA[buf][k][ty6 + 4];
            float av[6] = {x0.x, x0.y, x1.x, x1.y, x2.x, x2.y};
#pragma unroll
            for (int i = 0; i < 6; i++) {
                acc[i][0] = fmaf(av[i], b.x, acc[i][0]);
                acc[i][1] = fmaf(av[i], b.y, acc[i][1]);
                acc[i][2] = fmaf(av[i], b.z, acc[i][2]);
                acc[i][3] = fmaf(av[i], b.w, acc[i][3]);
            }
        }
        if (kt + 1 < nkt) {
            int nb = buf ^ 1;
            s->sA[nb][kq][rA]      = a0.x;  s->sA[nb][kq + 1][rA]      = a0.y;
            s->sA[nb][kq][rA + 32] = a1.x;  s->sA[nb][kq + 1][rA + 32] = a1.y;
            s->sA[nb][kq][rA + 64] = a2.x;  s->sA[nb][kq + 1][rA + 64] = a2.y;
            *(float4*)&s->sB[nb][brB][bcB] = bv;
        }
        buf ^= 1;
        __syncthreads();
    }
}

__global__ void __launch_bounds__(256, 1) attention_kernel(
    const float* __restrict__ pooled, float* __restrict__ out)
{
    extern __shared__ char smem_raw[];
    AttnSmem* s = (AttnSmem*)smem_raw;

    const int t  = threadIdx.x;
    const int m0 = blockIdx.x * BM_AT;
    const int ty6 = (t >> 4) * 6, tx4 = (t & 15) * 4;
    const int rA = t >> 3, kq = (t & 7) * 2;
    const int brB = t >> 4, bcB = (t & 15) * 4;

    float out_acc[6][4];
#pragma unroll
    for (int i = 0; i < 6; i++)
#pragma unroll
        for (int j = 0; j < 4; j++) out_acc[i][j] = 0.0f;
    float pw[6]  = {0.f, 0.f, 0.f, 0.f, 0.f, 0.f};
    float pwo[6] = {0.f, 0.f, 0.f, 0.f, 0.f, 0.f};

    const float* aR = g_RF + (size_t)(m0 + rA) * F_DIM + kq;

    for (int nt = 0; nt < ND / 64; ++nt) {
        const int n0 = nt * 64;
        const float* bB = g_DT + (size_t)brB * ND + n0 + bcB;

        float acc[6][4];

        // ---- phase CON: k in [256, 384)
#pragma unroll
        for (int i = 0; i < 6; i++)
#pragma unroll
            for (int j = 0; j < 4; j++) acc[i][j] = 0.0f;
        gemm_tile96(acc, s, aR + 256, bB + (size_t)256 * ND, 8, t);
#pragma unroll
        for (int i = 0; i < 6; i++)
#pragma unroll
            for (int j = 0; j < 4; j++)
                s->sC[ty6 + i][tx4 + j] = fast_tanh(acc[i][j] * INV_SQRT_H) * MAX_CONTRAST;

        // ---- phase OFF: k in [384, 512)
#pragma unroll
        for (int i = 0; i < 6; i++)
#pragma unroll
            for (int j = 0; j < 4; j++) acc[i][j] = 0.0f;
        gemm_tile96(acc, s, aR + 384, bB + (size_t)384 * ND, 8, t);
#pragma unroll
        for (int i = 0; i < 6; i++)
#pragma unroll
            for (int j = 0; j < 4; j++)
                s->sO[ty6 + i][tx4 + j] = fast_tanh(acc[i][j] * INV_SQRT_H);

        // ---- phase REPR: k in [0, 256)
#pragma unroll
        for (int i = 0; i < 6; i++)
#pragma unroll
            for (int j = 0; j < 4; j++) acc[i][j] = 0.0f;
        gemm_tile96(acc, s, aR, bB, 16, t);

        // ---- combine: w = exp(l-30); stage w*con; accumulate row sums
#pragma unroll
        for (int i = 0; i < 6; i++) {
#pragma unroll
            for (int j = 0; j < 4; j++) {
                float w   = __expf(acc[i][j] - EXP_SHIFT);
                float off = s->sO[ty6 + i][tx4 + j];
                float con = s->sC[ty6 + i][tx4 + j];
                pw[i]  += w;
                pwo[i] += w * off;
                s->sC[ty6 + i][tx4 + j] = w * con;
            }
        }

        // ---- load pooled tile [64][64]
        {
            int r = t >> 2, c = (t & 3) << 4;
            const float4* src = (const float4*)(pooled + (size_t)(n0 + r) * DF_W + c);
            float4* dst = (float4*)&s->sDF[r][c];
            dst[0] = src[0]; dst[1] = src[1]; dst[2] = src[2]; dst[3] = src[3];
        }
        __syncthreads();

        // ---- epilogue: out_acc += (w*con) @ df
#pragma unroll 4
        for (int n = 0; n < 64; ++n) {
            float4 df = *(const float4*)&s->sDF[n][tx4];
#pragma unroll
            for (int i = 0; i < 6; i++) {
                float wc = s->sC[ty6 + i][n];
                out_acc[i][0] = fmaf(wc, df.x, out_acc[i][0]);
                out_acc[i][1] = fmaf(wc, df.y, out_acc[i][1]);
                out_acc[i][2] = fmaf(wc, df.z, out_acc[i][2]);
                out_acc[i][3] = fmaf(wc, df.w, out_acc[i][3]);
            }
        }
        // no trailing sync needed: next phase's gemm prologue only touches
        // sA/sB and syncs before anything reads them; sC/sO/sDF are next
        // written long after that barrier.
    }

    // ---- row reductions across the 16 threads of each row (within 16-lane groups)
#pragma unroll
    for (int i = 0; i < 6; i++) {
#pragma unroll
        for (int m = 8; m; m >>= 1) {
            pw[i]  += __shfl_xor_sync(0xffffffffu, pw[i], m);
            pwo[i] += __shfl_xor_sync(0xffffffffu, pwo[i], m);
        }
    }

#pragma unroll
    for (int i = 0; i < 6; i++) {
        float inv = 1.0f / pw[i];
        float4 v;
        v.x = (out_acc[i][0] + pwo[i]) * inv;
        v.y = (out_acc[i][1] + pwo[i]) * inv;
        v.z = (out_acc[i][2] + pwo[i]) * inv;
        v.w = (out_acc[i][3] + pwo[i]) * inv;
        *(float4*)(out + (size_t)(m0 + ty6 + i) * DF_W + tx4) = v;
    }
}

// ---------------------------------------------------------------------------
// kernel_launch
// ---------------------------------------------------------------------------
extern "C" void kernel_launch(void* const* d_in, const int* in_sizes, int n_in,
                              void* d_out, int out_size)
{
    const float* pooled = (const float*)d_in[0];
    const float* rl     = (const float*)d_in[1];
    const float* dl     = (const float*)d_in[2];
    const float* rp     = (const float*)d_in[3];
    const float* dp     = (const float*)d_in[4];
    const float* Wrp    = (const float*)d_in[5];
    const float* brp    = (const float*)d_in[6];
    const float* Wdp    = (const float*)d_in[7];
    const float* bdp    = (const float*)d_in[8];
    const float* Wrc    = (const float*)d_in[9];
    const float* brc    = (const float*)d_in[10];
    const float* Wdc    = (const float*)d_in[11];
    const float* bdc    = (const float*)d_in[12];
    const float* Wro    = (const float*)d_in[13];
    const float* bro    = (const float*)d_in[14];
    const float* Wdo    = (const float*)d_in[15];
    const float* bdo    = (const float*)d_in[16];
    float* out = (float*)d_out;

    prep_weights<<<512, 512>>>(Wrp, brp, Wdp, bdp, Wrc, brc, Wdc, bdc,
                               Wro, bro, Wdo, bdo);

    dim3 gridD(ND / 64, F_DIM / 64);   // 27 x 8
    feat_gemm<false><<<gridD, 256>>>(dl, dp);

    dim3 gridR(NR / 64, F_DIM / 64);   // 216 x 8
    feat_gemm<true><<<gridR, 256>>>(rl, rp);

    int smem = (int)sizeof(AttnSmem);
    cudaFuncSetAttribute(attention_kernel,
                         cudaFuncAttributeMaxDynamicSharedMemorySize, smem);
    attention_kernel<<<NR / BM_AT, 256, smem>>>(pooled, out);
}

// round 4
// speedup vs baseline: 3.4012x; 1.7607x over previous
#include <cuda_runtime.h>
#include <cuda_bf16.h>
#include <cstdint>
#include <math.h>

// ---------------------------------------------------------------------------
// FractalAttention3D — mma.sync bf16 (2-way split, 3 products) fused attention
//   Family-portable PTX only (sm_80+ features): mma.sync / ldmatrix / cp.async.
//   NR=13824, ND=1728, E=512; feature layout (512):
//     [0:256) repr*0.25 | [256:384) con | [384:512) off
// ---------------------------------------------------------------------------

#define NR 13824
#define ND 1728
#define E_DIM 512
#define F_DIM 512
#define DF_W 64
#define LOGIT_SCALE 0.25f
#define INV_SQRT_H 0.08838834764831843f
#define MAX_CONTRAST 1.8f
#define EXP_SHIFT 30.0f

#define BM 96                 // 13824/96 = 144 CTAs ~ one wave
#define BN 64
#define KC 64                 // k per stage
#define NTILES (ND / BN)      // 27
#define NSTG 8                // stages per tile (2 con + 2 off + 4 repr)
#define NTHREADS 192          // 6 warps (3 x 2 grid of 32x32)

// -------- device scratch (static; no cudaMalloc allowed) --------
__device__ __align__(16) float g_Wr[F_DIM * F_DIM];
__device__ __align__(16) float g_Wd[F_DIM * F_DIM];
__device__ __align__(16) float g_br[F_DIM];
__device__ __align__(16) float g_bd[F_DIM];
__device__ __align__(16) __nv_bfloat16 g_RFh[(size_t)NR * F_DIM];
__device__ __align__(16) __nv_bfloat16 g_RFl[(size_t)NR * F_DIM];
__device__ __align__(16) __nv_bfloat16 g_DFh[(size_t)ND * F_DIM];
__device__ __align__(16) __nv_bfloat16 g_DFl[(size_t)ND * F_DIM];
__device__ __align__(16) __nv_bfloat16 g_PDth[(size_t)DF_W * ND];  // pooled^T hi [64][1728]
__device__ __align__(16) __nv_bfloat16 g_PDtl[(size_t)DF_W * ND];  // pooled^T lo

// ---------------- smem layout (bytes) ----------------
// A stage: [buf][hl][96][72] bf16 ; B stage: [buf][hl][64][72] bf16
#define AST 13824            // 96*72*2
#define BST 9216             // 64*72*2
#define SM_A  0              // 4*AST = 55296
#define SM_B  55296          // 4*BST = 36864
#define SM_WCH 92160         // 96*72*2 = 13824
#define SM_WCL 105984
#define SM_DFH 119808        // 64*72*2 = 9216
#define SM_DFL 129024
#define SM_C  138240         // 96*68*4 = 26112 (con, f32)
#define SM_O  164352         // 26112 (off, f32)
#define SM_RW 190464         // 2*96*4
#define SM_RO 191232
#define SM_TOTAL 192000

// ---------------- PTX helpers (sm_80-portable) ----------------
__device__ __forceinline__ uint32_t smem_u32(const void* p) {
    uint32_t a;
    asm("{ .reg .u64 t; cvta.to.shared.u64 t, %1; cvt.u32.u64 %0, t; }" : "=r"(a) : "l"(p));
    return a;
}
__device__ __forceinline__ void cp16(uint32_t dst, const void* src) {
    asm volatile("cp.async.cg.shared.global [%0], [%1], 16;" :: "r"(dst), "l"(src));
}
#define CP_COMMIT() asm volatile("cp.async.commit_group;" ::: "memory")
#define CP_WAIT1()  asm volatile("cp.async.wait_group 1;" ::: "memory")
#define CP_WAIT0()  asm volatile("cp.async.wait_group 0;" ::: "memory")

__device__ __forceinline__ void ldsm4(uint32_t& r0, uint32_t& r1, uint32_t& r2, uint32_t& r3,
                                      uint32_t addr) {
    asm volatile("ldmatrix.sync.aligned.m8n8.x4.shared.b16 {%0,%1,%2,%3}, [%4];"
                 : "=r"(r0), "=r"(r1), "=r"(r2), "=r"(r3) : "r"(addr));
}
__device__ __forceinline__ void mma_bf16(float* c, const uint32_t* a, uint32_t b0, uint32_t b1) {
    asm("mma.sync.aligned.m16n8k16.row.col.f32.bf16.bf16.f32 "
        "{%0,%1,%2,%3}, {%4,%5,%6,%7}, {%8,%9}, {%0,%1,%2,%3};"
        : "+f"(c[0]), "+f"(c[1]), "+f"(c[2]), "+f"(c[3])
        : "r"(a[0]), "r"(a[1]), "r"(a[2]), "r"(a[3]), "r"(b0), "r"(b1));
}
__device__ __forceinline__ float fast_tanh(float x) {
    float e = __expf(-2.0f * x);
    return __fdividef(2.0f, e + 1.0f) - 1.0f;
}

// ---------------------------------------------------------------------------
// Kernel 0a: concatenated weights + biases (logit scale folded into range side)
// ---------------------------------------------------------------------------
__global__ void prep_weights(
    const float* __restrict__ Wrp, const float* __restrict__ brp,
    const float* __restrict__ Wdp, const float* __restrict__ bdp,
    const float* __restrict__ Wrc, const float* __restrict__ brc,
    const float* __restrict__ Wdc, const float* __restrict__ bdc,
    const float* __restrict__ Wro, const float* __restrict__ bro,
    const float* __restrict__ Wdo, const float* __restrict__ bdo)
{
    int e = blockIdx.x, j = threadIdx.x;
    float wr, wd;
    if (j < 256)      { wr = Wrp[e * 256 + j] * LOGIT_SCALE; wd = Wdp[e * 256 + j]; }
    else if (j < 384) { wr = Wrc[e * 128 + (j - 256)];       wd = Wdc[e * 128 + (j - 256)]; }
    else              { wr = Wro[e * 128 + (j - 384)];       wd = Wdo[e * 128 + (j - 384)]; }
    g_Wr[e * F_DIM + j] = wr;
    g_Wd[e * F_DIM + j] = wd;
    if (e == 0) {
        float br, bd;
        if (j < 256)      { br = brp[j] * LOGIT_SCALE; bd = bdp[j]; }
        else if (j < 384) { br = brc[j - 256];         bd = bdc[j - 256]; }
        else              { br = bro[j - 384];         bd = bdo[j - 384]; }
        g_br[j] = br;
        g_bd[j] = bd;
    }
}

// Kernel 0b: pooled_domains^T with bf16 hi/lo split: PDt[d][n]
__global__ void prep_pd(const float* __restrict__ pooled) {
    int n = blockIdx.x, d = threadIdx.x;
    float v = pooled[(size_t)n * DF_W + d];
    __nv_bfloat16 h = __float2bfloat16(v);
    float l = v - __bfloat162float(h);
    g_PDth[(size_t)d * ND + n] = h;
    g_PDtl[(size_t)d * ND + n] = __float2bfloat16(l);
}

// ---------------------------------------------------------------------------
// Kernel 1: feature GEMM -> bf16 hi/lo split panels (row-major [M][512])
// ---------------------------------------------------------------------------
template <bool RANGE>
__global__ void __launch_bounds__(256) feat_gemm(
    const float* __restrict__ lat, const float* __restrict__ pos)
{
    __shared__ float sA[2][16][64];
    __shared__ float sB[2][16][64];

    const float* __restrict__ W    = RANGE ? g_Wr : g_Wd;
    const float* __restrict__ bias = RANGE ? g_br : g_bd;
    __nv_bfloat16* __restrict__ OH = RANGE ? g_RFh : g_DFh;
    __nv_bfloat16* __restrict__ OL = RANGE ? g_RFl : g_DFl;

    const int t  = threadIdx.x;
    const int m0 = blockIdx.x * 64;
    const int n0 = blockIdx.y * 64;
    const int ty4 = (t >> 4) * 4, tx4 = (t & 15) * 4;
    const int ar = t >> 2, ak = (t & 3) << 2;
    const int br = t >> 4, bc = (t & 15) << 2;

    const float* aL = lat + (size_t)(m0 + ar) * E_DIM + ak;
    const float* aP = pos + (size_t)(m0 + ar) * E_DIM + ak;
    const float* bW = W + (size_t)br * F_DIM + n0 + bc;

    float acc[4][4];
#pragma unroll
    for (int i = 0; i < 4; i++)
#pragma unroll
        for (int j = 0; j < 4; j++) acc[i][j] = 0.0f;

    float4 la = *(const float4*)aL;
    float4 pa = *(const float4*)aP;
    float4 bv = *(const float4*)bW;
    sA[0][ak + 0][ar] = la.x + pa.x;
    sA[0][ak + 1][ar] = la.y + pa.y;
    sA[0][ak + 2][ar] = la.z + pa.z;
    sA[0][ak + 3][ar] = la.w + pa.w;
    *(float4*)&sB[0][br][bc] = bv;
    __syncthreads();

    int buf = 0;
#pragma unroll 1
    for (int kt = 0; kt < 32; ++kt) {
        if (kt < 31) {
            la = *(const float4*)(aL + (kt + 1) * 16);
            pa = *(const float4*)(aP + (kt + 1) * 16);
            bv = *(const float4*)(bW + (size_t)(kt + 1) * 16 * F_DIM);
        }
#pragma unroll
        for (int k = 0; k < 16; ++k) {
            float4 a = *(const float4*)&sA[buf][k][ty4];
            float4 b = *(const float4*)&sB[buf][k][tx4];
            acc[0][0] = fmaf(a.x, b.x, acc[0][0]); acc[0][1] = fmaf(a.x, b.y, acc[0][1]);
            acc[0][2] = fmaf(a.x, b.z, acc[0][2]); acc[0][3] = fmaf(a.x, b.w, acc[0][3]);
            acc[1][0] = fmaf(a.y, b.x, acc[1][0]); acc[1][1] = fmaf(a.y, b.y, acc[1][1]);
            acc[1][2] = fmaf(a.y, b.z, acc[1][2]); acc[1][3] = fmaf(a.y, b.w, acc[1][3]);
            acc[2][0] = fmaf(a.z, b.x, acc[2][0]); acc[2][1] = fmaf(a.z, b.y, acc[2][1]);
            acc[2][2] = fmaf(a.z, b.z, acc[2][2]); acc[2][3] = fmaf(a.z, b.w, acc[2][3]);
            acc[3][0] = fmaf(a.w, b.x, acc[3][0]); acc[3][1] = fmaf(a.w, b.y, acc[3][1]);
            acc[3][2] = fmaf(a.w, b.z, acc[3][2]); acc[3][3] = fmaf(a.w, b.w, acc[3][3]);
        }
        if (kt < 31) {
            int nb = buf ^ 1;
            sA[nb][ak + 0][ar] = la.x + pa.x;
            sA[nb][ak + 1][ar] = la.y + pa.y;
            sA[nb][ak + 2][ar] = la.z + pa.z;
            sA[nb][ak + 3][ar] = la.w + pa.w;
            *(float4*)&sB[nb][br][bc] = bv;
        }
        buf ^= 1;
        __syncthreads();
    }

    float bj[4];
#pragma unroll
    for (int j = 0; j < 4; j++) bj[j] = bias[n0 + tx4 + j];

#pragma unroll
    for (int i = 0; i < 4; i++) {
        __nv_bfloat16 hb[4], lb[4];
#pragma unroll
        for (int j = 0; j < 4; j++) {
            float v = acc[i][j] + bj[j];
            __nv_bfloat16 h = __float2bfloat16(v);
            hb[j] = h;
            lb[j] = __float2bfloat16(v - __bfloat162float(h));
        }
        size_t off = (size_t)(m0 + ty4 + i) * F_DIM + n0 + tx4;
        *(uint2*)(OH + off) = *(uint2*)hb;
        *(uint2*)(OL + off) = *(uint2*)lb;
    }
}

// ---------------------------------------------------------------------------
// Kernel 2: fused attention (mma.sync bf16, cp.async double-buffered)
// ---------------------------------------------------------------------------

// stage -> k offset: 2 con, 2 off, 4 repr
__device__ __forceinline__ int stage_koff(int s) {
    return (s < 4) ? (256 + s * 64) : ((s - 4) * 64);
}

__device__ __forceinline__ void load_stage(uint32_t sb0, int gs, int m0, int t) {
    const int s = gs & 7;
    const int nt = gs >> 3;
    const int koff = stage_koff(s);
    const int n0 = nt * BN;
    const int buf = gs & 1;
    const uint32_t aH = sb0 + SM_A + (buf * 2 + 0) * AST;
    const uint32_t aL = sb0 + SM_A + (buf * 2 + 1) * AST;
#pragma unroll
    for (int c = t; c < 768; c += NTHREADS) {          // 96 rows x 8 chunks
        int row = c >> 3, k8 = (c & 7) * 8;
        uint32_t so = (uint32_t)(row * 144 + k8 * 2);
        size_t go = (size_t)(m0 + row) * F_DIM + koff + k8;
        cp16(aH + so, g_RFh + go);
        cp16(aL + so, g_RFl + go);
    }
    const uint32_t bH = sb0 + SM_B + (buf * 2 + 0) * BST;
    const uint32_t bL = sb0 + SM_B + (buf * 2 + 1) * BST;
#pragma unroll
    for (int c = t; c < 512; c += NTHREADS) {          // 64 rows x 8 chunks
        int row = c >> 3, k8 = (c & 7) * 8;
        uint32_t so = (uint32_t)(row * 144 + k8 * 2);
        size_t go = (size_t)(n0 + row) * F_DIM + koff + k8;
        cp16(bH + so, g_DFh + go);
        cp16(bL + so, g_DFl + go);
    }
}

__device__ __forceinline__ void load_df(uint32_t sb0, int nt, int t) {
    const int n0 = nt * BN;
#pragma unroll
    for (int c = t; c < 512; c += NTHREADS) {          // 64 d-rows x 8 chunks
        int row = c >> 3, k8 = (c & 7) * 8;
        uint32_t so = (uint32_t)(row * 144 + k8 * 2);
        size_t go = (size_t)row * ND + n0 + k8;
        cp16(sb0 + SM_DFH + so, g_PDth + go);
        cp16(sb0 + SM_DFL + so, g_PDtl + go);
    }
}

// 96x64x64 MMA stage: A from [aH,aL] (stride 144B), B from [bH,bL]
__device__ __forceinline__ void mma_stage(
    float (&acc)[2][4][4], uint32_t aH, uint32_t aL, uint32_t bH, uint32_t bL,
    int mrow0, int ncol0, int l)
{
    const uint32_t aRowOff = (uint32_t)((l & 15) * 144) + (uint32_t)((l >> 4) * 16);
    const uint32_t bRowOff = (uint32_t)((((l >> 4) & 1) * 8 + (l & 7)) * 144)
                           + (uint32_t)(((l >> 3) & 1) * 16);
#pragma unroll
    for (int k16 = 0; k16 < 4; k16++) {
        uint32_t ah[2][4], al[2][4], bh[2][4], bl[2][4];
        const uint32_t kb = (uint32_t)(k16 * 32);
#pragma unroll
        for (int mt = 0; mt < 2; mt++) {
            uint32_t off = (uint32_t)((mrow0 + mt * 16) * 144) + aRowOff + kb;
            ldsm4(ah[mt][0], ah[mt][1], ah[mt][2], ah[mt][3], aH + off);
            ldsm4(al[mt][0], al[mt][1], al[mt][2], al[mt][3], aL + off);
        }
#pragma unroll
        for (int np = 0; np < 2; np++) {
            uint32_t off = (uint32_t)((ncol0 + np * 16) * 144) + bRowOff + kb;
            ldsm4(bh[np][0], bh[np][1], bh[np][2], bh[np][3], bH + off);
            ldsm4(bl[np][0], bl[np][1], bl[np][2], bl[np][3], bL + off);
        }
#pragma unroll
        for (int mt = 0; mt < 2; mt++)
#pragma unroll
            for (int ntl = 0; ntl < 4; ntl++) {
                const int np = ntl >> 1, ri = (ntl & 1) * 2;
                mma_bf16(acc[mt][ntl], ah[mt], bh[np][ri], bh[np][ri + 1]);
                mma_bf16(acc[mt][ntl], ah[mt], bl[np][ri], bl[np][ri + 1]);
                mma_bf16(acc[mt][ntl], al[mt], bh[np][ri], bh[np][ri + 1]);
            }
    }
}

__global__ void __launch_bounds__(NTHREADS, 1) attention_kernel(float* __restrict__ out)
{
    extern __shared__ char smem[];
    const uint32_t sb0 = smem_u32(smem);

    const int t = threadIdx.x;
    const int w = t >> 5, l = t & 31;
    const int m0 = blockIdx.x * BM;
    const int mrow0 = (w >> 1) * 32;     // 0/32/64
    const int ncol0 = (w & 1) * 32;      // 0/32

    float* sC = (float*)(smem + SM_C);
    float* sO = (float*)(smem + SM_O);
    __nv_bfloat16* sWCh = (__nv_bfloat16*)(smem + SM_WCH);
    __nv_bfloat16* sWCl = (__nv_bfloat16*)(smem + SM_WCL);
    float* sRW = (float*)(smem + SM_RW);
    float* sRO = (float*)(smem + SM_RO);

    float ep[2][4][4];
#pragma unroll
    for (int i = 0; i < 2; i++)
#pragma unroll
        for (int j = 0; j < 4; j++)
#pragma unroll
            for (int r = 0; r < 4; r++) ep[i][j][r] = 0.0f;
    float pw[4]  = {0.f, 0.f, 0.f, 0.f};
    float pwo[4] = {0.f, 0.f, 0.f, 0.f};

    load_stage(sb0, 0, m0, t);
    CP_COMMIT();

#pragma unroll 1
    for (int nt = 0; nt < NTILES; ++nt) {
        float acc[2][4][4];

#pragma unroll 1
        for (int s = 0; s < NSTG; ++s) {
            const int gs = nt * NSTG + s;
            const bool haveNext = (gs + 1 < NTILES * NSTG);
            if (s == NSTG - 1) { load_df(sb0, nt, t); CP_COMMIT(); }
            if (haveNext) { load_stage(sb0, gs + 1, m0, t); CP_COMMIT(); CP_WAIT1(); }
            else          { CP_WAIT0(); }
            __syncthreads();

            if (s == 0 || s == 2 || s == 4) {
#pragma unroll
                for (int i = 0; i < 2; i++)
#pragma unroll
                    for (int j = 0; j < 4; j++)
#pragma unroll
                        for (int r = 0; r < 4; r++) acc[i][j][r] = 0.0f;
            }
            const int buf = gs & 1;
            mma_stage(acc,
                      sb0 + SM_A + (buf * 2 + 0) * AST, sb0 + SM_A + (buf * 2 + 1) * AST,
                      sb0 + SM_B + (buf * 2 + 0) * BST, sb0 + SM_B + (buf * 2 + 1) * BST,
                      mrow0, ncol0, l);
            __syncthreads();

            if (s == 1 || s == 3) {          // stash con / off (thread-private map)
                float* dst = (s == 1) ? sC : sO;
#pragma unroll
                for (int mt = 0; mt < 2; mt++)
#pragma unroll
                    for (int ntl = 0; ntl < 4; ntl++)
#pragma unroll
                        for (int r = 0; r < 4; r++) {
                            int row = mrow0 + mt * 16 + (l >> 2) + 8 * (r >> 1);
                            int col = ncol0 + ntl * 8 + 2 * (l & 3) + (r & 1);
                            float th = fast_tanh(acc[mt][ntl][r] * INV_SQRT_H);
                            dst[row * 68 + col] = (s == 1) ? th * MAX_CONTRAST : th;
                        }
            }
        }

        // ---- combine: w = exp(l-30); row sums; wc -> bf16 hi/lo smem ----
#pragma unroll
        for (int mt = 0; mt < 2; mt++)
#pragma unroll
            for (int ntl = 0; ntl < 4; ntl++)
#pragma unroll
                for (int r = 0; r < 4; r++) {
                    int row = mrow0 + mt * 16 + (l >> 2) + 8 * (r >> 1);
                    int col = ncol0 + ntl * 8 + 2 * (l & 3) + (r & 1);
                    float wgt = __expf(acc[mt][ntl][r] - EXP_SHIFT);
                    pw[mt * 2 + (r >> 1)] += wgt;
                    pwo[mt * 2 + (r >> 1)] += wgt * sO[row * 68 + col];
                    float wc = wgt * sC[row * 68 + col];
                    __nv_bfloat16 h = __float2bfloat16(wc);
                    sWCh[row * 72 + col] = h;
                    sWCl[row * 72 + col] = __float2bfloat16(wc - __bfloat162float(h));
                }
        __syncthreads();

        // ---- epilogue mma: ep += wc @ pooled^T  (k = 64 tile cols) ----
        mma_stage(ep, sb0 + SM_WCH, sb0 + SM_WCL, sb0 + SM_DFH, sb0 + SM_DFL,
                  mrow0, ncol0, l);
        // (no sync needed: sWC/sDF rewritten only after multiple barriers next tile)
    }

    // ---- row-sum reduce + store ----
#pragma unroll
    for (int i = 0; i < 4; i++) {
        pw[i]  += __shfl_xor_sync(0xffffffffu, pw[i], 1);
        pw[i]  += __shfl_xor_sync(0xffffffffu, pw[i], 2);
        pwo[i] += __shfl_xor_sync(0xffffffffu, pwo[i], 1);
        pwo[i] += __shfl_xor_sync(0xffffffffu, pwo[i], 2);
    }
    if ((l & 3) == 0) {
#pragma unroll
        for (int mt = 0; mt < 2; mt++)
#pragma unroll
            for (int half = 0; half < 2; half++) {
                int row = mrow0 + mt * 16 + (l >> 2) + 8 * half;
                sRW[(w & 1) * 96 + row] = pw[mt * 2 + half];
                sRO[(w & 1) * 96 + row] = pwo[mt * 2 + half];
            }
    }
    __syncthreads();

#pragma unroll
    for (int mt = 0; mt < 2; mt++)
#pragma unroll
        for (int ntl = 0; ntl < 4; ntl++)
#pragma unroll
            for (int half = 0; half < 2; half++) {
                int row = mrow0 + mt * 16 + (l >> 2) + 8 * half;
                int col = ncol0 + ntl * 8 + 2 * (l & 3);
                float sw  = sRW[row] + sRW[96 + row];
                float swo = sRO[row] + sRO[96 + row];
                float inv = 1.0f / sw;
                float2 v;
                v.x = (ep[mt][ntl][half * 2 + 0] + swo) * inv;
                v.y = (ep[mt][ntl][half * 2 + 1] + swo) * inv;
                *(float2*)(out + (size_t)(m0 + row) * DF_W + col) = v;
            }
}

// ---------------------------------------------------------------------------
// kernel_launch
// ---------------------------------------------------------------------------
extern "C" void kernel_launch(void* const* d_in, const int* in_sizes, int n_in,
                              void* d_out, int out_size)
{
    const float* pooled = (const float*)d_in[0];
    const float* rl     = (const float*)d_in[1];
    const float* dl     = (const float*)d_in[2];
    const float* rp     = (const float*)d_in[3];
    const float* dp     = (const float*)d_in[4];
    const float* Wrp    = (const float*)d_in[5];
    const float* brp    = (const float*)d_in[6];
    const float* Wdp    = (const float*)d_in[7];
    const float* bdp    = (const float*)d_in[8];
    const float* Wrc    = (const float*)d_in[9];
    const float* brc    = (const float*)d_in[10];
    const float* Wdc    = (const float*)d_in[11];
    const float* bdc    = (const float*)d_in[12];
    const float* Wro    = (const float*)d_in[13];
    const float* bro    = (const float*)d_in[14];
    const float* Wdo    = (const float*)d_in[15];
    const float* bdo    = (const float*)d_in[16];
    float* out = (float*)d_out;

    prep_weights<<<512, 512>>>(Wrp, brp, Wdp, bdp, Wrc, brc, Wdc, bdc,
                               Wro, bro, Wdo, bdo);
    prep_pd<<<ND, DF_W>>>(pooled);

    dim3 gridD(ND / 64, F_DIM / 64);   // 27 x 8
    feat_gemm<false><<<gridD, 256>>>(dl, dp);

    dim3 gridR(NR / 64, F_DIM / 64);   // 216 x 8
    feat_gemm<true><<<gridR, 256>>>(rl, rp);

    cudaFuncSetAttribute(attention_kernel,
                         cudaFuncAttributeMaxDynamicSharedMemorySize, SM_TOTAL);
    attention_kernel<<<NR / BM, NTHREADS, SM_TOTAL>>>(out);
}

// round 6
// speedup vs baseline: 4.3168x; 1.2692x over previous
#include <cuda_runtime.h>
#include <cuda_bf16.h>
#include <cstdint>
#include <math.h>

// ---------------------------------------------------------------------------
// FractalAttention3D — mma.sync bf16 (2-way split) everywhere
//   Family-portable PTX only (sm_80+): mma.sync / ldmatrix / cp.async.
//   NR=13824, ND=1728, E=512; feature layout (512):
//     [0:256) repr*0.25 | [256:384) con | [384:512) off
// ---------------------------------------------------------------------------

#define NR 13824
#define ND 1728
#define E_DIM 512
#define F_DIM 512
#define DF_W 64
#define LOGIT_SCALE 0.25f
#define INV_SQRT_H 0.08838834764831843f
#define MAX_CONTRAST 1.8f
#define EXP_SHIFT 30.0f

#define BM 96                 // 13824/96 = 144 CTAs ~ one wave
#define BN 64
#define NTILES (ND / BN)      // 27
#define NSTG 8                // stages per tile (2 con + 2 off + 4 repr)
#define NTHREADS 192          // 6 warps (3 x 2 grid of 32x32)

// -------- device scratch (static; no cudaMalloc allowed) --------
__device__ __align__(16) float g_br[F_DIM];
__device__ __align__(16) float g_bd[F_DIM];
// W concat, transposed [n][k], bf16 hi/lo (B-operand format)
__device__ __align__(16) __nv_bfloat16 g_Wrth[(size_t)F_DIM * F_DIM];
__device__ __align__(16) __nv_bfloat16 g_Wrtl[(size_t)F_DIM * F_DIM];
__device__ __align__(16) __nv_bfloat16 g_Wdth[(size_t)F_DIM * F_DIM];
__device__ __align__(16) __nv_bfloat16 g_Wdtl[(size_t)F_DIM * F_DIM];
// base = lat + pos, bf16 hi/lo
__device__ __align__(16) __nv_bfloat16 g_RBh[(size_t)NR * E_DIM];
__device__ __align__(16) __nv_bfloat16 g_RBl[(size_t)NR * E_DIM];
__device__ __align__(16) __nv_bfloat16 g_DBh[(size_t)ND * E_DIM];
__device__ __align__(16) __nv_bfloat16 g_DBl[(size_t)ND * E_DIM];
// features, bf16 hi/lo
__device__ __align__(16) __nv_bfloat16 g_RFh[(size_t)NR * F_DIM];
__device__ __align__(16) __nv_bfloat16 g_RFl[(size_t)NR * F_DIM];
__device__ __align__(16) __nv_bfloat16 g_DFh[(size_t)ND * F_DIM];
__device__ __align__(16) __nv_bfloat16 g_DFl[(size_t)ND * F_DIM];
// pooled^T, bf16 hi/lo [64][1728]
__device__ __align__(16) __nv_bfloat16 g_PDth[(size_t)DF_W * ND];
__device__ __align__(16) __nv_bfloat16 g_PDtl[(size_t)DF_W * ND];

// ---------------- attention smem layout (bytes) ----------------
#define AST 13824            // 96*72*2
#define BST 9216             // 64*72*2
#define SM_A  0              // 4*AST = 55296
#define SM_B  55296          // 4*BST = 36864
#define SM_WCH 92160         // 96*72*2 = 13824
#define SM_WCL 105984
#define SM_DFH 119808        // 64*72*2 = 9216
#define SM_DFL 129024
#define SM_C  138240         // 96*68*4 = 26112 (con, f32)
#define SM_O  164352         // 26112 (off, f32)
#define SM_RW 190464         // 2*96*4
#define SM_RO 191232
#define SM_TOTAL 192000

// feat_mma smem: A 4*AST + B 4*BST = 92160
#define SM2_TOTAL 92160

// ---------------- PTX helpers (sm_80-portable) ----------------
__device__ __forceinline__ uint32_t smem_u32(const void* p) {
    uint32_t a;
    asm("{ .reg .u64 t; cvta.to.shared.u64 t, %1; cvt.u32.u64 %0, t; }" : "=r"(a) : "l"(p));
    return a;
}
__device__ __forceinline__ void cp16(uint32_t dst, const void* src) {
    asm volatile("cp.async.cg.shared.global [%0], [%1], 16;" :: "r"(dst), "l"(src));
}
#define CP_COMMIT() asm volatile("cp.async.commit_group;" ::: "memory")
#define CP_WAIT1()  asm volatile("cp.async.wait_group 1;" ::: "memory")
#define CP_WAIT0()  asm volatile("cp.async.wait_group 0;" ::: "memory")

__device__ __forceinline__ void ldsm4(uint32_t& r0, uint32_t& r1, uint32_t& r2, uint32_t& r3,
                                      uint32_t addr) {
    asm volatile("ldmatrix.sync.aligned.m8n8.x4.shared.b16 {%0,%1,%2,%3}, [%4];"
                 : "=r"(r0), "=r"(r1), "=r"(r2), "=r"(r3) : "r"(addr));
}
__device__ __forceinline__ void mma_bf16(float* c, const uint32_t* a, uint32_t b0, uint32_t b1) {
    asm("mma.sync.aligned.m16n8k16.row.col.f32.bf16.bf16.f32 "
        "{%0,%1,%2,%3}, {%4,%5,%6,%7}, {%8,%9}, {%0,%1,%2,%3};"
        : "+f"(c[0]), "+f"(c[1]), "+f"(c[2]), "+f"(c[3])
        : "r"(a[0]), "r"(a[1]), "r"(a[2]), "r"(a[3]), "r"(b0), "r"(b1));
}
__device__ __forceinline__ float fast_tanh(float x) {
    float e = __expf(-2.0f * x);
    return __fdividef(2.0f, e + 1.0f) - 1.0f;
}

// ---------------------------------------------------------------------------
// Kernel 0a: concat weights (transposed, bf16 hi/lo) + biases
// ---------------------------------------------------------------------------
__global__ void prep_weights(
    const float* __restrict__ Wrp, const float* __restrict__ brp,
    const float* __restrict__ Wdp, const float* __restrict__ bdp,
    const float* __restrict__ Wrc, const float* __restrict__ brc,
    const float* __restrict__ Wdc, const float* __restrict__ bdc,
    const float* __restrict__ Wro, const float* __restrict__ bro,
    const float* __restrict__ Wdo, const float* __restrict__ bdo)
{
    int e = blockIdx.x, j = threadIdx.x;   // e = k index, j = n index
    float wr, wd;
    if (j < 256)      { wr = Wrp[e * 256 + j] * LOGIT_SCALE; wd = Wdp[e * 256 + j]; }
    else if (j < 384) { wr = Wrc[e * 128 + (j - 256)];       wd = Wdc[e * 128 + (j - 256)]; }
    else              { wr = Wro[e * 128 + (j - 384)];       wd = Wdo[e * 128 + (j - 384)]; }
    size_t toff = (size_t)j * F_DIM + e;   // transposed [n][k]
    __nv_bfloat16 h = __float2bfloat16(wr);
    g_Wrth[toff] = h;
    g_Wrtl[toff] = __float2bfloat16(wr - __bfloat162float(h));
    h = __float2bfloat16(wd);
    g_Wdth[toff] = h;
    g_Wdtl[toff] = __float2bfloat16(wd - __bfloat162float(h));
    if (e == 0) {
        float br, bd;
        if (j < 256)      { br = brp[j] * LOGIT_SCALE; bd = bdp[j]; }
        else if (j < 384) { br = brc[j - 256];         bd = bdc[j - 256]; }
        else              { br = bro[j - 384];         bd = bdo[j - 384]; }
        g_br[j] = br;
        g_bd[j] = bd;
    }
}

// Kernel 0b: pooled_domains^T bf16 hi/lo: PDt[d][n]
__global__ void prep_pd(const float* __restrict__ pooled) {
    int n = blockIdx.x, d = threadIdx.x;
    float v = pooled[(size_t)n * DF_W + d];
    __nv_bfloat16 h = __float2bfloat16(v);
    g_PDth[(size_t)d * ND + n] = h;
    g_PDtl[(size_t)d * ND + n] = __float2bfloat16(v - __bfloat162float(h));
}

// Kernel 0c: base = lat + pos -> bf16 hi/lo (vectorized x4)
template <bool RANGE>
__global__ void prep_base(const float* __restrict__ lat, const float* __restrict__ pos)
{
    __nv_bfloat16* __restrict__ OH = RANGE ? g_RBh : g_DBh;
    __nv_bfloat16* __restrict__ OL = RANGE ? g_RBl : g_DBl;
    size_t i = ((size_t)blockIdx.x * blockDim.x + threadIdx.x) * 4;
    float4 a = *(const float4*)(lat + i);
    float4 b = *(const float4*)(pos + i);
    float v[4] = {a.x + b.x, a.y + b.y, a.z + b.z, a.w + b.w};
    __nv_bfloat16 hb[4], lb[4];
#pragma unroll
    for (int j = 0; j < 4; j++) {
        hb[j] = __float2bfloat16(v[j]);
        lb[j] = __float2bfloat16(v[j] - __bfloat162float(hb[j]));
    }
    *(uint2*)(OH + i) = *(uint2*)hb;
    *(uint2*)(OL + i) = *(uint2*)lb;
}

// ---------------------------------------------------------------------------
// Shared 96x64x64 MMA stage: A tiles stride 144B, B tiles stride 144B
// (fragment maps validated in R4)
// ---------------------------------------------------------------------------
__device__ __forceinline__ void mma_stage(
    float (&acc)[2][4][4], uint32_t aH, uint32_t aL, uint32_t bH, uint32_t bL,
    int mrow0, int ncol0, int l)
{
    const uint32_t aRowOff = (uint32_t)((l & 15) * 144) + (uint32_t)((l >> 4) * 16);
    const uint32_t bRowOff = (uint32_t)((((l >> 4) & 1) * 8 + (l & 7)) * 144)
                           + (uint32_t)(((l >> 3) & 1) * 16);
#pragma unroll
    for (int k16 = 0; k16 < 4; k16++) {
        uint32_t ah[2][4], al[2][4], bh[2][4], bl[2][4];
        const uint32_t kb = (uint32_t)(k16 * 32);
#pragma unroll
        for (int mt = 0; mt < 2; mt++) {
            uint32_t off = (uint32_t)((mrow0 + mt * 16) * 144) + aRowOff + kb;
            ldsm4(ah[mt][0], ah[mt][1], ah[mt][2], ah[mt][3], aH + off);
            ldsm4(al[mt][0], al[mt][1], al[mt][2], al[mt][3], aL + off);
        }
#pragma unroll
        for (int np = 0; np < 2; np++) {
            uint32_t off = (uint32_t)((ncol0 + np * 16) * 144) + bRowOff + kb;
            ldsm4(bh[np][0], bh[np][1], bh[np][2], bh[np][3], bH + off);
            ldsm4(bl[np][0], bl[np][1], bl[np][2], bl[np][3], bL + off);
        }
#pragma unroll
        for (int mt = 0; mt < 2; mt++)
#pragma unroll
            for (int ntl = 0; ntl < 4; ntl++) {
                const int np = ntl >> 1, ri = (ntl & 1) * 2;
                mma_bf16(acc[mt][ntl], ah[mt], bh[np][ri], bh[np][ri + 1]);
                mma_bf16(acc[mt][ntl], ah[mt], bl[np][ri], bl[np][ri + 1]);
                mma_bf16(acc[mt][ntl], al[mt], bh[np][ri], bh[np][ri + 1]);
            }
    }
}

// ---------------------------------------------------------------------------
// Kernel 1: feature GEMM on tensor cores
//   O[M,512] = base[M,512] @ Wt^T + bias ; output split to bf16 hi/lo
//   grid = (M/96, 8), 192 threads, K=512 in 8 cp.async double-buffered stages
//   Globals referenced directly (no host symbol resolution needed).
// ---------------------------------------------------------------------------
template <bool RANGE>
__global__ void __launch_bounds__(NTHREADS) feat_mma()
{
    const __nv_bfloat16* __restrict__ Ah = RANGE ? g_RBh : g_DBh;
    const __nv_bfloat16* __restrict__ Al = RANGE ? g_RBl : g_DBl;
    const __nv_bfloat16* __restrict__ Bh = RANGE ? g_Wrth : g_Wdth;
    const __nv_bfloat16* __restrict__ Bl = RANGE ? g_Wrtl : g_Wdtl;
    const float* __restrict__ bias = RANGE ? g_br : g_bd;
    __nv_bfloat16* __restrict__ OH = RANGE ? g_RFh : g_DFh;
    __nv_bfloat16* __restrict__ OL = RANGE ? g_RFl : g_DFl;

    extern __shared__ char smem[];
    const uint32_t sb0 = smem_u32(smem);
    const int t = threadIdx.x;
    const int w = t >> 5, l = t & 31;
    const int m0 = blockIdx.x * BM;
    const int n0 = blockIdx.y * BN;
    const int mrow0 = (w >> 1) * 32;
    const int ncol0 = (w & 1) * 32;

    auto load_s = [&](int s) {
        const int buf = s & 1;
        const int koff = s * 64;
        const uint32_t aH = sb0 + (buf * 2 + 0) * AST;
        const uint32_t aL = sb0 + (buf * 2 + 1) * AST;
#pragma unroll
        for (int c = t; c < 768; c += NTHREADS) {
            int row = c >> 3, k8 = (c & 7) * 8;
            uint32_t so = (uint32_t)(row * 144 + k8 * 2);
            size_t go = (size_t)(m0 + row) * E_DIM + koff + k8;
            cp16(aH + so, Ah + go);
            cp16(aL + so, Al + go);
        }
        const uint32_t bH = sb0 + 4 * AST + (buf * 2 + 0) * BST;
        const uint32_t bL = sb0 + 4 * AST + (buf * 2 + 1) * BST;
#pragma unroll
        for (int c = t; c < 512; c += NTHREADS) {
            int row = c >> 3, k8 = (c & 7) * 8;
            uint32_t so = (uint32_t)(row * 144 + k8 * 2);
            size_t go = (size_t)(n0 + row) * F_DIM + koff + k8;
            cp16(bH + so, Bh + go);
            cp16(bL + so, Bl + go);
        }
    };

    float acc[2][4][4];
#pragma unroll
    for (int i = 0; i < 2; i++)
#pragma unroll
        for (int j = 0; j < 4; j++)
#pragma unroll
            for (int r = 0; r < 4; r++) acc[i][j][r] = 0.0f;

    load_s(0);
    CP_COMMIT();
#pragma unroll 1
    for (int s = 0; s < 8; ++s) {
        if (s < 7) { load_s(s + 1); CP_COMMIT(); CP_WAIT1(); }
        else       { CP_WAIT0(); }
        __syncthreads();
        const int buf = s & 1;
        mma_stage(acc, sb0 + (buf * 2 + 0) * AST, sb0 + (buf * 2 + 1) * AST,
                  sb0 + 4 * AST + (buf * 2 + 0) * BST, sb0 + 4 * AST + (buf * 2 + 1) * BST,
                  mrow0, ncol0, l);
        __syncthreads();
    }

    // epilogue: + bias, split, store
#pragma unroll
    for (int mt = 0; mt < 2; mt++)
#pragma unroll
        for (int ntl = 0; ntl < 4; ntl++)
#pragma unroll
            for (int half = 0; half < 2; half++) {
                int row = mrow0 + mt * 16 + (l >> 2) + 8 * half;
                int col = ncol0 + ntl * 8 + 2 * (l & 3);
                float v0 = acc[mt][ntl][half * 2 + 0] + bias[n0 + col];
                float v1 = acc[mt][ntl][half * 2 + 1] + bias[n0 + col + 1];
                __nv_bfloat16 h0 = __float2bfloat16(v0);
                __nv_bfloat16 h1 = __float2bfloat16(v1);
                __nv_bfloat16 l0 = __float2bfloat16(v0 - __bfloat162float(h0));
                __nv_bfloat16 l1 = __float2bfloat16(v1 - __bfloat162float(h1));
                size_t off = (size_t)(m0 + row) * F_DIM + n0 + col;
                __nv_bfloat16 hp[2] = {h0, h1}, lp[2] = {l0, l1};
                *(uint32_t*)(OH + off) = *(uint32_t*)hp;
                *(uint32_t*)(OL + off) = *(uint32_t*)lp;
            }
}

// ---------------------------------------------------------------------------
// Kernel 2: fused attention (unchanged from R4, passing at 1.6e-5)
// ---------------------------------------------------------------------------
__device__ __forceinline__ int stage_koff(int s) {
    return (s < 4) ? (256 + s * 64) : ((s - 4) * 64);
}

__device__ __forceinline__ void load_stage(uint32_t sb0, int gs, int m0, int t) {
    const int s = gs & 7;
    const int nt = gs >> 3;
    const int koff = stage_koff(s);
    const int n0 = nt * BN;
    const int buf = gs & 1;
    const uint32_t aH = sb0 + SM_A + (buf * 2 + 0) * AST;
    const uint32_t aL = sb0 + SM_A + (buf * 2 + 1) * AST;
#pragma unroll
    for (int c = t; c < 768; c += NTHREADS) {
        int row = c >> 3, k8 = (c & 7) * 8;
        uint32_t so = (uint32_t)(row * 144 + k8 * 2);
        size_t go = (size_t)(m0 + row) * F_DIM + koff + k8;
        cp16(aH + so, g_RFh + go);
        cp16(aL + so, g_RFl + go);
    }
    const uint32_t bH = sb0 + SM_B + (buf * 2 + 0) * BST;
    const uint32_t bL = sb0 + SM_B + (buf * 2 + 1) * BST;
#pragma unroll
    for (int c = t; c < 512; c += NTHREADS) {
        int row = c >> 3, k8 = (c & 7) * 8;
        uint32_t so = (uint32_t)(row * 144 + k8 * 2);
        size_t go = (size_t)(n0 + row) * F_DIM + koff + k8;
        cp16(bH + so, g_DFh + go);
        cp16(bL + so, g_DFl + go);
    }
}

__device__ __forceinline__ void load_df(uint32_t sb0, int nt, int t) {
    const int n0 = nt * BN;
#pragma unroll
    for (int c = t; c < 512; c += NTHREADS) {
        int row = c >> 3, k8 = (c & 7) * 8;
        uint32_t so = (uint32_t)(row * 144 + k8 * 2);
        size_t go = (size_t)row * ND + n0 + k8;
        cp16(sb0 + SM_DFH + so, g_PDth + go);
        cp16(sb0 + SM_DFL + so, g_PDtl + go);
    }
}

__global__ void __launch_bounds__(NTHREADS, 1) attention_kernel(float* __restrict__ out)
{
    extern __shared__ char smem[];
    const uint32_t sb0 = smem_u32(smem);

    const int t = threadIdx.x;
    const int w = t >> 5, l = t & 31;
    const int m0 = blockIdx.x * BM;
    const int mrow0 = (w >> 1) * 32;
    const int ncol0 = (w & 1) * 32;

    float* sC = (float*)(smem + SM_C);
    float* sO = (float*)(smem + SM_O);
    __nv_bfloat16* sWCh = (__nv_bfloat16*)(smem + SM_WCH);
    __nv_bfloat16* sWCl = (__nv_bfloat16*)(smem + SM_WCL);
    float* sRW = (float*)(smem + SM_RW);
    float* sRO = (float*)(smem + SM_RO);

    float ep[2][4][4];
#pragma unroll
    for (int i = 0; i < 2; i++)
#pragma unroll
        for (int j = 0; j < 4; j++)
#pragma unroll
            for (int r = 0; r < 4; r++) ep[i][j][r] = 0.0f;
    float pw[4]  = {0.f, 0.f, 0.f, 0.f};
    float pwo[4] = {0.f, 0.f, 0.f, 0.f};

    load_stage(sb0, 0, m0, t);
    CP_COMMIT();

#pragma unroll 1
    for (int nt = 0; nt < NTILES; ++nt) {
        float acc[2][4][4];

#pragma unroll 1
        for (int s = 0; s < NSTG; ++s) {
            const int gs = nt * NSTG + s;
            const bool haveNext = (gs + 1 < NTILES * NSTG);
            if (s == NSTG - 1) { load_df(sb0, nt, t); CP_COMMIT(); }
            if (haveNext) { load_stage(sb0, gs + 1, m0, t); CP_COMMIT(); CP_WAIT1(); }
            else          { CP_WAIT0(); }
            __syncthreads();

            if (s == 0 || s == 2 || s == 4) {
#pragma unroll
                for (int i = 0; i < 2; i++)
#pragma unroll
                    for (int j = 0; j < 4; j++)
#pragma unroll
                        for (int r = 0; r < 4; r++) acc[i][j][r] = 0.0f;
            }
            const int buf = gs & 1;
            mma_stage(acc,
                      sb0 + SM_A + (buf * 2 + 0) * AST, sb0 + SM_A + (buf * 2 + 1) * AST,
                      sb0 + SM_B + (buf * 2 + 0) * BST, sb0 + SM_B + (buf * 2 + 1) * BST,
                      mrow0, ncol0, l);
            __syncthreads();

            if (s == 1 || s == 3) {
                float* dst = (s == 1) ? sC : sO;
#pragma unroll
                for (int mt = 0; mt < 2; mt++)
#pragma unroll
                    for (int ntl = 0; ntl < 4; ntl++)
#pragma unroll
                        for (int r = 0; r < 4; r++) {
                            int row = mrow0 + mt * 16 + (l >> 2) + 8 * (r >> 1);
                            int col = ncol0 + ntl * 8 + 2 * (l & 3) + (r & 1);
                            float th = fast_tanh(acc[mt][ntl][r] * INV_SQRT_H);
                            dst[row * 68 + col] = (s == 1) ? th * MAX_CONTRAST : th;
                        }
            }
        }

        // ---- combine ----
#pragma unroll
        for (int mt = 0; mt < 2; mt++)
#pragma unroll
            for (int ntl = 0; ntl < 4; ntl++)
#pragma unroll
                for (int r = 0; r < 4; r++) {
                    int row = mrow0 + mt * 16 + (l >> 2) + 8 * (r >> 1);
                    int col = ncol0 + ntl * 8 + 2 * (l & 3) + (r & 1);
                    float wgt = __expf(acc[mt][ntl][r] - EXP_SHIFT);
                    pw[mt * 2 + (r >> 1)] += wgt;
                    pwo[mt * 2 + (r >> 1)] += wgt * sO[row * 68 + col];
                    float wc = wgt * sC[row * 68 + col];
                    __nv_bfloat16 h = __float2bfloat16(wc);
                    sWCh[row * 72 + col] = h;
                    sWCl[row * 72 + col] = __float2bfloat16(wc - __bfloat162float(h));
                }
        __syncthreads();

        mma_stage(ep, sb0 + SM_WCH, sb0 + SM_WCL, sb0 + SM_DFH, sb0 + SM_DFL,
                  mrow0, ncol0, l);
    }

    // ---- row-sum reduce + store ----
#pragma unroll
    for (int i = 0; i < 4; i++) {
        pw[i]  += __shfl_xor_sync(0xffffffffu, pw[i], 1);
        pw[i]  += __shfl_xor_sync(0xffffffffu, pw[i], 2);
        pwo[i] += __shfl_xor_sync(0xffffffffu, pwo[i], 1);
        pwo[i] += __shfl_xor_sync(0xffffffffu, pwo[i], 2);
    }
    if ((l & 3) == 0) {
#pragma unroll
        for (int mt = 0; mt < 2; mt++)
#pragma unroll
            for (int half = 0; half < 2; half++) {
                int row = mrow0 + mt * 16 + (l >> 2) + 8 * half;
                sRW[(w & 1) * 96 + row] = pw[mt * 2 + half];
                sRO[(w & 1) * 96 + row] = pwo[mt * 2 + half];
            }
    }
    __syncthreads();

#pragma unroll
    for (int mt = 0; mt < 2; mt++)
#pragma unroll
        for (int ntl = 0; ntl < 4; ntl++)
#pragma unroll
            for (int half = 0; half < 2; half++) {
                int row = mrow0 + mt * 16 + (l >> 2) + 8 * half;
                int col = ncol0 + ntl * 8 + 2 * (l & 3);
                float sw  = sRW[row] + sRW[96 + row];
                float swo = sRO[row] + sRO[96 + row];
                float inv = 1.0f / sw;
                float2 v;
                v.x = (ep[mt][ntl][half * 2 + 0] + swo) * inv;
                v.y = (ep[mt][ntl][half * 2 + 1] + swo) * inv;
                *(float2*)(out + (size_t)(m0 + row) * DF_W + col) = v;
            }
}

// ---------------------------------------------------------------------------
// kernel_launch — kernel launches only (graph-capture clean)
// ---------------------------------------------------------------------------
extern "C" void kernel_launch(void* const* d_in, const int* in_sizes, int n_in,
                              void* d_out, int out_size)
{
    const float* pooled = (const float*)d_in[0];
    const float* rl     = (const float*)d_in[1];
    const float* dl     = (const float*)d_in[2];
    const float* rp     = (const float*)d_in[3];
    const float* dp     = (const float*)d_in[4];
    const float* Wrp    = (const float*)d_in[5];
    const float* brp    = (const float*)d_in[6];
    const float* Wdp    = (const float*)d_in[7];
    const float* bdp    = (const float*)d_in[8];
    const float* Wrc    = (const float*)d_in[9];
    const float* brc    = (const float*)d_in[10];
    const float* Wdc    = (const float*)d_in[11];
    const float* bdc    = (const float*)d_in[12];
    const float* Wro    = (const float*)d_in[13];
    const float* bro    = (const float*)d_in[14];
    const float* Wdo    = (const float*)d_in[15];
    const float* bdo    = (const float*)d_in[16];
    float* out = (float*)d_out;

    prep_weights<<<512, 512>>>(Wrp, brp, Wdp, bdp, Wrc, brc, Wdc, bdc,
                               Wro, bro, Wdo, bdo);
    prep_pd<<<ND, DF_W>>>(pooled);
    prep_base<true><<<(NR * E_DIM / 4) / 256, 256>>>(rl, rp);
    prep_base<false><<<(ND * E_DIM / 4) / 256, 256>>>(dl, dp);

    cudaFuncSetAttribute(feat_mma<false>,
                         cudaFuncAttributeMaxDynamicSharedMemorySize, SM2_TOTAL);
    cudaFuncSetAttribute(feat_mma<true>,
                         cudaFuncAttributeMaxDynamicSharedMemorySize, SM2_TOTAL);
    dim3 gridD(ND / BM, F_DIM / BN);   // 18 x 8
    feat_mma<false><<<gridD, NTHREADS, SM2_TOTAL>>>();
    dim3 gridR(NR / BM, F_DIM / BN);   // 144 x 8
    feat_mma<true><<<gridR, NTHREADS, SM2_TOTAL>>>();

    cudaFuncSetAttribute(attention_kernel,
                         cudaFuncAttributeMaxDynamicSharedMemorySize, SM_TOTAL);
    attention_kernel<<<NR / BM, NTHREADS, SM_TOTAL>>>(out);
}

// round 7
// speedup vs baseline: 5.0571x; 1.1715x over previous
#include <cuda_runtime.h>
#include <cuda_bf16.h>
#include <cstdint>
#include <math.h>

// ---------------------------------------------------------------------------
// FractalAttention3D — mma.sync bf16 (2-way split), balanced 8-warp tiling
//   Family-portable PTX only (sm_80+): mma.sync / ldmatrix / cp.async.
//   NR=13824, ND=1728, E=512; feature layout (512):
//     [0:256) repr*0.25 | [256:384) con | [384:512) off
// ---------------------------------------------------------------------------

#define NR 13824
#define ND 1728
#define E_DIM 512
#define F_DIM 512
#define DF_W 64
#define LOGIT_SCALE 0.25f
#define INV_SQRT_H 0.08838834764831843f
#define MAX_CONTRAST 1.8f
#define EXP_SHIFT 30.0f

#define BM 96                 // 13824/96 = 144 CTAs ~ one wave
#define BN 64
#define NTILES (ND / BN)      // 27
#define NSTG 8                // stages per tile (2 con + 2 off + 4 repr)
#define NTHREADS 256          // 8 warps: 2m x 4n grid of 48x16 warp tiles

// -------- device scratch (static; no cudaMalloc allowed) --------
__device__ __align__(16) float g_br[F_DIM];
__device__ __align__(16) float g_bd[F_DIM];
__device__ __align__(16) __nv_bfloat16 g_Wrth[(size_t)F_DIM * F_DIM];
__device__ __align__(16) __nv_bfloat16 g_Wrtl[(size_t)F_DIM * F_DIM];
__device__ __align__(16) __nv_bfloat16 g_Wdth[(size_t)F_DIM * F_DIM];
__device__ __align__(16) __nv_bfloat16 g_Wdtl[(size_t)F_DIM * F_DIM];
__device__ __align__(16) __nv_bfloat16 g_RBh[(size_t)NR * E_DIM];
__device__ __align__(16) __nv_bfloat16 g_RBl[(size_t)NR * E_DIM];
__device__ __align__(16) __nv_bfloat16 g_DBh[(size_t)ND * E_DIM];
__device__ __align__(16) __nv_bfloat16 g_DBl[(size_t)ND * E_DIM];
__device__ __align__(16) __nv_bfloat16 g_RFh[(size_t)NR * F_DIM];
__device__ __align__(16) __nv_bfloat16 g_RFl[(size_t)NR * F_DIM];
__device__ __align__(16) __nv_bfloat16 g_DFh[(size_t)ND * F_DIM];
__device__ __align__(16) __nv_bfloat16 g_DFl[(size_t)ND * F_DIM];
__device__ __align__(16) __nv_bfloat16 g_PDth[(size_t)DF_W * ND];  // pooled^T hi [64][1728]
__device__ __align__(16) __nv_bfloat16 g_PDtl[(size_t)DF_W * ND];

// ---------------- attention smem layout (bytes) ----------------
#define AST 13824            // 96*72*2 (stride 144B/row)
#define BST 9216             // 64*72*2
#define SM_A   0             // 4*AST = 55296 (2 bufs x hi/lo)
#define SM_B   55296         // 4*BST = 36864
#define SM_WCH 92160         // 13824
#define SM_WCL 105984        // 13824
#define SM_DFH 119808        // 9216
#define SM_DFL 129024        // 9216
#define SM_RW  138240        // 4*96*4 = 1536
#define SM_RO  139776        // 1536
#define SM_TOTAL 141312

// feat_mma smem: A 4*AST + B 4*BST
#define SM2_TOTAL 92160

// ---------------- PTX helpers (sm_80-portable) ----------------
__device__ __forceinline__ uint32_t smem_u32(const void* p) {
    uint32_t a;
    asm("{ .reg .u64 t; cvta.to.shared.u64 t, %1; cvt.u32.u64 %0, t; }" : "=r"(a) : "l"(p));
    return a;
}
__device__ __forceinline__ void cp16(uint32_t dst, const void* src) {
    asm volatile("cp.async.cg.shared.global [%0], [%1], 16;" :: "r"(dst), "l"(src));
}
#define CP_COMMIT() asm volatile("cp.async.commit_group;" ::: "memory")
#define CP_WAIT1()  asm volatile("cp.async.wait_group 1;" ::: "memory")
#define CP_WAIT0()  asm volatile("cp.async.wait_group 0;" ::: "memory")

__device__ __forceinline__ void ldsm4(uint32_t& r0, uint32_t& r1, uint32_t& r2, uint32_t& r3,
                                      uint32_t addr) {
    asm volatile("ldmatrix.sync.aligned.m8n8.x4.shared.b16 {%0,%1,%2,%3}, [%4];"
                 : "=r"(r0), "=r"(r1), "=r"(r2), "=r"(r3) : "r"(addr));
}
__device__ __forceinline__ void mma_bf16(float* c, const uint32_t* a, uint32_t b0, uint32_t b1) {
    asm("mma.sync.aligned.m16n8k16.row.col.f32.bf16.bf16.f32 "
        "{%0,%1,%2,%3}, {%4,%5,%6,%7}, {%8,%9}, {%0,%1,%2,%3};"
        : "+f"(c[0]), "+f"(c[1]), "+f"(c[2]), "+f"(c[3])
        : "r"(a[0]), "r"(a[1]), "r"(a[2]), "r"(a[3]), "r"(b0), "r"(b1));
}
__device__ __forceinline__ float fast_tanh(float x) {
    float e = __expf(-2.0f * x);
    return __fdividef(2.0f, e + 1.0f) - 1.0f;
}

// ---------------------------------------------------------------------------
// prep kernels (unchanged)
// ---------------------------------------------------------------------------
__global__ void prep_weights(
    const float* __restrict__ Wrp, const float* __restrict__ brp,
    const float* __restrict__ Wdp, const float* __restrict__ bdp,
    const float* __restrict__ Wrc, const float* __restrict__ brc,
    const float* __restrict__ Wdc, const float* __restrict__ bdc,
    const float* __restrict__ Wro, const float* __restrict__ bro,
    const float* __restrict__ Wdo, const float* __restrict__ bdo)
{
    int e = blockIdx.x, j = threadIdx.x;   // e = k index, j = n index
    float wr, wd;
    if (j < 256)      { wr = Wrp[e * 256 + j] * LOGIT_SCALE; wd = Wdp[e * 256 + j]; }
    else if (j < 384) { wr = Wrc[e * 128 + (j - 256)];       wd = Wdc[e * 128 + (j - 256)]; }
    else              { wr = Wro[e * 128 + (j - 384)];       wd = Wdo[e * 128 + (j - 384)]; }
    size_t toff = (size_t)j * F_DIM + e;   // transposed [n][k]
    __nv_bfloat16 h = __float2bfloat16(wr);
    g_Wrth[toff] = h;
    g_Wrtl[toff] = __float2bfloat16(wr - __bfloat162float(h));
    h = __float2bfloat16(wd);
    g_Wdth[toff] = h;
    g_Wdtl[toff] = __float2bfloat16(wd - __bfloat162float(h));
    if (e == 0) {
        float br, bd;
        if (j < 256)      { br = brp[j] * LOGIT_SCALE; bd = bdp[j]; }
        else if (j < 384) { br = brc[j - 256];         bd = bdc[j - 256]; }
        else              { br = bro[j - 384];         bd = bdo[j - 384]; }
        g_br[j] = br;
        g_bd[j] = bd;
    }
}

__global__ void prep_pd(const float* __restrict__ pooled) {
    int n = blockIdx.x, d = threadIdx.x;
    float v = pooled[(size_t)n * DF_W + d];
    __nv_bfloat16 h = __float2bfloat16(v);
    g_PDth[(size_t)d * ND + n] = h;
    g_PDtl[(size_t)d * ND + n] = __float2bfloat16(v - __bfloat162float(h));
}

template <bool RANGE>
__global__ void prep_base(const float* __restrict__ lat, const float* __restrict__ pos)
{
    __nv_bfloat16* __restrict__ OH = RANGE ? g_RBh : g_DBh;
    __nv_bfloat16* __restrict__ OL = RANGE ? g_RBl : g_DBl;
    size_t i = ((size_t)blockIdx.x * blockDim.x + threadIdx.x) * 4;
    float4 a = *(const float4*)(lat + i);
    float4 b = *(const float4*)(pos + i);
    float v[4] = {a.x + b.x, a.y + b.y, a.z + b.z, a.w + b.w};
    __nv_bfloat16 hb[4], lb[4];
#pragma unroll
    for (int j = 0; j < 4; j++) {
        hb[j] = __float2bfloat16(v[j]);
        lb[j] = __float2bfloat16(v[j] - __bfloat162float(hb[j]));
    }
    *(uint2*)(OH + i) = *(uint2*)hb;
    *(uint2*)(OL + i) = *(uint2*)lb;
}

// ---------------------------------------------------------------------------
// 8-warp MMA stage: per warp 48m x 16n over a 96x64x64 tile.
//   acc[3 m16][2 n8][4]. A rows stride 144B; B rows ([n][k]) stride 144B.
// ---------------------------------------------------------------------------
__device__ __forceinline__ void mma_stage8(
    float (&acc)[3][2][4], uint32_t aH, uint32_t aL, uint32_t bH, uint32_t bL,
    int mrow0, int ncol0, int l)
{
    const uint32_t aRowOff = (uint32_t)((l & 15) * 144) + (uint32_t)((l >> 4) * 16);
    const uint32_t bRowOff = (uint32_t)((ncol0 + ((l >> 4) & 1) * 8 + (l & 7)) * 144)
                           + (uint32_t)(((l >> 3) & 1) * 16);
#pragma unroll
    for (int k16 = 0; k16 < 4; k16++) {
        const uint32_t kb = (uint32_t)(k16 * 32);
        uint32_t ah[3][4], al[3][4], bh[4], bl[4];
#pragma unroll
        for (int mt = 0; mt < 3; mt++) {
            uint32_t off = (uint32_t)((mrow0 + mt * 16) * 144) + aRowOff + kb;
            ldsm4(ah[mt][0], ah[mt][1], ah[mt][2], ah[mt][3], aH + off);
            ldsm4(al[mt][0], al[mt][1], al[mt][2], al[mt][3], aL + off);
        }
        {
            uint32_t off = bRowOff + kb;
            ldsm4(bh[0], bh[1], bh[2], bh[3], bH + off);
            ldsm4(bl[0], bl[1], bl[2], bl[3], bL + off);
        }
#pragma unroll
        for (int mt = 0; mt < 3; mt++)
#pragma unroll
            for (int nf = 0; nf < 2; nf++) {
                const int ri = nf * 2;
                mma_bf16(acc[mt][nf], ah[mt], bh[ri], bh[ri + 1]);
                mma_bf16(acc[mt][nf], ah[mt], bl[ri], bl[ri + 1]);
                mma_bf16(acc[mt][nf], al[mt], bh[ri], bh[ri + 1]);
            }
    }
}

// ---------------------------------------------------------------------------
// Kernel 1: feature GEMM on tensor cores (8-warp layout)
// ---------------------------------------------------------------------------
template <bool RANGE>
__global__ void __launch_bounds__(NTHREADS, 1) feat_mma()
{
    const __nv_bfloat16* __restrict__ Ah = RANGE ? g_RBh : g_DBh;
    const __nv_bfloat16* __restrict__ Al = RANGE ? g_RBl : g_DBl;
    const __nv_bfloat16* __restrict__ Bh = RANGE ? g_Wrth : g_Wdth;
    const __nv_bfloat16* __restrict__ Bl = RANGE ? g_Wrtl : g_Wdtl;
    const float* __restrict__ bias = RANGE ? g_br : g_bd;
    __nv_bfloat16* __restrict__ OH = RANGE ? g_RFh : g_DFh;
    __nv_bfloat16* __restrict__ OL = RANGE ? g_RFl : g_DFl;

    extern __shared__ char smem[];
    const uint32_t sb0 = smem_u32(smem);
    const int t = threadIdx.x;
    const int w = t >> 5, l = t & 31;
    const int m0 = blockIdx.x * BM;
    const int n0 = blockIdx.y * BN;
    const int mrow0 = (w >> 2) * 48;
    const int ncol0 = (w & 3) * 16;

    auto load_s = [&](int s) {
        const int buf = s & 1;
        const int koff = s * 64;
        const uint32_t aH = sb0 + (buf * 2 + 0) * AST;
        const uint32_t aL = sb0 + (buf * 2 + 1) * AST;
#pragma unroll
        for (int c = t; c < 768; c += NTHREADS) {
            int row = c >> 3, k8 = (c & 7) * 8;
            uint32_t so = (uint32_t)(row * 144 + k8 * 2);
            size_t go = (size_t)(m0 + row) * E_DIM + koff + k8;
            cp16(aH + so, Ah + go);
            cp16(aL + so, Al + go);
        }
        const uint32_t bH = sb0 + 4 * AST + (buf * 2 + 0) * BST;
        const uint32_t bL = sb0 + 4 * AST + (buf * 2 + 1) * BST;
#pragma unroll
        for (int c = t; c < 512; c += NTHREADS) {
            int row = c >> 3, k8 = (c & 7) * 8;
            uint32_t so = (uint32_t)(row * 144 + k8 * 2);
            size_t go = (size_t)(n0 + row) * F_DIM + koff + k8;
            cp16(bH + so, Bh + go);
            cp16(bL + so, Bl + go);
        }
    };

    float acc[3][2][4];
#pragma unroll
    for (int i = 0; i < 3; i++)
#pragma unroll
        for (int j = 0; j < 2; j++)
#pragma unroll
            for (int r = 0; r < 4; r++) acc[i][j][r] = 0.0f;

    load_s(0);
    CP_COMMIT();
#pragma unroll 1
    for (int s = 0; s < 8; ++s) {
        if (s < 7) { load_s(s + 1); CP_COMMIT(); CP_WAIT1(); }
        else       { CP_WAIT0(); }
        __syncthreads();
        const int buf = s & 1;
        mma_stage8(acc, sb0 + (buf * 2 + 0) * AST, sb0 + (buf * 2 + 1) * AST,
                   sb0 + 4 * AST + (buf * 2 + 0) * BST, sb0 + 4 * AST + (buf * 2 + 1) * BST,
                   mrow0, ncol0, l);
        __syncthreads();
    }

    // epilogue: + bias, split, store (2 cols per element pair)
#pragma unroll
    for (int mt = 0; mt < 3; mt++)
#pragma unroll
        for (int nf = 0; nf < 2; nf++)
#pragma unroll
            for (int half = 0; half < 2; half++) {
                int row = mrow0 + mt * 16 + (l >> 2) + 8 * half;
                int col = ncol0 + nf * 8 + 2 * (l & 3);
                float v0 = acc[mt][nf][half * 2 + 0] + bias[n0 + col];
                float v1 = acc[mt][nf][half * 2 + 1] + bias[n0 + col + 1];
                __nv_bfloat16 h0 = __float2bfloat16(v0);
                __nv_bfloat16 h1 = __float2bfloat16(v1);
                __nv_bfloat16 l0 = __float2bfloat16(v0 - __bfloat162float(h0));
                __nv_bfloat16 l1 = __float2bfloat16(v1 - __bfloat162float(h1));
                size_t off = (size_t)(m0 + row) * F_DIM + n0 + col;
                __nv_bfloat16 hp[2] = {h0, h1}, lp[2] = {l0, l1};
                *(uint32_t*)(OH + off) = *(uint32_t*)hp;
                *(uint32_t*)(OL + off) = *(uint32_t*)lp;
            }
}

// ---------------------------------------------------------------------------
// Kernel 2: fused attention (8-warp layout, con/off register-resident)
// ---------------------------------------------------------------------------
__device__ __forceinline__ int stage_koff(int s) {
    return (s < 4) ? (256 + s * 64) : ((s - 4) * 64);
}

__device__ __forceinline__ void load_stage(uint32_t sb0, int gs, int m0, int t) {
    const int s = gs & 7;
    const int nt = gs >> 3;
    const int koff = stage_koff(s);
    const int n0 = nt * BN;
    const int buf = gs & 1;
    const uint32_t aH = sb0 + SM_A + (buf * 2 + 0) * AST;
    const uint32_t aL = sb0 + SM_A + (buf * 2 + 1) * AST;
#pragma unroll
    for (int c = t; c < 768; c += NTHREADS) {
        int row = c >> 3, k8 = (c & 7) * 8;
        uint32_t so = (uint32_t)(row * 144 + k8 * 2);
        size_t go = (size_t)(m0 + row) * F_DIM + koff + k8;
        cp16(aH + so, g_RFh + go);
        cp16(aL + so, g_RFl + go);
    }
    const uint32_t bH = sb0 + SM_B + (buf * 2 + 0) * BST;
    const uint32_t bL = sb0 + SM_B + (buf * 2 + 1) * BST;
#pragma unroll
    for (int c = t; c < 512; c += NTHREADS) {
        int row = c >> 3, k8 = (c & 7) * 8;
        uint32_t so = (uint32_t)(row * 144 + k8 * 2);
        size_t go = (size_t)(n0 + row) * F_DIM + koff + k8;
        cp16(bH + so, g_DFh + go);
        cp16(bL + so, g_DFl + go);
    }
}

__device__ __forceinline__ void load_df(uint32_t sb0, int nt, int t) {
    const int n0 = nt * BN;
#pragma unroll
    for (int c = t; c < 512; c += NTHREADS) {
        int row = c >> 3, k8 = (c & 7) * 8;
        uint32_t so = (uint32_t)(row * 144 + k8 * 2);
        size_t go = (size_t)row * ND + n0 + k8;
        cp16(sb0 + SM_DFH + so, g_PDth + go);
        cp16(sb0 + SM_DFL + so, g_PDtl + go);
    }
}

__global__ void __launch_bounds__(NTHREADS, 1) attention_kernel(float* __restrict__ out)
{
    extern __shared__ char smem[];
    const uint32_t sb0 = smem_u32(smem);

    const int t = threadIdx.x;
    const int w = t >> 5, l = t & 31;
    const int m0 = blockIdx.x * BM;
    const int mrow0 = (w >> 2) * 48;
    const int ncol0 = (w & 3) * 16;

    __nv_bfloat16* sWCh = (__nv_bfloat16*)(smem + SM_WCH);
    __nv_bfloat16* sWCl = (__nv_bfloat16*)(smem + SM_WCL);
    float* sRW = (float*)(smem + SM_RW);
    float* sRO = (float*)(smem + SM_RO);

    float ep[3][2][4];
#pragma unroll
    for (int i = 0; i < 3; i++)
#pragma unroll
        for (int j = 0; j < 2; j++)
#pragma unroll
            for (int r = 0; r < 4; r++) ep[i][j][r] = 0.0f;
    float pw[3][2]  = {{0.f,0.f},{0.f,0.f},{0.f,0.f}};
    float pwo[3][2] = {{0.f,0.f},{0.f,0.f},{0.f,0.f}};

    load_stage(sb0, 0, m0, t);
    CP_COMMIT();

#pragma unroll 1
    for (int nt = 0; nt < NTILES; ++nt) {
        float acc[3][2][4];
        float con[3][2][4], off[3][2][4];

#pragma unroll 1
        for (int s = 0; s < NSTG; ++s) {
            const int gs = nt * NSTG + s;
            const bool haveNext = (gs + 1 < NTILES * NSTG);
            if (s == NSTG - 1) { load_df(sb0, nt, t); CP_COMMIT(); }
            if (haveNext) { load_stage(sb0, gs + 1, m0, t); CP_COMMIT(); CP_WAIT1(); }
            else          { CP_WAIT0(); }
            __syncthreads();

            if (s == 0 || s == 2 || s == 4) {
#pragma unroll
                for (int i = 0; i < 3; i++)
#pragma unroll
                    for (int j = 0; j < 2; j++)
#pragma unroll
                        for (int r = 0; r < 4; r++) acc[i][j][r] = 0.0f;
            }
            const int buf = gs & 1;
            mma_stage8(acc,
                       sb0 + SM_A + (buf * 2 + 0) * AST, sb0 + SM_A + (buf * 2 + 1) * AST,
                       sb0 + SM_B + (buf * 2 + 0) * BST, sb0 + SM_B + (buf * 2 + 1) * BST,
                       mrow0, ncol0, l);
            __syncthreads();

            if (s == 1) {          // con ready (k 256..383)
#pragma unroll
                for (int i = 0; i < 3; i++)
#pragma unroll
                    for (int j = 0; j < 2; j++)
#pragma unroll
                        for (int r = 0; r < 4; r++)
                            con[i][j][r] = fast_tanh(acc[i][j][r] * INV_SQRT_H) * MAX_CONTRAST;
            } else if (s == 3) {   // off ready (k 384..511)
#pragma unroll
                for (int i = 0; i < 3; i++)
#pragma unroll
                    for (int j = 0; j < 2; j++)
#pragma unroll
                        for (int r = 0; r < 4; r++)
                            off[i][j][r] = fast_tanh(acc[i][j][r] * INV_SQRT_H);
            }
        }

        // ---- combine: w = exp(l-30); row sums; wc -> bf16 hi/lo smem ----
#pragma unroll
        for (int mt = 0; mt < 3; mt++)
#pragma unroll
            for (int nf = 0; nf < 2; nf++)
#pragma unroll
                for (int r = 0; r < 4; r++) {
                    int row = mrow0 + mt * 16 + (l >> 2) + 8 * (r >> 1);
                    int col = ncol0 + nf * 8 + 2 * (l & 3) + (r & 1);
                    float wgt = __expf(acc[mt][nf][r] - EXP_SHIFT);
                    pw[mt][r >> 1]  += wgt;
                    pwo[mt][r >> 1] += wgt * off[mt][nf][r];
                    float wc = wgt * con[mt][nf][r];
                    __nv_bfloat16 h = __float2bfloat16(wc);
                    sWCh[row * 72 + col] = h;
                    sWCl[row * 72 + col] = __float2bfloat16(wc - __bfloat162float(h));
                }
        __syncthreads();

        // ---- epilogue mma: ep += wc @ pooled^T (k = 64 tile cols) ----
        mma_stage8(ep, sb0 + SM_WCH, sb0 + SM_WCL, sb0 + SM_DFH, sb0 + SM_DFL,
                   mrow0, ncol0, l);
        // next tile's stage barriers guard sWC/sDF reuse
    }

    // ---- row-sum reduce: lanes (xor 1,2) then across the 4 n-warps ----
#pragma unroll
    for (int mt = 0; mt < 3; mt++)
#pragma unroll
        for (int h = 0; h < 2; h++) {
            pw[mt][h]  += __shfl_xor_sync(0xffffffffu, pw[mt][h], 1);
            pw[mt][h]  += __shfl_xor_sync(0xffffffffu, pw[mt][h], 2);
            pwo[mt][h] += __shfl_xor_sync(0xffffffffu, pwo[mt][h], 1);
            pwo[mt][h] += __shfl_xor_sync(0xffffffffu, pwo[mt][h], 2);
        }
    if ((l & 3) == 0) {
        const int wq = w & 3;
#pragma unroll
        for (int mt = 0; mt < 3; mt++)
#pragma unroll
            for (int h = 0; h < 2; h++) {
                int row = mrow0 + mt * 16 + (l >> 2) + 8 * h;
                sRW[wq * 96 + row] = pw[mt][h];
                sRO[wq * 96 + row] = pwo[mt][h];
            }
    }
    __syncthreads();

    // ---- final: out = (ep + sum(w*off)) / sum(w) ----
#pragma unroll
    for (int mt = 0; mt < 3; mt++)
#pragma unroll
        for (int nf = 0; nf < 2; nf++)
#pragma unroll
            for (int half = 0; half < 2; half++) {
                int row = mrow0 + mt * 16 + (l >> 2) + 8 * half;
                int col = ncol0 + nf * 8 + 2 * (l & 3);
                float sw  = sRW[row] + sRW[96 + row] + sRW[192 + row] + sRW[288 + row];
                float swo = sRO[row] + sRO[96 + row] + sRO[192 + row] + sRO[288 + row];
                float inv = 1.0f / sw;
                float2 v;
                v.x = (ep[mt][nf][half * 2 + 0] + swo) * inv;
                v.y = (ep[mt][nf][half * 2 + 1] + swo) * inv;
                *(float2*)(out + (size_t)(m0 + row) * DF_W + col) = v;
            }
}

// ---------------------------------------------------------------------------
// kernel_launch — kernel launches only (graph-capture clean)
// ---------------------------------------------------------------------------
extern "C" void kernel_launch(void* const* d_in, const int* in_sizes, int n_in,
                              void* d_out, int out_size)
{
    const float* pooled = (const float*)d_in[0];
    const float* rl     = (const float*)d_in[1];
    const float* dl     = (const float*)d_in[2];
    const float* rp     = (const float*)d_in[3];
    const float* dp     = (const float*)d_in[4];
    const float* Wrp    = (const float*)d_in[5];
    const float* brp    = (const float*)d_in[6];
    const float* Wdp    = (const float*)d_in[7];
    const float* bdp    = (const float*)d_in[8];
    const float* Wrc    = (const float*)d_in[9];
    const float* brc    = (const float*)d_in[10];
    const float* Wdc    = (const float*)d_in[11];
    const float* bdc    = (const float*)d_in[12];
    const float* Wro    = (const float*)d_in[13];
    const float* bro    = (const float*)d_in[14];
    const float* Wdo    = (const float*)d_in[15];
    const float* bdo    = (const float*)d_in[16];
    float* out = (float*)d_out;

    prep_weights<<<512, 512>>>(Wrp, brp, Wdp, bdp, Wrc, brc, Wdc, bdc,
                               Wro, bro, Wdo, bdo);
    prep_pd<<<ND, DF_W>>>(pooled);
    prep_base<true><<<(NR * E_DIM / 4) / 256, 256>>>(rl, rp);
    prep_base<false><<<(ND * E_DIM / 4) / 256, 256>>>(dl, dp);

    cudaFuncSetAttribute(feat_mma<false>,
                         cudaFuncAttributeMaxDynamicSharedMemorySize, SM2_TOTAL);
    cudaFuncSetAttribute(feat_mma<true>,
                         cudaFuncAttributeMaxDynamicSharedMemorySize, SM2_TOTAL);
    dim3 gridD(ND / BM, F_DIM / BN);   // 18 x 8
    feat_mma<false><<<gridD, NTHREADS, SM2_TOTAL>>>();
    dim3 gridR(NR / BM, F_DIM / BN);   // 144 x 8
    feat_mma<true><<<gridR, NTHREADS, SM2_TOTAL>>>();

    cudaFuncSetAttribute(attention_kernel,
                         cudaFuncAttributeMaxDynamicSharedMemorySize, SM_TOTAL);
    attention_kernel<<<NR / BM, NTHREADS, SM_TOTAL>>>(out);
}

// round 8
// speedup vs baseline: 5.0845x; 1.0054x over previous
#include <cuda_runtime.h>
#include <cuda_bf16.h>
#include <cstdint>
#include <math.h>

// ---------------------------------------------------------------------------
// FractalAttention3D — mma.sync bf16 (2-way split), 8-warp tiling,
//   3-buffer cp.async pipeline (1 barrier/stage) in the attention kernel.
//   Family-portable PTX only (sm_80+): mma.sync / ldmatrix / cp.async.
// ---------------------------------------------------------------------------

#define NR 13824
#define ND 1728
#define E_DIM 512
#define F_DIM 512
#define DF_W 64
#define LOGIT_SCALE 0.25f
#define INV_SQRT_H 0.08838834764831843f
#define MAX_CONTRAST 1.8f
#define EXP_SHIFT 30.0f

#define BM 96                 // 13824/96 = 144 CTAs ~ one wave
#define BN 64
#define NTILES (ND / BN)      // 27
#define NSTG 8                // stages per tile (2 con + 2 off + 4 repr)
#define NTHREADS 256          // 8 warps: 2m x 4n grid of 48x16 warp tiles

// -------- device scratch (static; no cudaMalloc allowed) --------
__device__ __align__(16) float g_br[F_DIM];
__device__ __align__(16) float g_bd[F_DIM];
__device__ __align__(16) __nv_bfloat16 g_Wrth[(size_t)F_DIM * F_DIM];
__device__ __align__(16) __nv_bfloat16 g_Wrtl[(size_t)F_DIM * F_DIM];
__device__ __align__(16) __nv_bfloat16 g_Wdth[(size_t)F_DIM * F_DIM];
__device__ __align__(16) __nv_bfloat16 g_Wdtl[(size_t)F_DIM * F_DIM];
__device__ __align__(16) __nv_bfloat16 g_RBh[(size_t)NR * E_DIM];
__device__ __align__(16) __nv_bfloat16 g_RBl[(size_t)NR * E_DIM];
__device__ __align__(16) __nv_bfloat16 g_DBh[(size_t)ND * E_DIM];
__device__ __align__(16) __nv_bfloat16 g_DBl[(size_t)ND * E_DIM];
__device__ __align__(16) __nv_bfloat16 g_RFh[(size_t)NR * F_DIM];
__device__ __align__(16) __nv_bfloat16 g_RFl[(size_t)NR * F_DIM];
__device__ __align__(16) __nv_bfloat16 g_DFh[(size_t)ND * F_DIM];
__device__ __align__(16) __nv_bfloat16 g_DFl[(size_t)ND * F_DIM];
__device__ __align__(16) __nv_bfloat16 g_PDth[(size_t)DF_W * ND];  // pooled^T hi [64][1728]
__device__ __align__(16) __nv_bfloat16 g_PDtl[(size_t)DF_W * ND];

// ---------------- attention smem layout (bytes): 3 bufs x (hi,lo) ----------
#define AST 13824            // 96*72*2 (stride 144B/row)
#define BST 9216             // 64*72*2
#define SM_A   0             // 6*AST = 82944
#define SM_B   82944         // 6*BST = 55296
#define SM_WCH 138240        // 13824
#define SM_WCL 152064        // 13824
#define SM_DFH 165888        // 9216
#define SM_DFL 175104        // 9216
#define SM_RW  184320        // 4*96*4 = 1536
#define SM_RO  185856        // 1536
#define SM_TOTAL 187392

// feat_mma smem: 2 bufs (double-buffer) -> 2 CTAs/SM
#define SM2_TOTAL 92160

// ---------------- PTX helpers (sm_80-portable) ----------------
__device__ __forceinline__ uint32_t smem_u32(const void* p) {
    uint32_t a;
    asm("{ .reg .u64 t; cvta.to.shared.u64 t, %1; cvt.u32.u64 %0, t; }" : "=r"(a) : "l"(p));
    return a;
}
__device__ __forceinline__ void cp16(uint32_t dst, const void* src) {
    asm volatile("cp.async.cg.shared.global [%0], [%1], 16;" :: "r"(dst), "l"(src));
}
#define CP_COMMIT() asm volatile("cp.async.commit_group;" ::: "memory")
#define CP_WAIT1()  asm volatile("cp.async.wait_group 1;" ::: "memory")
#define CP_WAIT0()  asm volatile("cp.async.wait_group 0;" ::: "memory")

__device__ __forceinline__ void ldsm4(uint32_t& r0, uint32_t& r1, uint32_t& r2, uint32_t& r3,
                                      uint32_t addr) {
    asm volatile("ldmatrix.sync.aligned.m8n8.x4.shared.b16 {%0,%1,%2,%3}, [%4];"
                 : "=r"(r0), "=r"(r1), "=r"(r2), "=r"(r3) : "r"(addr));
}
__device__ __forceinline__ void mma_bf16(float* c, const uint32_t* a, uint32_t b0, uint32_t b1) {
    asm("mma.sync.aligned.m16n8k16.row.col.f32.bf16.bf16.f32 "
        "{%0,%1,%2,%3}, {%4,%5,%6,%7}, {%8,%9}, {%0,%1,%2,%3};"
        : "+f"(c[0]), "+f"(c[1]), "+f"(c[2]), "+f"(c[3])
        : "r"(a[0]), "r"(a[1]), "r"(a[2]), "r"(a[3]), "r"(b0), "r"(b1));
}
__device__ __forceinline__ float fast_tanh(float x) {
    float e = __expf(-2.0f * x);
    return __fdividef(2.0f, e + 1.0f) - 1.0f;
}

// ---------------------------------------------------------------------------
// prep kernels (unchanged)
// ---------------------------------------------------------------------------
__global__ void prep_weights(
    const float* __restrict__ Wrp, const float* __restrict__ brp,
    const float* __restrict__ Wdp, const float* __restrict__ bdp,
    const float* __restrict__ Wrc, const float* __restrict__ brc,
    const float* __restrict__ Wdc, const float* __restrict__ bdc,
    const float* __restrict__ Wro, const float* __restrict__ bro,
    const float* __restrict__ Wdo, const float* __restrict__ bdo)
{
    int e = blockIdx.x, j = threadIdx.x;   // e = k index, j = n index
    float wr, wd;
    if (j < 256)      { wr = Wrp[e * 256 + j] * LOGIT_SCALE; wd = Wdp[e * 256 + j]; }
    else if (j < 384) { wr = Wrc[e * 128 + (j - 256)];       wd = Wdc[e * 128 + (j - 256)]; }
    else              { wr = Wro[e * 128 + (j - 384)];       wd = Wdo[e * 128 + (j - 384)]; }
    size_t toff = (size_t)j * F_DIM + e;   // transposed [n][k]
    __nv_bfloat16 h = __float2bfloat16(wr);
    g_Wrth[toff] = h;
    g_Wrtl[toff] = __float2bfloat16(wr - __bfloat162float(h));
    h = __float2bfloat16(wd);
    g_Wdth[toff] = h;
    g_Wdtl[toff] = __float2bfloat16(wd - __bfloat162float(h));
    if (e == 0) {
        float br, bd;
        if (j < 256)      { br = brp[j] * LOGIT_SCALE; bd = bdp[j]; }
        else if (j < 384) { br = brc[j - 256];         bd = bdc[j - 256]; }
        else              { br = bro[j - 384];         bd = bdo[j - 384]; }
        g_br[j] = br;
        g_bd[j] = bd;
    }
}

__global__ void prep_pd(const float* __restrict__ pooled) {
    int n = blockIdx.x, d = threadIdx.x;
    float v = pooled[(size_t)n * DF_W + d];
    __nv_bfloat16 h = __float2bfloat16(v);
    g_PDth[(size_t)d * ND + n] = h;
    g_PDtl[(size_t)d * ND + n] = __float2bfloat16(v - __bfloat162float(h));
}

template <bool RANGE>
__global__ void prep_base(const float* __restrict__ lat, const float* __restrict__ pos)
{
    __nv_bfloat16* __restrict__ OH = RANGE ? g_RBh : g_DBh;
    __nv_bfloat16* __restrict__ OL = RANGE ? g_RBl : g_DBl;
    size_t i = ((size_t)blockIdx.x * blockDim.x + threadIdx.x) * 4;
    float4 a = *(const float4*)(lat + i);
    float4 b = *(const float4*)(pos + i);
    float v[4] = {a.x + b.x, a.y + b.y, a.z + b.z, a.w + b.w};
    __nv_bfloat16 hb[4], lb[4];
#pragma unroll
    for (int j = 0; j < 4; j++) {
        hb[j] = __float2bfloat16(v[j]);
        lb[j] = __float2bfloat16(v[j] - __bfloat162float(hb[j]));
    }
    *(uint2*)(OH + i) = *(uint2*)hb;
    *(uint2*)(OL + i) = *(uint2*)lb;
}

// ---------------------------------------------------------------------------
// 8-warp MMA stage: per warp 48m x 16n over a 96x64x64 tile.
// ---------------------------------------------------------------------------
__device__ __forceinline__ void mma_stage8(
    float (&acc)[3][2][4], uint32_t aH, uint32_t aL, uint32_t bH, uint32_t bL,
    int mrow0, int ncol0, int l)
{
    const uint32_t aRowOff = (uint32_t)((l & 15) * 144) + (uint32_t)((l >> 4) * 16);
    const uint32_t bRowOff = (uint32_t)((ncol0 + ((l >> 4) & 1) * 8 + (l & 7)) * 144)
                           + (uint32_t)(((l >> 3) & 1) * 16);
#pragma unroll
    for (int k16 = 0; k16 < 4; k16++) {
        const uint32_t kb = (uint32_t)(k16 * 32);
        uint32_t ah[3][4], al[3][4], bh[4], bl[4];
#pragma unroll
        for (int mt = 0; mt < 3; mt++) {
            uint32_t off = (uint32_t)((mrow0 + mt * 16) * 144) + aRowOff + kb;
            ldsm4(ah[mt][0], ah[mt][1], ah[mt][2], ah[mt][3], aH + off);
            ldsm4(al[mt][0], al[mt][1], al[mt][2], al[mt][3], aL + off);
        }
        {
            uint32_t off = bRowOff + kb;
            ldsm4(bh[0], bh[1], bh[2], bh[3], bH + off);
            ldsm4(bl[0], bl[1], bl[2], bl[3], bL + off);
        }
#pragma unroll
        for (int mt = 0; mt < 3; mt++)
#pragma unroll
            for (int nf = 0; nf < 2; nf++) {
                const int ri = nf * 2;
                mma_bf16(acc[mt][nf], ah[mt], bh[ri], bh[ri + 1]);
                mma_bf16(acc[mt][nf], ah[mt], bl[ri], bl[ri + 1]);
                mma_bf16(acc[mt][nf], al[mt], bh[ri], bh[ri + 1]);
            }
    }
}

// ---------------------------------------------------------------------------
// Kernel 1: feature GEMM on tensor cores (unchanged: 2-buf, 2 CTAs/SM)
// ---------------------------------------------------------------------------
template <bool RANGE>
__global__ void __launch_bounds__(NTHREADS, 1) feat_mma()
{
    const __nv_bfloat16* __restrict__ Ah = RANGE ? g_RBh : g_DBh;
    const __nv_bfloat16* __restrict__ Al = RANGE ? g_RBl : g_DBl;
    const __nv_bfloat16* __restrict__ Bh = RANGE ? g_Wrth : g_Wdth;
    const __nv_bfloat16* __restrict__ Bl = RANGE ? g_Wrtl : g_Wdtl;
    const float* __restrict__ bias = RANGE ? g_br : g_bd;
    __nv_bfloat16* __restrict__ OH = RANGE ? g_RFh : g_DFh;
    __nv_bfloat16* __restrict__ OL = RANGE ? g_RFl : g_DFl;

    extern __shared__ char smem[];
    const uint32_t sb0 = smem_u32(smem);
    const int t = threadIdx.x;
    const int w = t >> 5, l = t & 31;
    const int m0 = blockIdx.x * BM;
    const int n0 = blockIdx.y * BN;
    const int mrow0 = (w >> 2) * 48;
    const int ncol0 = (w & 3) * 16;

    auto load_s = [&](int s) {
        const int buf = s & 1;
        const int koff = s * 64;
        const uint32_t aH = sb0 + (buf * 2 + 0) * AST;
        const uint32_t aL = sb0 + (buf * 2 + 1) * AST;
#pragma unroll
        for (int c = t; c < 768; c += NTHREADS) {
            int row = c >> 3, k8 = (c & 7) * 8;
            uint32_t so = (uint32_t)(row * 144 + k8 * 2);
            size_t go = (size_t)(m0 + row) * E_DIM + koff + k8;
            cp16(aH + so, Ah + go);
            cp16(aL + so, Al + go);
        }
        const uint32_t bH = sb0 + 4 * AST + (buf * 2 + 0) * BST;
        const uint32_t bL = sb0 + 4 * AST + (buf * 2 + 1) * BST;
#pragma unroll
        for (int c = t; c < 512; c += NTHREADS) {
            int row = c >> 3, k8 = (c & 7) * 8;
            uint32_t so = (uint32_t)(row * 144 + k8 * 2);
            size_t go = (size_t)(n0 + row) * F_DIM + koff + k8;
            cp16(bH + so, Bh + go);
            cp16(bL + so, Bl + go);
        }
    };

    float acc[3][2][4];
#pragma unroll
    for (int i = 0; i < 3; i++)
#pragma unroll
        for (int j = 0; j < 2; j++)
#pragma unroll
            for (int r = 0; r < 4; r++) acc[i][j][r] = 0.0f;

    load_s(0);
    CP_COMMIT();
#pragma unroll 1
    for (int s = 0; s < 8; ++s) {
        if (s < 7) { load_s(s + 1); CP_COMMIT(); CP_WAIT1(); }
        else       { CP_WAIT0(); }
        __syncthreads();
        const int buf = s & 1;
        mma_stage8(acc, sb0 + (buf * 2 + 0) * AST, sb0 + (buf * 2 + 1) * AST,
                   sb0 + 4 * AST + (buf * 2 + 0) * BST, sb0 + 4 * AST + (buf * 2 + 1) * BST,
                   mrow0, ncol0, l);
        __syncthreads();
    }

    // epilogue: + bias, split, store
#pragma unroll
    for (int mt = 0; mt < 3; mt++)
#pragma unroll
        for (int nf = 0; nf < 2; nf++)
#pragma unroll
            for (int half = 0; half < 2; half++) {
                int row = mrow0 + mt * 16 + (l >> 2) + 8 * half;
                int col = ncol0 + nf * 8 + 2 * (l & 3);
                float v0 = acc[mt][nf][half * 2 + 0] + bias[n0 + col];
                float v1 = acc[mt][nf][half * 2 + 1] + bias[n0 + col + 1];
                __nv_bfloat16 h0 = __float2bfloat16(v0);
                __nv_bfloat16 h1 = __float2bfloat16(v1);
                __nv_bfloat16 l0 = __float2bfloat16(v0 - __bfloat162float(h0));
                __nv_bfloat16 l1 = __float2bfloat16(v1 - __bfloat162float(h1));
                size_t off = (size_t)(m0 + row) * F_DIM + n0 + col;
                __nv_bfloat16 hp[2] = {h0, h1}, lp[2] = {l0, l1};
                *(uint32_t*)(OH + off) = *(uint32_t*)hp;
                *(uint32_t*)(OL + off) = *(uint32_t*)lp;
            }
}

// ---------------------------------------------------------------------------
// Kernel 2: fused attention — 3-buffer pipeline, one barrier per stage
// ---------------------------------------------------------------------------
__device__ __forceinline__ int stage_koff(int s) {
    return (s < 4) ? (256 + s * 64) : ((s - 4) * 64);
}

__device__ __forceinline__ void load_stage(uint32_t sb0, int gs, int m0, int t) {
    const int s = gs & 7;
    const int nt = gs >> 3;
    const int koff = stage_koff(s);
    const int n0 = nt * BN;
    const int buf = gs % 3;
    const uint32_t aH = sb0 + SM_A + (buf * 2 + 0) * AST;
    const uint32_t aL = sb0 + SM_A + (buf * 2 + 1) * AST;
#pragma unroll
    for (int c = t; c < 768; c += NTHREADS) {
        int row = c >> 3, k8 = (c & 7) * 8;
        uint32_t so = (uint32_t)(row * 144 + k8 * 2);
        size_t go = (size_t)(m0 + row) * F_DIM + koff + k8;
        cp16(aH + so, g_RFh + go);
        cp16(aL + so, g_RFl + go);
    }
    const uint32_t bH = sb0 + SM_B + (buf * 2 + 0) * BST;
    const uint32_t bL = sb0 + SM_B + (buf * 2 + 1) * BST;
#pragma unroll
    for (int c = t; c < 512; c += NTHREADS) {
        int row = c >> 3, k8 = (c & 7) * 8;
        uint32_t so = (uint32_t)(row * 144 + k8 * 2);
        size_t go = (size_t)(n0 + row) * F_DIM + koff + k8;
        cp16(bH + so, g_DFh + go);
        cp16(bL + so, g_DFl + go);
    }
}

__device__ __forceinline__ void load_df(uint32_t sb0, int nt, int t) {
    const int n0 = nt * BN;
#pragma unroll
    for (int c = t; c < 512; c += NTHREADS) {
        int row = c >> 3, k8 = (c & 7) * 8;
        uint32_t so = (uint32_t)(row * 144 + k8 * 2);
        size_t go = (size_t)row * ND + n0 + k8;
        cp16(sb0 + SM_DFH + so, g_PDth + go);
        cp16(sb0 + SM_DFL + so, g_PDtl + go);
    }
}

__global__ void __launch_bounds__(NTHREADS, 1) attention_kernel(float* __restrict__ out)
{
    extern __shared__ char smem[];
    const uint32_t sb0 = smem_u32(smem);

    const int t = threadIdx.x;
    const int w = t >> 5, l = t & 31;
    const int m0 = blockIdx.x * BM;
    const int mrow0 = (w >> 2) * 48;
    const int ncol0 = (w & 3) * 16;

    __nv_bfloat16* sWCh = (__nv_bfloat16*)(smem + SM_WCH);
    __nv_bfloat16* sWCl = (__nv_bfloat16*)(smem + SM_WCL);
    float* sRW = (float*)(smem + SM_RW);
    float* sRO = (float*)(smem + SM_RO);

    float ep[3][2][4];
#pragma unroll
    for (int i = 0; i < 3; i++)
#pragma unroll
        for (int j = 0; j < 2; j++)
#pragma unroll
            for (int r = 0; r < 4; r++) ep[i][j][r] = 0.0f;
    float pw[3][2]  = {{0.f,0.f},{0.f,0.f},{0.f,0.f}};
    float pwo[3][2] = {{0.f,0.f},{0.f,0.f},{0.f,0.f}};

    // prologue: two stages in flight
    load_stage(sb0, 0, m0, t);
    CP_COMMIT();
    load_stage(sb0, 1, m0, t);
    CP_COMMIT();

#pragma unroll 1
    for (int nt = 0; nt < NTILES; ++nt) {
        float acc[3][2][4];
        float con[3][2][4], off[3][2][4];

#pragma unroll 1
        for (int s = 0; s < NSTG; ++s) {
            const int gs = nt * NSTG + s;
            // wait for stage gs data (allow 1 newer group in flight), then barrier
            CP_WAIT1();
            __syncthreads();
            // issue loads for stage gs+2 (after the barrier: the buffer it
            // writes, (gs+2)%3 == (gs-1)%3, had its readers ordered before
            // this barrier). Commit unconditionally to keep group counting
            // uniform.
            {
                const int ns = gs + 2;
                if (ns < NTILES * NSTG) load_stage(sb0, ns, m0, t);
                if (s == 5) load_df(sb0, nt, t);
                CP_COMMIT();
            }

            if (s == 0 || s == 2 || s == 4) {
#pragma unroll
                for (int i = 0; i < 3; i++)
#pragma unroll
                    for (int j = 0; j < 2; j++)
#pragma unroll
                        for (int r = 0; r < 4; r++) acc[i][j][r] = 0.0f;
            }
            const int buf = gs % 3;
            mma_stage8(acc,
                       sb0 + SM_A + (buf * 2 + 0) * AST, sb0 + SM_A + (buf * 2 + 1) * AST,
                       sb0 + SM_B + (buf * 2 + 0) * BST, sb0 + SM_B + (buf * 2 + 1) * BST,
                       mrow0, ncol0, l);

            if (s == 1) {          // con ready (k 256..383)
#pragma unroll
                for (int i = 0; i < 3; i++)
#pragma unroll
                    for (int j = 0; j < 2; j++)
#pragma unroll
                        for (int r = 0; r < 4; r++)
                            con[i][j][r] = fast_tanh(acc[i][j][r] * INV_SQRT_H) * MAX_CONTRAST;
            } else if (s == 3) {   // off ready (k 384..511)
#pragma unroll
                for (int i = 0; i < 3; i++)
#pragma unroll
                    for (int j = 0; j < 2; j++)
#pragma unroll
                        for (int r = 0; r < 4; r++)
                            off[i][j][r] = fast_tanh(acc[i][j][r] * INV_SQRT_H);
            }
        }

        // ---- combine: w = exp(l-30); row sums; wc -> bf16 hi/lo smem ----
#pragma unroll
        for (int mt = 0; mt < 3; mt++)
#pragma unroll
            for (int nf = 0; nf < 2; nf++)
#pragma unroll
                for (int r = 0; r < 4; r++) {
                    int row = mrow0 + mt * 16 + (l >> 2) + 8 * (r >> 1);
                    int col = ncol0 + nf * 8 + 2 * (l & 3) + (r & 1);
                    float wgt = __expf(acc[mt][nf][r] - EXP_SHIFT);
                    pw[mt][r >> 1]  += wgt;
                    pwo[mt][r >> 1] += wgt * off[mt][nf][r];
                    float wc = wgt * con[mt][nf][r];
                    __nv_bfloat16 h = __float2bfloat16(wc);
                    sWCh[row * 72 + col] = h;
                    sWCl[row * 72 + col] = __float2bfloat16(wc - __bfloat162float(h));
                }
        __syncthreads();

        // ---- epilogue mma: ep += wc @ pooled^T (k = 64 tile cols) ----
        mma_stage8(ep, sb0 + SM_WCH, sb0 + SM_WCL, sb0 + SM_DFH, sb0 + SM_DFL,
                   mrow0, ncol0, l);
        // next tile's stage barriers order these reads before sWC/sDF rewrite
    }

    // ---- row-sum reduce: lanes (xor 1,2) then across the 4 n-warps ----
#pragma unroll
    for (int mt = 0; mt < 3; mt++)
#pragma unroll
        for (int h = 0; h < 2; h++) {
            pw[mt][h]  += __shfl_xor_sync(0xffffffffu, pw[mt][h], 1);
            pw[mt][h]  += __shfl_xor_sync(0xffffffffu, pw[mt][h], 2);
            pwo[mt][h] += __shfl_xor_sync(0xffffffffu, pwo[mt][h], 1);
            pwo[mt][h] += __shfl_xor_sync(0xffffffffu, pwo[mt][h], 2);
        }
    if ((l & 3) == 0) {
        const int wq = w & 3;
#pragma unroll
        for (int mt = 0; mt < 3; mt++)
#pragma unroll
            for (int h = 0; h < 2; h++) {
                int row = mrow0 + mt * 16 + (l >> 2) + 8 * h;
                sRW[wq * 96 + row] = pw[mt][h];
                sRO[wq * 96 + row] = pwo[mt][h];
            }
    }
    __syncthreads();

    // ---- final: out = (ep + sum(w*off)) / sum(w) ----
#pragma unroll
    for (int mt = 0; mt < 3; mt++)
#pragma unroll
        for (int nf = 0; nf < 2; nf++)
#pragma unroll
            for (int half = 0; half < 2; half++) {
                int row = mrow0 + mt * 16 + (l >> 2) + 8 * half;
                int col = ncol0 + nf * 8 + 2 * (l & 3);
                float sw  = sRW[row] + sRW[96 + row] + sRW[192 + row] + sRW[288 + row];
                float swo = sRO[row] + sRO[96 + row] + sRO[192 + row] + sRO[288 + row];
                float inv = 1.0f / sw;
                float2 v;
                v.x = (ep[mt][nf][half * 2 + 0] + swo) * inv;
                v.y = (ep[mt][nf][half * 2 + 1] + swo) * inv;
                *(float2*)(out + (size_t)(m0 + row) * DF_W + col) = v;
            }
}

// ---------------------------------------------------------------------------
// kernel_launch — kernel launches only (graph-capture clean)
// ---------------------------------------------------------------------------
extern "C" void kernel_launch(void* const* d_in, const int* in_sizes, int n_in,
                              void* d_out, int out_size)
{
    const float* pooled = (const float*)d_in[0];
    const float* rl     = (const float*)d_in[1];
    const float* dl     = (const float*)d_in[2];
    const float* rp     = (const float*)d_in[3];
    const float* dp     = (const float*)d_in[4];
    const float* Wrp    = (const float*)d_in[5];
    const float* brp    = (const float*)d_in[6];
    const float* Wdp    = (const float*)d_in[7];
    const float* bdp    = (const float*)d_in[8];
    const float* Wrc    = (const float*)d_in[9];
    const float* brc    = (const float*)d_in[10];
    const float* Wdc    = (const float*)d_in[11];
    const float* bdc    = (const float*)d_in[12];
    const float* Wro    = (const float*)d_in[13];
    const float* bro    = (const float*)d_in[14];
    const float* Wdo    = (const float*)d_in[15];
    const float* bdo    = (const float*)d_in[16];
    float* out = (float*)d_out;

    prep_weights<<<512, 512>>>(Wrp, brp, Wdp, bdp, Wrc, brc, Wdc, bdc,
                               Wro, bro, Wdo, bdo);
    prep_pd<<<ND, DF_W>>>(pooled);
    prep_base<true><<<(NR * E_DIM / 4) / 256, 256>>>(rl, rp);
    prep_base<false><<<(ND * E_DIM / 4) / 256, 256>>>(dl, dp);

    cudaFuncSetAttribute(feat_mma<false>,
                         cudaFuncAttributeMaxDynamicSharedMemorySize, SM2_TOTAL);
    cudaFuncSetAttribute(feat_mma<true>,
                         cudaFuncAttributeMaxDynamicSharedMemorySize, SM2_TOTAL);
    dim3 gridD(ND / BM, F_DIM / BN);   // 18 x 8
    feat_mma<false><<<gridD, NTHREADS, SM2_TOTAL>>>();
    dim3 gridR(NR / BM, F_DIM / BN);   // 144 x 8
    feat_mma<true><<<gridR, NTHREADS, SM2_TOTAL>>>();

    cudaFuncSetAttribute(attention_kernel,
                         cudaFuncAttributeMaxDynamicSharedMemorySize, SM_TOTAL);
    attention_kernel<<<NR / BM, NTHREADS, SM_TOTAL>>>(out);
}

// round 9
// speedup vs baseline: 5.1022x; 1.0035x over previous
#include <cuda_runtime.h>
#include <cuda_bf16.h>
#include <cstdint>
#include <math.h>

// ---------------------------------------------------------------------------
// FractalAttention3D — mma.sync bf16 (2-way split), 8-warp tiling,
//   3-buffer cp.async pipeline + k16-level fragment double-buffering.
//   Family-portable PTX only (sm_80+): mma.sync / ldmatrix / cp.async.
// ---------------------------------------------------------------------------

#define NR 13824
#define ND 1728
#define E_DIM 512
#define F_DIM 512
#define DF_W 64
#define LOGIT_SCALE 0.25f
#define INV_SQRT_H 0.08838834764831843f
#define MAX_CONTRAST 1.8f
#define EXP_SHIFT 30.0f

#define BM 96                 // 13824/96 = 144 CTAs ~ one wave
#define BN 64
#define NTILES (ND / BN)      // 27
#define NSTG 8                // stages per tile (2 con + 2 off + 4 repr)
#define NTHREADS 256          // 8 warps: 2m x 4n grid of 48x16 warp tiles

// -------- device scratch (static; no cudaMalloc allowed) --------
__device__ __align__(16) float g_br[F_DIM];
__device__ __align__(16) float g_bd[F_DIM];
__device__ __align__(16) __nv_bfloat16 g_Wrth[(size_t)F_DIM * F_DIM];
__device__ __align__(16) __nv_bfloat16 g_Wrtl[(size_t)F_DIM * F_DIM];
__device__ __align__(16) __nv_bfloat16 g_Wdth[(size_t)F_DIM * F_DIM];
__device__ __align__(16) __nv_bfloat16 g_Wdtl[(size_t)F_DIM * F_DIM];
__device__ __align__(16) __nv_bfloat16 g_RBh[(size_t)NR * E_DIM];
__device__ __align__(16) __nv_bfloat16 g_RBl[(size_t)NR * E_DIM];
__device__ __align__(16) __nv_bfloat16 g_DBh[(size_t)ND * E_DIM];
__device__ __align__(16) __nv_bfloat16 g_DBl[(size_t)ND * E_DIM];
__device__ __align__(16) __nv_bfloat16 g_RFh[(size_t)NR * F_DIM];
__device__ __align__(16) __nv_bfloat16 g_RFl[(size_t)NR * F_DIM];
__device__ __align__(16) __nv_bfloat16 g_DFh[(size_t)ND * F_DIM];
__device__ __align__(16) __nv_bfloat16 g_DFl[(size_t)ND * F_DIM];
__device__ __align__(16) __nv_bfloat16 g_PDth[(size_t)DF_W * ND];  // pooled^T hi [64][1728]
__device__ __align__(16) __nv_bfloat16 g_PDtl[(size_t)DF_W * ND];

// ---------------- attention smem layout (bytes): 3 bufs x (hi,lo) ----------
#define AST 13824            // 96*72*2 (stride 144B/row)
#define BST 9216             // 64*72*2
#define SM_A   0             // 6*AST = 82944
#define SM_B   82944         // 6*BST = 55296
#define SM_WCH 138240        // 13824
#define SM_WCL 152064        // 13824
#define SM_DFH 165888        // 9216
#define SM_DFL 175104        // 9216
#define SM_RW  184320        // 4*96*4 = 1536
#define SM_RO  185856        // 1536
#define SM_TOTAL 187392

// feat_mma smem: 2 bufs (double-buffer) -> 2 CTAs/SM
#define SM2_TOTAL 92160

// ---------------- PTX helpers (sm_80-portable) ----------------
__device__ __forceinline__ uint32_t smem_u32(const void* p) {
    uint32_t a;
    asm("{ .reg .u64 t; cvta.to.shared.u64 t, %1; cvt.u32.u64 %0, t; }" : "=r"(a) : "l"(p));
    return a;
}
__device__ __forceinline__ void cp16(uint32_t dst, const void* src) {
    asm volatile("cp.async.cg.shared.global [%0], [%1], 16;" :: "r"(dst), "l"(src));
}
#define CP_COMMIT() asm volatile("cp.async.commit_group;" ::: "memory")
#define CP_WAIT1()  asm volatile("cp.async.wait_group 1;" ::: "memory")
#define CP_WAIT0()  asm volatile("cp.async.wait_group 0;" ::: "memory")

__device__ __forceinline__ void ldsm4(uint32_t& r0, uint32_t& r1, uint32_t& r2, uint32_t& r3,
                                      uint32_t addr) {
    asm volatile("ldmatrix.sync.aligned.m8n8.x4.shared.b16 {%0,%1,%2,%3}, [%4];"
                 : "=r"(r0), "=r"(r1), "=r"(r2), "=r"(r3) : "r"(addr));
}
__device__ __forceinline__ void mma_bf16(float* c, const uint32_t* a, uint32_t b0, uint32_t b1) {
    asm("mma.sync.aligned.m16n8k16.row.col.f32.bf16.bf16.f32 "
        "{%0,%1,%2,%3}, {%4,%5,%6,%7}, {%8,%9}, {%0,%1,%2,%3};"
        : "+f"(c[0]), "+f"(c[1]), "+f"(c[2]), "+f"(c[3])
        : "r"(a[0]), "r"(a[1]), "r"(a[2]), "r"(a[3]), "r"(b0), "r"(b1));
}
__device__ __forceinline__ float fast_tanh(float x) {
    float e = __expf(-2.0f * x);
    return __fdividef(2.0f, e + 1.0f) - 1.0f;
}

// ---------------------------------------------------------------------------
// prep kernels (unchanged)
// ---------------------------------------------------------------------------
__global__ void prep_weights(
    const float* __restrict__ Wrp, const float* __restrict__ brp,
    const float* __restrict__ Wdp, const float* __restrict__ bdp,
    const float* __restrict__ Wrc, const float* __restrict__ brc,
    const float* __restrict__ Wdc, const float* __restrict__ bdc,
    const float* __restrict__ Wro, const float* __restrict__ bro,
    const float* __restrict__ Wdo, const float* __restrict__ bdo)
{
    int e = blockIdx.x, j = threadIdx.x;   // e = k index, j = n index
    float wr, wd;
    if (j < 256)      { wr = Wrp[e * 256 + j] * LOGIT_SCALE; wd = Wdp[e * 256 + j]; }
    else if (j < 384) { wr = Wrc[e * 128 + (j - 256)];       wd = Wdc[e * 128 + (j - 256)]; }
    else              { wr = Wro[e * 128 + (j - 384)];       wd = Wdo[e * 128 + (j - 384)]; }
    size_t toff = (size_t)j * F_DIM + e;   // transposed [n][k]
    __nv_bfloat16 h = __float2bfloat16(wr);
    g_Wrth[toff] = h;
    g_Wrtl[toff] = __float2bfloat16(wr - __bfloat162float(h));
    h = __float2bfloat16(wd);
    g_Wdth[toff] = h;
    g_Wdtl[toff] = __float2bfloat16(wd - __bfloat162float(h));
    if (e == 0) {
        float br, bd;
        if (j < 256)      { br = brp[j] * LOGIT_SCALE; bd = bdp[j]; }
        else if (j < 384) { br = brc[j - 256];         bd = bdc[j - 256]; }
        else              { br = bro[j - 384];         bd = bdo[j - 384]; }
        g_br[j] = br;
        g_bd[j] = bd;
    }
}

__global__ void prep_pd(const float* __restrict__ pooled) {
    int n = blockIdx.x, d = threadIdx.x;
    float v = pooled[(size_t)n * DF_W + d];
    __nv_bfloat16 h = __float2bfloat16(v);
    g_PDth[(size_t)d * ND + n] = h;
    g_PDtl[(size_t)d * ND + n] = __float2bfloat16(v - __bfloat162float(h));
}

template <bool RANGE>
__global__ void prep_base(const float* __restrict__ lat, const float* __restrict__ pos)
{
    __nv_bfloat16* __restrict__ OH = RANGE ? g_RBh : g_DBh;
    __nv_bfloat16* __restrict__ OL = RANGE ? g_RBl : g_DBl;
    size_t i = ((size_t)blockIdx.x * blockDim.x + threadIdx.x) * 4;
    float4 a = *(const float4*)(lat + i);
    float4 b = *(const float4*)(pos + i);
    float v[4] = {a.x + b.x, a.y + b.y, a.z + b.z, a.w + b.w};
    __nv_bfloat16 hb[4], lb[4];
#pragma unroll
    for (int j = 0; j < 4; j++) {
        hb[j] = __float2bfloat16(v[j]);
        lb[j] = __float2bfloat16(v[j] - __bfloat162float(hb[j]));
    }
    *(uint2*)(OH + i) = *(uint2*)hb;
    *(uint2*)(OL + i) = *(uint2*)lb;
}

// ---------------------------------------------------------------------------
// Fragment loads for one k16 slice (8 ldsm4 per warp)
// ---------------------------------------------------------------------------
__device__ __forceinline__ void ld_frags(
    uint32_t (&ah)[3][4], uint32_t (&al)[3][4], uint32_t (&bh)[4], uint32_t (&bl)[4],
    uint32_t aH, uint32_t aL, uint32_t bH, uint32_t bL,
    uint32_t aRowOff, uint32_t bRowOff, int mrow0, uint32_t kb)
{
#pragma unroll
    for (int mt = 0; mt < 3; mt++) {
        uint32_t off = (uint32_t)((mrow0 + mt * 16) * 144) + aRowOff + kb;
        ldsm4(ah[mt][0], ah[mt][1], ah[mt][2], ah[mt][3], aH + off);
        ldsm4(al[mt][0], al[mt][1], al[mt][2], al[mt][3], aL + off);
    }
    uint32_t off = bRowOff + kb;
    ldsm4(bh[0], bh[1], bh[2], bh[3], bH + off);
    ldsm4(bl[0], bl[1], bl[2], bl[3], bL + off);
}

// ---------------------------------------------------------------------------
// 8-warp MMA stage with k16-level fragment double-buffering:
//   prefetch k16+1 fragments while issuing k16's 18 HMMAs.
// ---------------------------------------------------------------------------
__device__ __forceinline__ void mma_stage8(
    float (&acc)[3][2][4], uint32_t aH, uint32_t aL, uint32_t bH, uint32_t bL,
    int mrow0, int ncol0, int l)
{
    const uint32_t aRowOff = (uint32_t)((l & 15) * 144) + (uint32_t)((l >> 4) * 16);
    const uint32_t bRowOff = (uint32_t)((ncol0 + ((l >> 4) & 1) * 8 + (l & 7)) * 144)
                           + (uint32_t)(((l >> 3) & 1) * 16);

    uint32_t ah[2][3][4], al[2][3][4], bh[2][4], bl[2][4];
    ld_frags(ah[0], al[0], bh[0], bl[0], aH, aL, bH, bL, aRowOff, bRowOff, mrow0, 0);

#pragma unroll
    for (int k16 = 0; k16 < 4; k16++) {
        const int cur = k16 & 1;
        if (k16 < 3)
            ld_frags(ah[cur ^ 1], al[cur ^ 1], bh[cur ^ 1], bl[cur ^ 1],
                     aH, aL, bH, bL, aRowOff, bRowOff, mrow0,
                     (uint32_t)((k16 + 1) * 32));
#pragma unroll
        for (int mt = 0; mt < 3; mt++)
#pragma unroll
            for (int nf = 0; nf < 2; nf++) {
                const int ri = nf * 2;
                mma_bf16(acc[mt][nf], ah[cur][mt], bh[cur][ri], bh[cur][ri + 1]);
                mma_bf16(acc[mt][nf], ah[cur][mt], bl[cur][ri], bl[cur][ri + 1]);
                mma_bf16(acc[mt][nf], al[cur][mt], bh[cur][ri], bh[cur][ri + 1]);
            }
    }
}

// ---------------------------------------------------------------------------
// Kernel 1: feature GEMM on tensor cores (unchanged: 2-buf, 2 CTAs/SM)
// ---------------------------------------------------------------------------
template <bool RANGE>
__global__ void __launch_bounds__(NTHREADS, 1) feat_mma()
{
    const __nv_bfloat16* __restrict__ Ah = RANGE ? g_RBh : g_DBh;
    const __nv_bfloat16* __restrict__ Al = RANGE ? g_RBl : g_DBl;
    const __nv_bfloat16* __restrict__ Bh = RANGE ? g_Wrth : g_Wdth;
    const __nv_bfloat16* __restrict__ Bl = RANGE ? g_Wrtl : g_Wdtl;
    const float* __restrict__ bias = RANGE ? g_br : g_bd;
    __nv_bfloat16* __restrict__ OH = RANGE ? g_RFh : g_DFh;
    __nv_bfloat16* __restrict__ OL = RANGE ? g_RFl : g_DFl;

    extern __shared__ char smem[];
    const uint32_t sb0 = smem_u32(smem);
    const int t = threadIdx.x;
    const int w = t >> 5, l = t & 31;
    const int m0 = blockIdx.x * BM;
    const int n0 = blockIdx.y * BN;
    const int mrow0 = (w >> 2) * 48;
    const int ncol0 = (w & 3) * 16;

    auto load_s = [&](int s) {
        const int buf = s & 1;
        const int koff = s * 64;
        const uint32_t aH = sb0 + (buf * 2 + 0) * AST;
        const uint32_t aL = sb0 + (buf * 2 + 1) * AST;
#pragma unroll
        for (int c = t; c < 768; c += NTHREADS) {
            int row = c >> 3, k8 = (c & 7) * 8;
            uint32_t so = (uint32_t)(row * 144 + k8 * 2);
            size_t go = (size_t)(m0 + row) * E_DIM + koff + k8;
            cp16(aH + so, Ah + go);
            cp16(aL + so, Al + go);
        }
        const uint32_t bH = sb0 + 4 * AST + (buf * 2 + 0) * BST;
        const uint32_t bL = sb0 + 4 * AST + (buf * 2 + 1) * BST;
#pragma unroll
        for (int c = t; c < 512; c += NTHREADS) {
            int row = c >> 3, k8 = (c & 7) * 8;
            uint32_t so = (uint32_t)(row * 144 + k8 * 2);
            size_t go = (size_t)(n0 + row) * F_DIM + koff + k8;
            cp16(bH + so, Bh + go);
            cp16(bL + so, Bl + go);
        }
    };

    float acc[3][2][4];
#pragma unroll
    for (int i = 0; i < 3; i++)
#pragma unroll
        for (int j = 0; j < 2; j++)
#pragma unroll
            for (int r = 0; r < 4; r++) acc[i][j][r] = 0.0f;

    load_s(0);
    CP_COMMIT();
#pragma unroll 1
    for (int s = 0; s < 8; ++s) {
        if (s < 7) { load_s(s + 1); CP_COMMIT(); CP_WAIT1(); }
        else       { CP_WAIT0(); }
        __syncthreads();
        const int buf = s & 1;
        mma_stage8(acc, sb0 + (buf * 2 + 0) * AST, sb0 + (buf * 2 + 1) * AST,
                   sb0 + 4 * AST + (buf * 2 + 0) * BST, sb0 + 4 * AST + (buf * 2 + 1) * BST,
                   mrow0, ncol0, l);
        __syncthreads();
    }

    // epilogue: + bias, split, store
#pragma unroll
    for (int mt = 0; mt < 3; mt++)
#pragma unroll
        for (int nf = 0; nf < 2; nf++)
#pragma unroll
            for (int half = 0; half < 2; half++) {
                int row = mrow0 + mt * 16 + (l >> 2) + 8 * half;
                int col = ncol0 + nf * 8 + 2 * (l & 3);
                float v0 = acc[mt][nf][half * 2 + 0] + bias[n0 + col];
                float v1 = acc[mt][nf][half * 2 + 1] + bias[n0 + col + 1];
                __nv_bfloat16 h0 = __float2bfloat16(v0);
                __nv_bfloat16 h1 = __float2bfloat16(v1);
                __nv_bfloat16 l0 = __float2bfloat16(v0 - __bfloat162float(h0));
                __nv_bfloat16 l1 = __float2bfloat16(v1 - __bfloat162float(h1));
                size_t off = (size_t)(m0 + row) * F_DIM + n0 + col;
                __nv_bfloat16 hp[2] = {h0, h1}, lp[2] = {l0, l1};
                *(uint32_t*)(OH + off) = *(uint32_t*)hp;
                *(uint32_t*)(OL + off) = *(uint32_t*)lp;
            }
}

// ---------------------------------------------------------------------------
// Kernel 2: fused attention — 3-buffer pipeline, one barrier per stage
// ---------------------------------------------------------------------------
__device__ __forceinline__ int stage_koff(int s) {
    return (s < 4) ? (256 + s * 64) : ((s - 4) * 64);
}

__device__ __forceinline__ void load_stage(uint32_t sb0, int gs, int m0, int t) {
    const int s = gs & 7;
    const int nt = gs >> 3;
    const int koff = stage_koff(s);
    const int n0 = nt * BN;
    const int buf = gs % 3;
    const uint32_t aH = sb0 + SM_A + (buf * 2 + 0) * AST;
    const uint32_t aL = sb0 + SM_A + (buf * 2 + 1) * AST;
#pragma unroll
    for (int c = t; c < 768; c += NTHREADS) {
        int row = c >> 3, k8 = (c & 7) * 8;
        uint32_t so = (uint32_t)(row * 144 + k8 * 2);
        size_t go = (size_t)(m0 + row) * F_DIM + koff + k8;
        cp16(aH + so, g_RFh + go);
        cp16(aL + so, g_RFl + go);
    }
    const uint32_t bH = sb0 + SM_B + (buf * 2 + 0) * BST;
    const uint32_t bL = sb0 + SM_B + (buf * 2 + 1) * BST;
#pragma unroll
    for (int c = t; c < 512; c += NTHREADS) {
        int row = c >> 3, k8 = (c & 7) * 8;
        uint32_t so = (uint32_t)(row * 144 + k8 * 2);
        size_t go = (size_t)(n0 + row) * F_DIM + koff + k8;
        cp16(bH + so, g_DFh + go);
        cp16(bL + so, g_DFl + go);
    }
}

__device__ __forceinline__ void load_df(uint32_t sb0, int nt, int t) {
    const int n0 = nt * BN;
#pragma unroll
    for (int c = t; c < 512; c += NTHREADS) {
        int row = c >> 3, k8 = (c & 7) * 8;
        uint32_t so = (uint32_t)(row * 144 + k8 * 2);
        size_t go = (size_t)row * ND + n0 + k8;
        cp16(sb0 + SM_DFH + so, g_PDth + go);
        cp16(sb0 + SM_DFL + so, g_PDtl + go);
    }
}

__global__ void __launch_bounds__(NTHREADS, 1) attention_kernel(float* __restrict__ out)
{
    extern __shared__ char smem[];
    const uint32_t sb0 = smem_u32(smem);

    const int t = threadIdx.x;
    const int w = t >> 5, l = t & 31;
    const int m0 = blockIdx.x * BM;
    const int mrow0 = (w >> 2) * 48;
    const int ncol0 = (w & 3) * 16;

    __nv_bfloat16* sWCh = (__nv_bfloat16*)(smem + SM_WCH);
    __nv_bfloat16* sWCl = (__nv_bfloat16*)(smem + SM_WCL);
    float* sRW = (float*)(smem + SM_RW);
    float* sRO = (float*)(smem + SM_RO);

    float ep[3][2][4];
#pragma unroll
    for (int i = 0; i < 3; i++)
#pragma unroll
        for (int j = 0; j < 2; j++)
#pragma unroll
            for (int r = 0; r < 4; r++) ep[i][j][r] = 0.0f;
    float pw[3][2]  = {{0.f,0.f},{0.f,0.f},{0.f,0.f}};
    float pwo[3][2] = {{0.f,0.f},{0.f,0.f},{0.f,0.f}};

    // prologue: two stages in flight
    load_stage(sb0, 0, m0, t);
    CP_COMMIT();
    load_stage(sb0, 1, m0, t);
    CP_COMMIT();

#pragma unroll 1
    for (int nt = 0; nt < NTILES; ++nt) {
        float acc[3][2][4];
        float con[3][2][4], off[3][2][4];

#pragma unroll 1
        for (int s = 0; s < NSTG; ++s) {
            const int gs = nt * NSTG + s;
            // wait for stage gs data (allow 1 newer group in flight), then barrier
            CP_WAIT1();
            __syncthreads();
            // issue loads for stage gs+2; buffer (gs+2)%3 == (gs-1)%3 had its
            // readers ordered before this barrier. Commit unconditionally to
            // keep group counting uniform.
            {
                const int ns = gs + 2;
                if (ns < NTILES * NSTG) load_stage(sb0, ns, m0, t);
                if (s == 5) load_df(sb0, nt, t);
                CP_COMMIT();
            }

            if (s == 0 || s == 2 || s == 4) {
#pragma unroll
                for (int i = 0; i < 3; i++)
#pragma unroll
                    for (int j = 0; j < 2; j++)
#pragma unroll
                        for (int r = 0; r < 4; r++) acc[i][j][r] = 0.0f;
            }
            const int buf = gs % 3;
            mma_stage8(acc,
                       sb0 + SM_A + (buf * 2 + 0) * AST, sb0 + SM_A + (buf * 2 + 1) * AST,
                       sb0 + SM_B + (buf * 2 + 0) * BST, sb0 + SM_B + (buf * 2 + 1) * BST,
                       mrow0, ncol0, l);

            if (s == 1) {          // con ready (k 256..383)
#pragma unroll
                for (int i = 0; i < 3; i++)
#pragma unroll
                    for (int j = 0; j < 2; j++)
#pragma unroll
                        for (int r = 0; r < 4; r++)
                            con[i][j][r] = fast_tanh(acc[i][j][r] * INV_SQRT_H) * MAX_CONTRAST;
            } else if (s == 3) {   // off ready (k 384..511)
#pragma unroll
                for (int i = 0; i < 3; i++)
#pragma unroll
                    for (int j = 0; j < 2; j++)
#pragma unroll
                        for (int r = 0; r < 4; r++)
                            off[i][j][r] = fast_tanh(acc[i][j][r] * INV_SQRT_H);
            }
        }

        // ---- combine: w = exp(l-30); row sums; wc -> bf16 hi/lo smem ----
#pragma unroll
        for (int mt = 0; mt < 3; mt++)
#pragma unroll
            for (int nf = 0; nf < 2; nf++)
#pragma unroll
                for (int r = 0; r < 4; r++) {
                    int row = mrow0 + mt * 16 + (l >> 2) + 8 * (r >> 1);
                    int col = ncol0 + nf * 8 + 2 * (l & 3) + (r & 1);
                    float wgt = __expf(acc[mt][nf][r] - EXP_SHIFT);
                    pw[mt][r >> 1]  += wgt;
                    pwo[mt][r >> 1] += wgt * off[mt][nf][r];
                    float wc = wgt * con[mt][nf][r];
                    __nv_bfloat16 h = __float2bfloat16(wc);
                    sWCh[row * 72 + col] = h;
                    sWCl[row * 72 + col] = __float2bfloat16(wc - __bfloat162float(h));
                }
        __syncthreads();

        // ---- epilogue mma: ep += wc @ pooled^T (k = 64 tile cols) ----
        mma_stage8(ep, sb0 + SM_WCH, sb0 + SM_WCL, sb0 + SM_DFH, sb0 + SM_DFL,
                   mrow0, ncol0, l);
        // next tile's stage barriers order these reads before sWC/sDF rewrite
    }

    // ---- row-sum reduce: lanes (xor 1,2) then across the 4 n-warps ----
#pragma unroll
    for (int mt = 0; mt < 3; mt++)
#pragma unroll
        for (int h = 0; h < 2; h++) {
            pw[mt][h]  += __shfl_xor_sync(0xffffffffu, pw[mt][h], 1);
            pw[mt][h]  += __shfl_xor_sync(0xffffffffu, pw[mt][h], 2);
            pwo[mt][h] += __shfl_xor_sync(0xffffffffu, pwo[mt][h], 1);
            pwo[mt][h] += __shfl_xor_sync(0xffffffffu, pwo[mt][h], 2);
        }
    if ((l & 3) == 0) {
        const int wq = w & 3;
#pragma unroll
        for (int mt = 0; mt < 3; mt++)
#pragma unroll
            for (int h = 0; h < 2; h++) {
                int row = mrow0 + mt * 16 + (l >> 2) + 8 * h;
                sRW[wq * 96 + row] = pw[mt][h];
                sRO[wq * 96 + row] = pwo[mt][h];
            }
    }
    __syncthreads();

    // ---- final: out = (ep + sum(w*off)) / sum(w) ----
#pragma unroll
    for (int mt = 0; mt < 3; mt++)
#pragma unroll
        for (int nf = 0; nf < 2; nf++)
#pragma unroll
            for (int half = 0; half < 2; half++) {
                int row = mrow0 + mt * 16 + (l >> 2) + 8 * half;
                int col = ncol0 + nf * 8 + 2 * (l & 3);
                float sw  = sRW[row] + sRW[96 + row] + sRW[192 + row] + sRW[288 + row];
                float swo = sRO[row] + sRO[96 + row] + sRO[192 + row] + sRO[288 + row];
                float inv = 1.0f / sw;
                float2 v;
                v.x = (ep[mt][nf][half * 2 + 0] + swo) * inv;
                v.y = (ep[mt][nf][half * 2 + 1] + swo) * inv;
                *(float2*)(out + (size_t)(m0 + row) * DF_W + col) = v;
            }
}

// ---------------------------------------------------------------------------
// kernel_launch — kernel launches only (graph-capture clean)
// ---------------------------------------------------------------------------
extern "C" void kernel_launch(void* const* d_in, const int* in_sizes, int n_in,
                              void* d_out, int out_size)
{
    const float* pooled = (const float*)d_in[0];
    const float* rl     = (const float*)d_in[1];
    const float* dl     = (const float*)d_in[2];
    const float* rp     = (const float*)d_in[3];
    const float* dp     = (const float*)d_in[4];
    const float* Wrp    = (const float*)d_in[5];
    const float* brp    = (const float*)d_in[6];
    const float* Wdp    = (const float*)d_in[7];
    const float* bdp    = (const float*)d_in[8];
    const float* Wrc    = (const float*)d_in[9];
    const float* brc    = (const float*)d_in[10];
    const float* Wdc    = (const float*)d_in[11];
    const float* bdc    = (const float*)d_in[12];
    const float* Wro    = (const float*)d_in[13];
    const float* bro    = (const float*)d_in[14];
    const float* Wdo    = (const float*)d_in[15];
    const float* bdo    = (const float*)d_in[16];
    float* out = (float*)d_out;

    prep_weights<<<512, 512>>>(Wrp, brp, Wdp, bdp, Wrc, brc, Wdc, bdc,
                               Wro, bro, Wdo, bdo);
    prep_pd<<<ND, DF_W>>>(pooled);
    prep_base<true><<<(NR * E_DIM / 4) / 256, 256>>>(rl, rp);
    prep_base<false><<<(ND * E_DIM / 4) / 256, 256>>>(dl, dp);

    cudaFuncSetAttribute(feat_mma<false>,
                         cudaFuncAttributeMaxDynamicSharedMemorySize, SM2_TOTAL);
    cudaFuncSetAttribute(feat_mma<true>,
                         cudaFuncAttributeMaxDynamicSharedMemorySize, SM2_TOTAL);
    dim3 gridD(ND / BM, F_DIM / BN);   // 18 x 8
    feat_mma<false><<<gridD, NTHREADS, SM2_TOTAL>>>();
    dim3 gridR(NR / BM, F_DIM / BN);   // 144 x 8
    feat_mma<true><<<gridR, NTHREADS, SM2_TOTAL>>>();

    cudaFuncSetAttribute(attention_kernel,
                         cudaFuncAttributeMaxDynamicSharedMemorySize, SM_TOTAL);
    attention_kernel<<<NR / BM, NTHREADS, SM_TOTAL>>>(out);
}

// round 10
// speedup vs baseline: 5.9439x; 1.1650x over previous
#include <cuda_runtime.h>
#include <cuda_bf16.h>
#include <cstdint>
#include <math.h>

// ---------------------------------------------------------------------------
// FractalAttention3D — mma.sync bf16 (2-way split), 8-warp tiling,
//   3-buffer cp.async pipeline, XOR-swizzled 128B smem rows (conflict-free
//   ldmatrix). Family-portable PTX only (sm_80+).
// ---------------------------------------------------------------------------

#define NR 13824
#define ND 1728
#define E_DIM 512
#define F_DIM 512
#define DF_W 64
#define LOGIT_SCALE 0.25f
#define INV_SQRT_H 0.08838834764831843f
#define MAX_CONTRAST 1.8f
#define EXP_SHIFT 30.0f

#define BM 96                 // 13824/96 = 144 CTAs ~ one wave
#define BN 64
#define NTILES (ND / BN)      // 27
#define NSTG 8                // stages per tile (2 con + 2 off + 4 repr)
#define NTHREADS 256          // 8 warps: 2m x 4n grid of 48x16 warp tiles

// -------- device scratch (static; no cudaMalloc allowed) --------
__device__ __align__(16) float g_br[F_DIM];
__device__ __align__(16) float g_bd[F_DIM];
__device__ __align__(16) __nv_bfloat16 g_Wrth[(size_t)F_DIM * F_DIM];
__device__ __align__(16) __nv_bfloat16 g_Wrtl[(size_t)F_DIM * F_DIM];
__device__ __align__(16) __nv_bfloat16 g_Wdth[(size_t)F_DIM * F_DIM];
__device__ __align__(16) __nv_bfloat16 g_Wdtl[(size_t)F_DIM * F_DIM];
__device__ __align__(16) __nv_bfloat16 g_RBh[(size_t)NR * E_DIM];
__device__ __align__(16) __nv_bfloat16 g_RBl[(size_t)NR * E_DIM];
__device__ __align__(16) __nv_bfloat16 g_DBh[(size_t)ND * E_DIM];
__device__ __align__(16) __nv_bfloat16 g_DBl[(size_t)ND * E_DIM];
__device__ __align__(16) __nv_bfloat16 g_RFh[(size_t)NR * F_DIM];
__device__ __align__(16) __nv_bfloat16 g_RFl[(size_t)NR * F_DIM];
__device__ __align__(16) __nv_bfloat16 g_DFh[(size_t)ND * F_DIM];
__device__ __align__(16) __nv_bfloat16 g_DFl[(size_t)ND * F_DIM];
__device__ __align__(16) __nv_bfloat16 g_PDth[(size_t)DF_W * ND];  // pooled^T hi [64][1728]
__device__ __align__(16) __nv_bfloat16 g_PDtl[(size_t)DF_W * ND];

// ---------------- smem layout: 128B rows, XOR-swizzled chunks ----------------
#define AST 12288            // 96*128
#define BST 8192             // 64*128
#define SM_A   0             // 6*AST = 73728 (3 bufs x hi/lo)
#define SM_B   73728         // 6*BST = 49152
#define SM_WCH 122880        // 12288
#define SM_WCL 135168        // 12288
#define SM_DFH 147456        // 8192
#define SM_DFL 155648        // 8192
#define SM_RW  163840        // 4*96*4 = 1536
#define SM_RO  165376        // 1536
#define SM_TOTAL 166912

// feat_mma smem: 2 bufs -> 4*AST + 4*BST
#define SM2_TOTAL 81920

// swizzled byte offset of (row, 16B-chunk c) within a tile
__device__ __forceinline__ uint32_t sw_off(int row, int c) {
    return (uint32_t)(row * 128 + ((c ^ (row & 7)) * 16));
}

// ---------------- PTX helpers (sm_80-portable) ----------------
__device__ __forceinline__ uint32_t smem_u32(const void* p) {
    uint32_t a;
    asm("{ .reg .u64 t; cvta.to.shared.u64 t, %1; cvt.u32.u64 %0, t; }" : "=r"(a) : "l"(p));
    return a;
}
__device__ __forceinline__ void cp16(uint32_t dst, const void* src) {
    asm volatile("cp.async.cg.shared.global [%0], [%1], 16;" :: "r"(dst), "l"(src));
}
#define CP_COMMIT() asm volatile("cp.async.commit_group;" ::: "memory")
#define CP_WAIT1()  asm volatile("cp.async.wait_group 1;" ::: "memory")
#define CP_WAIT0()  asm volatile("cp.async.wait_group 0;" ::: "memory")

__device__ __forceinline__ void ldsm4(uint32_t& r0, uint32_t& r1, uint32_t& r2, uint32_t& r3,
                                      uint32_t addr) {
    asm volatile("ldmatrix.sync.aligned.m8n8.x4.shared.b16 {%0,%1,%2,%3}, [%4];"
                 : "=r"(r0), "=r"(r1), "=r"(r2), "=r"(r3) : "r"(addr));
}
__device__ __forceinline__ void mma_bf16(float* c, const uint32_t* a, uint32_t b0, uint32_t b1) {
    asm("mma.sync.aligned.m16n8k16.row.col.f32.bf16.bf16.f32 "
        "{%0,%1,%2,%3}, {%4,%5,%6,%7}, {%8,%9}, {%0,%1,%2,%3};"
        : "+f"(c[0]), "+f"(c[1]), "+f"(c[2]), "+f"(c[3])
        : "r"(a[0]), "r"(a[1]), "r"(a[2]), "r"(a[3]), "r"(b0), "r"(b1));
}
__device__ __forceinline__ float fast_tanh(float x) {
    float e = __expf(-2.0f * x);
    return __fdividef(2.0f, e + 1.0f) - 1.0f;
}

// ---------------------------------------------------------------------------
// prep kernels (unchanged)
// ---------------------------------------------------------------------------
__global__ void prep_weights(
    const float* __restrict__ Wrp, const float* __restrict__ brp,
    const float* __restrict__ Wdp, const float* __restrict__ bdp,
    const float* __restrict__ Wrc, const float* __restrict__ brc,
    const float* __restrict__ Wdc, const float* __restrict__ bdc,
    const float* __restrict__ Wro, const float* __restrict__ bro,
    const float* __restrict__ Wdo, const float* __restrict__ bdo)
{
    int e = blockIdx.x, j = threadIdx.x;   // e = k index, j = n index
    float wr, wd;
    if (j < 256)      { wr = Wrp[e * 256 + j] * LOGIT_SCALE; wd = Wdp[e * 256 + j]; }
    else if (j < 384) { wr = Wrc[e * 128 + (j - 256)];       wd = Wdc[e * 128 + (j - 256)]; }
    else              { wr = Wro[e * 128 + (j - 384)];       wd = Wdo[e * 128 + (j - 384)]; }
    size_t toff = (size_t)j * F_DIM + e;   // transposed [n][k]
    __nv_bfloat16 h = __float2bfloat16(wr);
    g_Wrth[toff] = h;
    g_Wrtl[toff] = __float2bfloat16(wr - __bfloat162float(h));
    h = __float2bfloat16(wd);
    g_Wdth[toff] = h;
    g_Wdtl[toff] = __float2bfloat16(wd - __bfloat162float(h));
    if (e == 0) {
        float br, bd;
        if (j < 256)      { br = brp[j] * LOGIT_SCALE; bd = bdp[j]; }
        else if (j < 384) { br = brc[j - 256];         bd = bdc[j - 256]; }
        else              { br = bro[j - 384];         bd = bdo[j - 384]; }
        g_br[j] = br;
        g_bd[j] = bd;
    }
}

__global__ void prep_pd(const float* __restrict__ pooled) {
    int n = blockIdx.x, d = threadIdx.x;
    float v = pooled[(size_t)n * DF_W + d];
    __nv_bfloat16 h = __float2bfloat16(v);
    g_PDth[(size_t)d * ND + n] = h;
    g_PDtl[(size_t)d * ND + n] = __float2bfloat16(v - __bfloat162float(h));
}

template <bool RANGE>
__global__ void prep_base(const float* __restrict__ lat, const float* __restrict__ pos)
{
    __nv_bfloat16* __restrict__ OH = RANGE ? g_RBh : g_DBh;
    __nv_bfloat16* __restrict__ OL = RANGE ? g_RBl : g_DBl;
    size_t i = ((size_t)blockIdx.x * blockDim.x + threadIdx.x) * 4;
    float4 a = *(const float4*)(lat + i);
    float4 b = *(const float4*)(pos + i);
    float v[4] = {a.x + b.x, a.y + b.y, a.z + b.z, a.w + b.w};
    __nv_bfloat16 hb[4], lb[4];
#pragma unroll
    for (int j = 0; j < 4; j++) {
        hb[j] = __float2bfloat16(v[j]);
        lb[j] = __float2bfloat16(v[j] - __bfloat162float(hb[j]));
    }
    *(uint2*)(OH + i) = *(uint2*)hb;
    *(uint2*)(OL + i) = *(uint2*)lb;
}

// ---------------------------------------------------------------------------
// Fragment loads for one k16 slice (8 ldsm4 per warp), swizzled layout.
//   kc = 2*k16 (16B-chunk base of the k16 slice)
// ---------------------------------------------------------------------------
__device__ __forceinline__ void ld_frags(
    uint32_t (&ah)[3][4], uint32_t (&al)[3][4], uint32_t (&bh)[4], uint32_t (&bl)[4],
    uint32_t aH, uint32_t aL, uint32_t bH, uint32_t bL,
    int mrow0, int ncol0, int l, int kc)
{
    const int a7 = l & 7;
    const int ar = l & 15;
    const uint32_t aChunk = (uint32_t)((((l >> 4) + kc) ^ a7) * 16);
#pragma unroll
    for (int mt = 0; mt < 3; mt++) {
        uint32_t off = (uint32_t)((mrow0 + mt * 16 + ar) * 128) + aChunk;
        ldsm4(ah[mt][0], ah[mt][1], ah[mt][2], ah[mt][3], aH + off);
        ldsm4(al[mt][0], al[mt][1], al[mt][2], al[mt][3], aL + off);
    }
    {
        int brow = ncol0 + ((l >> 4) & 1) * 8 + (l & 7);
        uint32_t off = (uint32_t)(brow * 128)
                     + (uint32_t)(((((l >> 3) & 1) + kc) ^ a7) * 16);
        ldsm4(bh[0], bh[1], bh[2], bh[3], bH + off);
        ldsm4(bl[0], bl[1], bl[2], bl[3], bL + off);
    }
}

// ---------------------------------------------------------------------------
// 8-warp MMA stage with k16-level fragment double-buffering.
// ---------------------------------------------------------------------------
__device__ __forceinline__ void mma_stage8(
    float (&acc)[3][2][4], uint32_t aH, uint32_t aL, uint32_t bH, uint32_t bL,
    int mrow0, int ncol0, int l)
{
    uint32_t ah[2][3][4], al[2][3][4], bh[2][4], bl[2][4];
    ld_frags(ah[0], al[0], bh[0], bl[0], aH, aL, bH, bL, mrow0, ncol0, l, 0);

#pragma unroll
    for (int k16 = 0; k16 < 4; k16++) {
        const int cur = k16 & 1;
        if (k16 < 3)
            ld_frags(ah[cur ^ 1], al[cur ^ 1], bh[cur ^ 1], bl[cur ^ 1],
                     aH, aL, bH, bL, mrow0, ncol0, l, (k16 + 1) * 2);
#pragma unroll
        for (int mt = 0; mt < 3; mt++)
#pragma unroll
            for (int nf = 0; nf < 2; nf++) {
                const int ri = nf * 2;
                mma_bf16(acc[mt][nf], ah[cur][mt], bh[cur][ri], bh[cur][ri + 1]);
                mma_bf16(acc[mt][nf], ah[cur][mt], bl[cur][ri], bl[cur][ri + 1]);
                mma_bf16(acc[mt][nf], al[cur][mt], bh[cur][ri], bh[cur][ri + 1]);
            }
    }
}

// ---------------------------------------------------------------------------
// Kernel 1: feature GEMM on tensor cores (2-buf, 2 CTAs/SM, swizzled)
// ---------------------------------------------------------------------------
template <bool RANGE>
__global__ void __launch_bounds__(NTHREADS, 1) feat_mma()
{
    const __nv_bfloat16* __restrict__ Ah = RANGE ? g_RBh : g_DBh;
    const __nv_bfloat16* __restrict__ Al = RANGE ? g_RBl : g_DBl;
    const __nv_bfloat16* __restrict__ Bh = RANGE ? g_Wrth : g_Wdth;
    const __nv_bfloat16* __restrict__ Bl = RANGE ? g_Wrtl : g_Wdtl;
    const float* __restrict__ bias = RANGE ? g_br : g_bd;
    __nv_bfloat16* __restrict__ OH = RANGE ? g_RFh : g_DFh;
    __nv_bfloat16* __restrict__ OL = RANGE ? g_RFl : g_DFl;

    extern __shared__ char smem[];
    const uint32_t sb0 = smem_u32(smem);
    const int t = threadIdx.x;
    const int w = t >> 5, l = t & 31;
    const int m0 = blockIdx.x * BM;
    const int n0 = blockIdx.y * BN;
    const int mrow0 = (w >> 2) * 48;
    const int ncol0 = (w & 3) * 16;

    auto load_s = [&](int s) {
        const int buf = s & 1;
        const int koff = s * 64;
        const uint32_t aH = sb0 + (buf * 2 + 0) * AST;
        const uint32_t aL = sb0 + (buf * 2 + 1) * AST;
#pragma unroll
        for (int c = t; c < 768; c += NTHREADS) {
            int row = c >> 3, ch = c & 7;
            uint32_t so = sw_off(row, ch);
            size_t go = (size_t)(m0 + row) * E_DIM + koff + ch * 8;
            cp16(aH + so, Ah + go);
            cp16(aL + so, Al + go);
        }
        const uint32_t bH = sb0 + 4 * AST + (buf * 2 + 0) * BST;
        const uint32_t bL = sb0 + 4 * AST + (buf * 2 + 1) * BST;
#pragma unroll
        for (int c = t; c < 512; c += NTHREADS) {
            int row = c >> 3, ch = c & 7;
            uint32_t so = sw_off(row, ch);
            size_t go = (size_t)(n0 + row) * F_DIM + koff + ch * 8;
            cp16(bH + so, Bh + go);
            cp16(bL + so, Bl + go);
        }
    };

    float acc[3][2][4];
#pragma unroll
    for (int i = 0; i < 3; i++)
#pragma unroll
        for (int j = 0; j < 2; j++)
#pragma unroll
            for (int r = 0; r < 4; r++) acc[i][j][r] = 0.0f;

    load_s(0);
    CP_COMMIT();
#pragma unroll 1
    for (int s = 0; s < 8; ++s) {
        if (s < 7) { load_s(s + 1); CP_COMMIT(); CP_WAIT1(); }
        else       { CP_WAIT0(); }
        __syncthreads();
        const int buf = s & 1;
        mma_stage8(acc, sb0 + (buf * 2 + 0) * AST, sb0 + (buf * 2 + 1) * AST,
                   sb0 + 4 * AST + (buf * 2 + 0) * BST, sb0 + 4 * AST + (buf * 2 + 1) * BST,
                   mrow0, ncol0, l);
        __syncthreads();
    }

    // epilogue: + bias, split, store
#pragma unroll
    for (int mt = 0; mt < 3; mt++)
#pragma unroll
        for (int nf = 0; nf < 2; nf++)
#pragma unroll
            for (int half = 0; half < 2; half++) {
                int row = mrow0 + mt * 16 + (l >> 2) + 8 * half;
                int col = ncol0 + nf * 8 + 2 * (l & 3);
                float v0 = acc[mt][nf][half * 2 + 0] + bias[n0 + col];
                float v1 = acc[mt][nf][half * 2 + 1] + bias[n0 + col + 1];
                __nv_bfloat16 h0 = __float2bfloat16(v0);
                __nv_bfloat16 h1 = __float2bfloat16(v1);
                __nv_bfloat16 l0 = __float2bfloat16(v0 - __bfloat162float(h0));
                __nv_bfloat16 l1 = __float2bfloat16(v1 - __bfloat162float(h1));
                size_t off = (size_t)(m0 + row) * F_DIM + n0 + col;
                __nv_bfloat16 hp[2] = {h0, h1}, lp[2] = {l0, l1};
                *(uint32_t*)(OH + off) = *(uint32_t*)hp;
                *(uint32_t*)(OL + off) = *(uint32_t*)lp;
            }
}

// ---------------------------------------------------------------------------
// Kernel 2: fused attention — 3-buffer pipeline, swizzled layout
// ---------------------------------------------------------------------------
__device__ __forceinline__ int stage_koff(int s) {
    return (s < 4) ? (256 + s * 64) : ((s - 4) * 64);
}

__device__ __forceinline__ void load_stage(uint32_t sb0, int gs, int m0, int t) {
    const int s = gs & 7;
    const int nt = gs >> 3;
    const int koff = stage_koff(s);
    const int n0 = nt * BN;
    const int buf = gs % 3;
    const uint32_t aH = sb0 + SM_A + (buf * 2 + 0) * AST;
    const uint32_t aL = sb0 + SM_A + (buf * 2 + 1) * AST;
#pragma unroll
    for (int c = t; c < 768; c += NTHREADS) {
        int row = c >> 3, ch = c & 7;
        uint32_t so = sw_off(row, ch);
        size_t go = (size_t)(m0 + row) * F_DIM + koff + ch * 8;
        cp16(aH + so, g_RFh + go);
        cp16(aL + so, g_RFl + go);
    }
    const uint32_t bH = sb0 + SM_B + (buf * 2 + 0) * BST;
    const uint32_t bL = sb0 + SM_B + (buf * 2 + 1) * BST;
#pragma unroll
    for (int c = t; c < 512; c += NTHREADS) {
        int row = c >> 3, ch = c & 7;
        uint32_t so = sw_off(row, ch);
        size_t go = (size_t)(n0 + row) * F_DIM + koff + ch * 8;
        cp16(bH + so, g_DFh + go);
        cp16(bL + so, g_DFl + go);
    }
}

__device__ __forceinline__ void load_df(uint32_t sb0, int nt, int t) {
    const int n0 = nt * BN;
#pragma unroll
    for (int c = t; c < 512; c += NTHREADS) {
        int row = c >> 3, ch = c & 7;
        uint32_t so = sw_off(row, ch);
        size_t go = (size_t)row * ND + n0 + ch * 8;
        cp16(sb0 + SM_DFH + so, g_PDth + go);
        cp16(sb0 + SM_DFL + so, g_PDtl + go);
    }
}

__global__ void __launch_bounds__(NTHREADS, 1) attention_kernel(float* __restrict__ out)
{
    extern __shared__ char smem[];
    const uint32_t sb0 = smem_u32(smem);

    const int t = threadIdx.x;
    const int w = t >> 5, l = t & 31;
    const int m0 = blockIdx.x * BM;
    const int mrow0 = (w >> 2) * 48;
    const int ncol0 = (w & 3) * 16;

    float* sRW = (float*)(smem + SM_RW);
    float* sRO = (float*)(smem + SM_RO);

    float ep[3][2][4];
#pragma unroll
    for (int i = 0; i < 3; i++)
#pragma unroll
        for (int j = 0; j < 2; j++)
#pragma unroll
            for (int r = 0; r < 4; r++) ep[i][j][r] = 0.0f;
    float pw[3][2]  = {{0.f,0.f},{0.f,0.f},{0.f,0.f}};
    float pwo[3][2] = {{0.f,0.f},{0.f,0.f},{0.f,0.f}};

    // prologue: two stages in flight
    load_stage(sb0, 0, m0, t);
    CP_COMMIT();
    load_stage(sb0, 1, m0, t);
    CP_COMMIT();

#pragma unroll 1
    for (int nt = 0; nt < NTILES; ++nt) {
        float acc[3][2][4];
        float con[3][2][4], off[3][2][4];

#pragma unroll 1
        for (int s = 0; s < NSTG; ++s) {
            const int gs = nt * NSTG + s;
            CP_WAIT1();
            __syncthreads();
            // issue loads for stage gs+2; its buffer (gs+2)%3 == (gs-1)%3 had
            // readers ordered before this barrier. Commit unconditionally.
            {
                const int ns = gs + 2;
                if (ns < NTILES * NSTG) load_stage(sb0, ns, m0, t);
                if (s == 5) load_df(sb0, nt, t);
                CP_COMMIT();
            }

            if (s == 0 || s == 2 || s == 4) {
#pragma unroll
                for (int i = 0; i < 3; i++)
#pragma unroll
                    for (int j = 0; j < 2; j++)
#pragma unroll
                        for (int r = 0; r < 4; r++) acc[i][j][r] = 0.0f;
            }
            const int buf = gs % 3;
            mma_stage8(acc,
                       sb0 + SM_A + (buf * 2 + 0) * AST, sb0 + SM_A + (buf * 2 + 1) * AST,
                       sb0 + SM_B + (buf * 2 + 0) * BST, sb0 + SM_B + (buf * 2 + 1) * BST,
                       mrow0, ncol0, l);

            if (s == 1) {          // con ready (k 256..383)
#pragma unroll
                for (int i = 0; i < 3; i++)
#pragma unroll
                    for (int j = 0; j < 2; j++)
#pragma unroll
                        for (int r = 0; r < 4; r++)
                            con[i][j][r] = fast_tanh(acc[i][j][r] * INV_SQRT_H) * MAX_CONTRAST;
            } else if (s == 3) {   // off ready (k 384..511)
#pragma unroll
                for (int i = 0; i < 3; i++)
#pragma unroll
                    for (int j = 0; j < 2; j++)
#pragma unroll
                        for (int r = 0; r < 4; r++)
                            off[i][j][r] = fast_tanh(acc[i][j][r] * INV_SQRT_H);
            }
        }

        // ---- combine: w = exp(l-30); row sums; wc -> bf16 hi/lo smem ----
#pragma unroll
        for (int mt = 0; mt < 3; mt++)
#pragma unroll
            for (int nf = 0; nf < 2; nf++)
#pragma unroll
                for (int r = 0; r < 4; r++) {
                    int row = mrow0 + mt * 16 + (l >> 2) + 8 * (r >> 1);
                    int col = ncol0 + nf * 8 + 2 * (l & 3) + (r & 1);
                    float wgt = __expf(acc[mt][nf][r] - EXP_SHIFT);
                    pw[mt][r >> 1]  += wgt;
                    pwo[mt][r >> 1] += wgt * off[mt][nf][r];
                    float wc = wgt * con[mt][nf][r];
                    __nv_bfloat16 h = __float2bfloat16(wc);
                    uint32_t so = sw_off(row, col >> 3) + (uint32_t)((col & 7) * 2);
                    *(__nv_bfloat16*)(smem + SM_WCH + so) = h;
                    *(__nv_bfloat16*)(smem + SM_WCL + so) =
                        __float2bfloat16(wc - __bfloat162float(h));
                }
        __syncthreads();

        // ---- epilogue mma: ep += wc @ pooled^T (k = 64 tile cols) ----
        mma_stage8(ep, sb0 + SM_WCH, sb0 + SM_WCL, sb0 + SM_DFH, sb0 + SM_DFL,
                   mrow0, ncol0, l);
        // next tile's stage barriers order these reads before sWC/sDF rewrite
    }

    // ---- row-sum reduce: lanes (xor 1,2) then across the 4 n-warps ----
#pragma unroll
    for (int mt = 0; mt < 3; mt++)
#pragma unroll
        for (int h = 0; h < 2; h++) {
            pw[mt][h]  += __shfl_xor_sync(0xffffffffu, pw[mt][h], 1);
            pw[mt][h]  += __shfl_xor_sync(0xffffffffu, pw[mt][h], 2);
            pwo[mt][h] += __shfl_xor_sync(0xffffffffu, pwo[mt][h], 1);
            pwo[mt][h] += __shfl_xor_sync(0xffffffffu, pwo[mt][h], 2);
        }
    if ((l & 3) == 0) {
        const int wq = w & 3;
#pragma unroll
        for (int mt = 0; mt < 3; mt++)
#pragma unroll
            for (int h = 0; h < 2; h++) {
                int row = mrow0 + mt * 16 + (l >> 2) + 8 * h;
                sRW[wq * 96 + row] = pw[mt][h];
                sRO[wq * 96 + row] = pwo[mt][h];
            }
    }
    __syncthreads();

    // ---- final: out = (ep + sum(w*off)) / sum(w) ----
#pragma unroll
    for (int mt = 0; mt < 3; mt++)
#pragma unroll
        for (int nf = 0; nf < 2; nf++)
#pragma unroll
            for (int half = 0; half < 2; half++) {
                int row = mrow0 + mt * 16 + (l >> 2) + 8 * half;
                int col = ncol0 + nf * 8 + 2 * (l & 3);
                float sw  = sRW[row] + sRW[96 + row] + sRW[192 + row] + sRW[288 + row];
                float swo = sRO[row] + sRO[96 + row] + sRO[192 + row] + sRO[288 + row];
                float inv = 1.0f / sw;
                float2 v;
                v.x = (ep[mt][nf][half * 2 + 0] + swo) * inv;
                v.y = (ep[mt][nf][half * 2 + 1] + swo) * inv;
                *(float2*)(out + (size_t)(m0 + row) * DF_W + col) = v;
            }
}

// ---------------------------------------------------------------------------
// kernel_launch — kernel launches only (graph-capture clean)
// ---------------------------------------------------------------------------
extern "C" void kernel_launch(void* const* d_in, const int* in_sizes, int n_in,
                              void* d_out, int out_size)
{
    const float* pooled = (const float*)d_in[0];
    const float* rl     = (const float*)d_in[1];
    const float* dl     = (const float*)d_in[2];
    const float* rp     = (const float*)d_in[3];
    const float* dp     = (const float*)d_in[4];
    const float* Wrp    = (const float*)d_in[5];
    const float* brp    = (const float*)d_in[6];
    const float* Wdp    = (const float*)d_in[7];
    const float* bdp    = (const float*)d_in[8];
    const float* Wrc    = (const float*)d_in[9];
    const float* brc    = (const float*)d_in[10];
    const float* Wdc    = (const float*)d_in[11];
    const float* bdc    = (const float*)d_in[12];
    const float* Wro    = (const float*)d_in[13];
    const float* bro    = (const float*)d_in[14];
    const float* Wdo    = (const float*)d_in[15];
    const float* bdo    = (const float*)d_in[16];
    float* out = (float*)d_out;

    prep_weights<<<512, 512>>>(Wrp, brp, Wdp, bdp, Wrc, brc, Wdc, bdc,
                               Wro, bro, Wdo, bdo);
    prep_pd<<<ND, DF_W>>>(pooled);
    prep_base<true><<<(NR * E_DIM / 4) / 256, 256>>>(rl, rp);
    prep_base<false><<<(ND * E_DIM / 4) / 256, 256>>>(dl, dp);

    cudaFuncSetAttribute(feat_mma<false>,
                         cudaFuncAttributeMaxDynamicSharedMemorySize, SM2_TOTAL);
    cudaFuncSetAttribute(feat_mma<true>,
                         cudaFuncAttributeMaxDynamicSharedMemorySize, SM2_TOTAL);
    dim3 gridD(ND / BM, F_DIM / BN);   // 18 x 8
    feat_mma<false><<<gridD, NTHREADS, SM2_TOTAL>>>();
    dim3 gridR(NR / BM, F_DIM / BN);   // 144 x 8
    feat_mma<true><<<gridR, NTHREADS, SM2_TOTAL>>>();

    cudaFuncSetAttribute(attention_kernel,
                         cudaFuncAttributeMaxDynamicSharedMemorySize, SM_TOTAL);
    attention_kernel<<<NR / BM, NTHREADS, SM_TOTAL>>>(out);
}

// round 12
// speedup vs baseline: 6.0530x; 1.0184x over previous
#include <cuda_runtime.h>
#include <cuda_bf16.h>
#include <cstdint>
#include <math.h>

// ---------------------------------------------------------------------------
// FractalAttention3D — mma.sync bf16 (2-way split), 8-warp tiling,
//   4-buffer cp.async pipeline (wait_group 2 -> stage gs complete, 2 in
//   flight), XOR-swizzled 128B smem rows. Family-portable PTX only (sm_80+).
// ---------------------------------------------------------------------------

#define NR 13824
#define ND 1728
#define E_DIM 512
#define F_DIM 512
#define DF_W 64
#define LOGIT_SCALE 0.25f
#define INV_SQRT_H 0.08838834764831843f
#define MAX_CONTRAST 1.8f
#define EXP_SHIFT 30.0f

#define BM 96                 // 13824/96 = 144 CTAs ~ one wave
#define BN 64
#define NTILES (ND / BN)      // 27
#define NSTG 8                // stages per tile (2 con + 2 off + 4 repr)
#define NTHREADS 256          // 8 warps: 2m x 4n grid of 48x16 warp tiles

// -------- device scratch (static; no cudaMalloc allowed) --------
__device__ __align__(16) float g_br[F_DIM];
__device__ __align__(16) float g_bd[F_DIM];
__device__ __align__(16) __nv_bfloat16 g_Wrth[(size_t)F_DIM * F_DIM];
__device__ __align__(16) __nv_bfloat16 g_Wrtl[(size_t)F_DIM * F_DIM];
__device__ __align__(16) __nv_bfloat16 g_Wdth[(size_t)F_DIM * F_DIM];
__device__ __align__(16) __nv_bfloat16 g_Wdtl[(size_t)F_DIM * F_DIM];
__device__ __align__(16) __nv_bfloat16 g_RBh[(size_t)NR * E_DIM];
__device__ __align__(16) __nv_bfloat16 g_RBl[(size_t)NR * E_DIM];
__device__ __align__(16) __nv_bfloat16 g_DBh[(size_t)ND * E_DIM];
__device__ __align__(16) __nv_bfloat16 g_DBl[(size_t)ND * E_DIM];
__device__ __align__(16) __nv_bfloat16 g_RFh[(size_t)NR * F_DIM];
__device__ __align__(16) __nv_bfloat16 g_RFl[(size_t)NR * F_DIM];
__device__ __align__(16) __nv_bfloat16 g_DFh[(size_t)ND * F_DIM];
__device__ __align__(16) __nv_bfloat16 g_DFl[(size_t)ND * F_DIM];
__device__ __align__(16) __nv_bfloat16 g_PDth[(size_t)DF_W * ND];  // pooled^T hi [64][1728]
__device__ __align__(16) __nv_bfloat16 g_PDtl[(size_t)DF_W * ND];

// ---------------- smem layout: 128B rows, XOR-swizzled chunks ----------------
#define AST 12288            // 96*128
#define BST 8192             // 64*128
#define SM_A   0             // 8*AST = 98304 (4 bufs x hi/lo)
#define SM_B   98304         // 8*BST = 65536
#define SM_WCH 163840        // 12288
#define SM_WCL 176128        // 12288
#define SM_DFH 188416        // 8192
#define SM_DFL 196608        // 8192
#define SM_RW  204800        // 4*96*4 = 1536
#define SM_RO  206336        // 1536
#define SM_TOTAL 207872

// feat_mma smem: 2 bufs -> 4*AST + 4*BST
#define SM2_TOTAL 81920

// swizzled byte offset of (row, 16B-chunk c) within a tile
__device__ __forceinline__ uint32_t sw_off(int row, int c) {
    return (uint32_t)(row * 128 + ((c ^ (row & 7)) * 16));
}

// ---------------- PTX helpers (sm_80-portable) ----------------
__device__ __forceinline__ uint32_t smem_u32(const void* p) {
    uint32_t a;
    asm("{ .reg .u64 t; cvta.to.shared.u64 t, %1; cvt.u32.u64 %0, t; }" : "=r"(a) : "l"(p));
    return a;
}
__device__ __forceinline__ void cp16(uint32_t dst, const void* src) {
    asm volatile("cp.async.cg.shared.global [%0], [%1], 16;" :: "r"(dst), "l"(src));
}
#define CP_COMMIT() asm volatile("cp.async.commit_group;" ::: "memory")
#define CP_WAIT0()  asm volatile("cp.async.wait_group 0;" ::: "memory")
#define CP_WAIT1()  asm volatile("cp.async.wait_group 1;" ::: "memory")
#define CP_WAIT2()  asm volatile("cp.async.wait_group 2;" ::: "memory")

__device__ __forceinline__ void ldsm4(uint32_t& r0, uint32_t& r1, uint32_t& r2, uint32_t& r3,
                                      uint32_t addr) {
    asm volatile("ldmatrix.sync.aligned.m8n8.x4.shared.b16 {%0,%1,%2,%3}, [%4];"
                 : "=r"(r0), "=r"(r1), "=r"(r2), "=r"(r3) : "r"(addr));
}
__device__ __forceinline__ void mma_bf16(float* c, const uint32_t* a, uint32_t b0, uint32_t b1) {
    asm("mma.sync.aligned.m16n8k16.row.col.f32.bf16.bf16.f32 "
        "{%0,%1,%2,%3}, {%4,%5,%6,%7}, {%8,%9}, {%0,%1,%2,%3};"
        : "+f"(c[0]), "+f"(c[1]), "+f"(c[2]), "+f"(c[3])
        : "r"(a[0]), "r"(a[1]), "r"(a[2]), "r"(a[3]), "r"(b0), "r"(b1));
}
__device__ __forceinline__ float fast_tanh(float x) {
    float e = __expf(-2.0f * x);
    return __fdividef(2.0f, e + 1.0f) - 1.0f;
}

// ---------------------------------------------------------------------------
// prep kernels (unchanged)
// ---------------------------------------------------------------------------
__global__ void prep_weights(
    const float* __restrict__ Wrp, const float* __restrict__ brp,
    const float* __restrict__ Wdp, const float* __restrict__ bdp,
    const float* __restrict__ Wrc, const float* __restrict__ brc,
    const float* __restrict__ Wdc, const float* __restrict__ bdc,
    const float* __restrict__ Wro, const float* __restrict__ bro,
    const float* __restrict__ Wdo, const float* __restrict__ bdo)
{
    int e = blockIdx.x, j = threadIdx.x;   // e = k index, j = n index
    float wr, wd;
    if (j < 256)      { wr = Wrp[e * 256 + j] * LOGIT_SCALE; wd = Wdp[e * 256 + j]; }
    else if (j < 384) { wr = Wrc[e * 128 + (j - 256)];       wd = Wdc[e * 128 + (j - 256)]; }
    else              { wr = Wro[e * 128 + (j - 384)];       wd = Wdo[e * 128 + (j - 384)]; }
    size_t toff = (size_t)j * F_DIM + e;   // transposed [n][k]
    __nv_bfloat16 h = __float2bfloat16(wr);
    g_Wrth[toff] = h;
    g_Wrtl[toff] = __float2bfloat16(wr - __bfloat162float(h));
    h = __float2bfloat16(wd);
    g_Wdth[toff] = h;
    g_Wdtl[toff] = __float2bfloat16(wd - __bfloat162float(h));
    if (e == 0) {
        float br, bd;
        if (j < 256)      { br = brp[j] * LOGIT_SCALE; bd = bdp[j]; }
        else if (j < 384) { br = brc[j - 256];         bd = bdc[j - 256]; }
        else              { br = bro[j - 384];         bd = bdo[j - 384]; }
        g_br[j] = br;
        g_bd[j] = bd;
    }
}

__global__ void prep_pd(const float* __restrict__ pooled) {
    int n = blockIdx.x, d = threadIdx.x;
    float v = pooled[(size_t)n * DF_W + d];
    __nv_bfloat16 h = __float2bfloat16(v);
    g_PDth[(size_t)d * ND + n] = h;
    g_PDtl[(size_t)d * ND + n] = __float2bfloat16(v - __bfloat162float(h));
}

template <bool RANGE>
__global__ void prep_base(const float* __restrict__ lat, const float* __restrict__ pos)
{
    __nv_bfloat16* __restrict__ OH = RANGE ? g_RBh : g_DBh;
    __nv_bfloat16* __restrict__ OL = RANGE ? g_RBl : g_DBl;
    size_t i = ((size_t)blockIdx.x * blockDim.x + threadIdx.x) * 4;
    float4 a = *(const float4*)(lat + i);
    float4 b = *(const float4*)(pos + i);
    float v[4] = {a.x + b.x, a.y + b.y, a.z + b.z, a.w + b.w};
    __nv_bfloat16 hb[4], lb[4];
#pragma unroll
    for (int j = 0; j < 4; j++) {
        hb[j] = __float2bfloat16(v[j]);
        lb[j] = __float2bfloat16(v[j] - __bfloat162float(hb[j]));
    }
    *(uint2*)(OH + i) = *(uint2*)hb;
    *(uint2*)(OL + i) = *(uint2*)lb;
}

// ---------------------------------------------------------------------------
// Fragment loads for one k16 slice (8 ldsm4 per warp), swizzled layout.
// ---------------------------------------------------------------------------
__device__ __forceinline__ void ld_frags(
    uint32_t (&ah)[3][4], uint32_t (&al)[3][4], uint32_t (&bh)[4], uint32_t (&bl)[4],
    uint32_t aH, uint32_t aL, uint32_t bH, uint32_t bL,
    int mrow0, int ncol0, int l, int kc)
{
    const int a7 = l & 7;
    const int ar = l & 15;
    const uint32_t aChunk = (uint32_t)((((l >> 4) + kc) ^ a7) * 16);
#pragma unroll
    for (int mt = 0; mt < 3; mt++) {
        uint32_t off = (uint32_t)((mrow0 + mt * 16 + ar) * 128) + aChunk;
        ldsm4(ah[mt][0], ah[mt][1], ah[mt][2], ah[mt][3], aH + off);
        ldsm4(al[mt][0], al[mt][1], al[mt][2], al[mt][3], aL + off);
    }
    {
        int brow = ncol0 + ((l >> 4) & 1) * 8 + (l & 7);
        uint32_t off = (uint32_t)(brow * 128)
                     + (uint32_t)(((((l >> 3) & 1) + kc) ^ a7) * 16);
        ldsm4(bh[0], bh[1], bh[2], bh[3], bH + off);
        ldsm4(bl[0], bl[1], bl[2], bl[3], bL + off);
    }
}

// ---------------------------------------------------------------------------
// 8-warp MMA stage with k16-level fragment double-buffering.
// ---------------------------------------------------------------------------
__device__ __forceinline__ void mma_stage8(
    float (&acc)[3][2][4], uint32_t aH, uint32_t aL, uint32_t bH, uint32_t bL,
    int mrow0, int ncol0, int l)
{
    uint32_t ah[2][3][4], al[2][3][4], bh[2][4], bl[2][4];
    ld_frags(ah[0], al[0], bh[0], bl[0], aH, aL, bH, bL, mrow0, ncol0, l, 0);

#pragma unroll
    for (int k16 = 0; k16 < 4; k16++) {
        const int cur = k16 & 1;
        if (k16 < 3)
            ld_frags(ah[cur ^ 1], al[cur ^ 1], bh[cur ^ 1], bl[cur ^ 1],
                     aH, aL, bH, bL, mrow0, ncol0, l, (k16 + 1) * 2);
#pragma unroll
        for (int mt = 0; mt < 3; mt++)
#pragma unroll
            for (int nf = 0; nf < 2; nf++) {
                const int ri = nf * 2;
                mma_bf16(acc[mt][nf], ah[cur][mt], bh[cur][ri], bh[cur][ri + 1]);
                mma_bf16(acc[mt][nf], ah[cur][mt], bl[cur][ri], bl[cur][ri + 1]);
                mma_bf16(acc[mt][nf], al[cur][mt], bh[cur][ri], bh[cur][ri + 1]);
            }
    }
}

// ---------------------------------------------------------------------------
// Kernel 1: feature GEMM on tensor cores (2-buf, 2 CTAs/SM, swizzled)
// ---------------------------------------------------------------------------
template <bool RANGE>
__global__ void __launch_bounds__(NTHREADS, 1) feat_mma()
{
    const __nv_bfloat16* __restrict__ Ah = RANGE ? g_RBh : g_DBh;
    const __nv_bfloat16* __restrict__ Al = RANGE ? g_RBl : g_DBl;
    const __nv_bfloat16* __restrict__ Bh = RANGE ? g_Wrth : g_Wdth;
    const __nv_bfloat16* __restrict__ Bl = RANGE ? g_Wrtl : g_Wdtl;
    const float* __restrict__ bias = RANGE ? g_br : g_bd;
    __nv_bfloat16* __restrict__ OH = RANGE ? g_RFh : g_DFh;
    __nv_bfloat16* __restrict__ OL = RANGE ? g_RFl : g_DFl;

    extern __shared__ char smem[];
    const uint32_t sb0 = smem_u32(smem);
    const int t = threadIdx.x;
    const int w = t >> 5, l = t & 31;
    const int m0 = blockIdx.x * BM;
    const int n0 = blockIdx.y * BN;
    const int mrow0 = (w >> 2) * 48;
    const int ncol0 = (w & 3) * 16;

    auto load_s = [&](int s) {
        const int buf = s & 1;
        const int koff = s * 64;
        const uint32_t aH = sb0 + (buf * 2 + 0) * AST;
        const uint32_t aL = sb0 + (buf * 2 + 1) * AST;
#pragma unroll
        for (int c = t; c < 768; c += NTHREADS) {
            int row = c >> 3, ch = c & 7;
            uint32_t so = sw_off(row, ch);
            size_t go = (size_t)(m0 + row) * E_DIM + koff + ch * 8;
            cp16(aH + so, Ah + go);
            cp16(aL + so, Al + go);
        }
        const uint32_t bH = sb0 + 4 * AST + (buf * 2 + 0) * BST;
        const uint32_t bL = sb0 + 4 * AST + (buf * 2 + 1) * BST;
#pragma unroll
        for (int c = t; c < 512; c += NTHREADS) {
            int row = c >> 3, ch = c & 7;
            uint32_t so = sw_off(row, ch);
            size_t go = (size_t)(n0 + row) * F_DIM + koff + ch * 8;
            cp16(bH + so, Bh + go);
            cp16(bL + so, Bl + go);
        }
    };

    float acc[3][2][4];
#pragma unroll
    for (int i = 0; i < 3; i++)
#pragma unroll
        for (int j = 0; j < 2; j++)
#pragma unroll
            for (int r = 0; r < 4; r++) acc[i][j][r] = 0.0f;

    load_s(0);
    CP_COMMIT();
#pragma unroll 1
    for (int s = 0; s < 8; ++s) {
        if (s < 7) { load_s(s + 1); CP_COMMIT(); CP_WAIT1(); }
        else       { CP_WAIT0(); }
        __syncthreads();
        const int buf = s & 1;
        mma_stage8(acc, sb0 + (buf * 2 + 0) * AST, sb0 + (buf * 2 + 1) * AST,
                   sb0 + 4 * AST + (buf * 2 + 0) * BST, sb0 + 4 * AST + (buf * 2 + 1) * BST,
                   mrow0, ncol0, l);
        __syncthreads();
    }

    // epilogue: + bias, split, store
#pragma unroll
    for (int mt = 0; mt < 3; mt++)
#pragma unroll
        for (int nf = 0; nf < 2; nf++)
#pragma unroll
            for (int half = 0; half < 2; half++) {
                int row = mrow0 + mt * 16 + (l >> 2) + 8 * half;
                int col = ncol0 + nf * 8 + 2 * (l & 3);
                float v0 = acc[mt][nf][half * 2 + 0] + bias[n0 + col];
                float v1 = acc[mt][nf][half * 2 + 1] + bias[n0 + col + 1];
                __nv_bfloat16 h0 = __float2bfloat16(v0);
                __nv_bfloat16 h1 = __float2bfloat16(v1);
                __nv_bfloat16 l0 = __float2bfloat16(v0 - __bfloat162float(h0));
                __nv_bfloat16 l1 = __float2bfloat16(v1 - __bfloat162float(h1));
                size_t off = (size_t)(m0 + row) * F_DIM + n0 + col;
                __nv_bfloat16 hp[2] = {h0, h1}, lp[2] = {l0, l1};
                *(uint32_t*)(OH + off) = *(uint32_t*)hp;
                *(uint32_t*)(OL + off) = *(uint32_t*)lp;
            }
}

// ---------------------------------------------------------------------------
// Kernel 2: fused attention — 4-buffer pipeline (wait_group 2), swizzled
// ---------------------------------------------------------------------------
__device__ __forceinline__ int stage_koff(int s) {
    return (s < 4) ? (256 + s * 64) : ((s - 4) * 64);
}

__device__ __forceinline__ void load_stage(uint32_t sb0, int gs, int m0, int t) {
    const int s = gs & 7;
    const int nt = gs >> 3;
    const int koff = stage_koff(s);
    const int n0 = nt * BN;
    const int buf = gs & 3;
    const uint32_t aH = sb0 + SM_A + (buf * 2 + 0) * AST;
    const uint32_t aL = sb0 + SM_A + (buf * 2 + 1) * AST;
#pragma unroll
    for (int c = t; c < 768; c += NTHREADS) {
        int row = c >> 3, ch = c & 7;
        uint32_t so = sw_off(row, ch);
        size_t go = (size_t)(m0 + row) * F_DIM + koff + ch * 8;
        cp16(aH + so, g_RFh + go);
        cp16(aL + so, g_RFl + go);
    }
    const uint32_t bH = sb0 + SM_B + (buf * 2 + 0) * BST;
    const uint32_t bL = sb0 + SM_B + (buf * 2 + 1) * BST;
#pragma unroll
    for (int c = t; c < 512; c += NTHREADS) {
        int row = c >> 3, ch = c & 7;
        uint32_t so = sw_off(row, ch);
        size_t go = (size_t)(n0 + row) * F_DIM + koff + ch * 8;
        cp16(bH + so, g_DFh + go);
        cp16(bL + so, g_DFl + go);
    }
}

__device__ __forceinline__ void load_df(uint32_t sb0, int nt, int t) {
    const int n0 = nt * BN;
#pragma unroll
    for (int c = t; c < 512; c += NTHREADS) {
        int row = c >> 3, ch = c & 7;
        uint32_t so = sw_off(row, ch);
        size_t go = (size_t)row * ND + n0 + ch * 8;
        cp16(sb0 + SM_DFH + so, g_PDth + go);
        cp16(sb0 + SM_DFL + so, g_PDtl + go);
    }
}

__global__ void __launch_bounds__(NTHREADS, 1) attention_kernel(float* __restrict__ out)
{
    extern __shared__ char smem[];
    const uint32_t sb0 = smem_u32(smem);

    const int t = threadIdx.x;
    const int w = t >> 5, l = t & 31;
    const int m0 = blockIdx.x * BM;
    const int mrow0 = (w >> 2) * 48;
    const int ncol0 = (w & 3) * 16;

    float* sRW = (float*)(smem + SM_RW);
    float* sRO = (float*)(smem + SM_RO);

    float ep[3][2][4];
#pragma unroll
    for (int i = 0; i < 3; i++)
#pragma unroll
        for (int j = 0; j < 2; j++)
#pragma unroll
            for (int r = 0; r < 4; r++) ep[i][j][r] = 0.0f;
    float pw[3][2]  = {{0.f,0.f},{0.f,0.f},{0.f,0.f}};
    float pwo[3][2] = {{0.f,0.f},{0.f,0.f},{0.f,0.f}};

    // prologue: three stages in flight
    load_stage(sb0, 0, m0, t);
    CP_COMMIT();
    load_stage(sb0, 1, m0, t);
    CP_COMMIT();
    load_stage(sb0, 2, m0, t);
    CP_COMMIT();

#pragma unroll 1
    for (int nt = 0; nt < NTILES; ++nt) {
        float acc[3][2][4];
        float con[3][2][4], off[3][2][4];

#pragma unroll 1
        for (int s = 0; s < NSTG; ++s) {
            const int gs = nt * NSTG + s;
            // commits so far = gs+3 (stages 0..gs+2); wait_group 2 completes
            // through commit #(gs+1) = stage gs, leaving gs+1, gs+2 in flight.
            CP_WAIT2();
            __syncthreads();
            // issue loads for stage gs+3; its buffer (gs+3)&3 == (gs-1)&3 had
            // readers ordered before this barrier. Commit unconditionally to
            // keep group counting uniform.
            {
                const int ns = gs + 3;
                if (ns < NTILES * NSTG) load_stage(sb0, ns, m0, t);
                if (s == 5) load_df(sb0, nt, t);
                CP_COMMIT();
            }

            if (s == 0 || s == 2 || s == 4) {
#pragma unroll
                for (int i = 0; i < 3; i++)
#pragma unroll
                    for (int j = 0; j < 2; j++)
#pragma unroll
                        for (int r = 0; r < 4; r++) acc[i][j][r] = 0.0f;
            }
            const int buf = gs & 3;
            mma_stage8(acc,
                       sb0 + SM_A + (buf * 2 + 0) * AST, sb0 + SM_A + (buf * 2 + 1) * AST,
                       sb0 + SM_B + (buf * 2 + 0) * BST, sb0 + SM_B + (buf * 2 + 1) * BST,
                       mrow0, ncol0, l);

            if (s == 1) {          // con ready (k 256..383)
#pragma unroll
                for (int i = 0; i < 3; i++)
#pragma unroll
                    for (int j = 0; j < 2; j++)
#pragma unroll
                        for (int r = 0; r < 4; r++)
                            con[i][j][r] = fast_tanh(acc[i][j][r] * INV_SQRT_H) * MAX_CONTRAST;
            } else if (s == 3) {   // off ready (k 384..511)
#pragma unroll
                for (int i = 0; i < 3; i++)
#pragma unroll
                    for (int j = 0; j < 2; j++)
#pragma unroll
                        for (int r = 0; r < 4; r++)
                            off[i][j][r] = fast_tanh(acc[i][j][r] * INV_SQRT_H);
            }
        }

        // ---- combine: w = exp(l-30); row sums; wc -> bf16 hi/lo smem ----
#pragma unroll
        for (int mt = 0; mt < 3; mt++)
#pragma unroll
            for (int nf = 0; nf < 2; nf++)
#pragma unroll
                for (int r = 0; r < 4; r++) {
                    int row = mrow0 + mt * 16 + (l >> 2) + 8 * (r >> 1);
                    int col = ncol0 + nf * 8 + 2 * (l & 3) + (r & 1);
                    float wgt = __expf(acc[mt][nf][r] - EXP_SHIFT);
                    pw[mt][r >> 1]  += wgt;
                    pwo[mt][r >> 1] += wgt * off[mt][nf][r];
                    float wc = wgt * con[mt][nf][r];
                    __nv_bfloat16 h = __float2bfloat16(wc);
                    uint32_t so = sw_off(row, col >> 3) + (uint32_t)((col & 7) * 2);
                    *(__nv_bfloat16*)(smem + SM_WCH + so) = h;
                    *(__nv_bfloat16*)(smem + SM_WCL + so) =
                        __float2bfloat16(wc - __bfloat162float(h));
                }
        // df group (commit #(nt*8+9)) complete when <=2 newer outstanding
        // (total commits here = nt*8+11).
        CP_WAIT2();
        __syncthreads();

        // ---- epilogue mma: ep += wc @ pooled^T (k = 64 tile cols) ----
        mma_stage8(ep, sb0 + SM_WCH, sb0 + SM_WCL, sb0 + SM_DFH, sb0 + SM_DFL,
                   mrow0, ncol0, l);
        // next tile's stage barriers order these reads before sWC/sDF rewrite
    }

    // ---- row-sum reduce: lanes (xor 1,2) then across the 4 n-warps ----
#pragma unroll
    for (int mt = 0; mt < 3; mt++)
#pragma unroll
        for (int h = 0; h < 2; h++) {
            pw[mt][h]  += __shfl_xor_sync(0xffffffffu, pw[mt][h], 1);
            pw[mt][h]  += __shfl_xor_sync(0xffffffffu, pw[mt][h], 2);
            pwo[mt][h] += __shfl_xor_sync(0xffffffffu, pwo[mt][h], 1);
            pwo[mt][h] += __shfl_xor_sync(0xffffffffu, pwo[mt][h], 2);
        }
    if ((l & 3) == 0) {
        const int wq = w & 3;
#pragma unroll
        for (int mt = 0; mt < 3; mt++)
#pragma unroll
            for (int h = 0; h < 2; h++) {
                int row = mrow0 + mt * 16 + (l >> 2) + 8 * h;
                sRW[wq * 96 + row] = pw[mt][h];
                sRO[wq * 96 + row] = pwo[mt][h];
            }
    }
    __syncthreads();

    // ---- final: out = (ep + sum(w*off)) / sum(w) ----
#pragma unroll
    for (int mt = 0; mt < 3; mt++)
#pragma unroll
        for (int nf = 0; nf < 2; nf++)
#pragma unroll
            for (int half = 0; half < 2; half++) {
                int row = mrow0 + mt * 16 + (l >> 2) + 8 * half;
                int col = ncol0 + nf * 8 + 2 * (l & 3);
                float sw  = sRW[row] + sRW[96 + row] + sRW[192 + row] + sRW[288 + row];
                float swo = sRO[row] + sRO[96 + row] + sRO[192 + row] + sRO[288 + row];
                float inv = 1.0f / sw;
                float2 v;
                v.x = (ep[mt][nf][half * 2 + 0] + swo) * inv;
                v.y = (ep[mt][nf][half * 2 + 1] + swo) * inv;
                *(float2*)(out + (size_t)(m0 + row) * DF_W + col) = v;
            }
}

// ---------------------------------------------------------------------------
// kernel_launch — kernel launches only (graph-capture clean)
// ---------------------------------------------------------------------------
extern "C" void kernel_launch(void* const* d_in, const int* in_sizes, int n_in,
                              void* d_out, int out_size)
{
    const float* pooled = (const float*)d_in[0];
    const float* rl     = (const float*)d_in[1];
    const float* dl     = (const float*)d_in[2];
    const float* rp     = (const float*)d_in[3];
    const float* dp     = (const float*)d_in[4];
    const float* Wrp    = (const float*)d_in[5];
    const float* brp    = (const float*)d_in[6];
    const float* Wdp    = (const float*)d_in[7];
    const float* bdp    = (const float*)d_in[8];
    const float* Wrc    = (const float*)d_in[9];
    const float* brc    = (const float*)d_in[10];
    const float* Wdc    = (const float*)d_in[11];
    const float* bdc    = (const float*)d_in[12];
    const float* Wro    = (const float*)d_in[13];
    const float* bro    = (const float*)d_in[14];
    const float* Wdo    = (const float*)d_in[15];
    const float* bdo    = (const float*)d_in[16];
    float* out = (float*)d_out;

    prep_weights<<<512, 512>>>(Wrp, brp, Wdp, bdp, Wrc, brc, Wdc, bdc,
                               Wro, bro, Wdo, bdo);
    prep_pd<<<ND, DF_W>>>(pooled);
    prep_base<true><<<(NR * E_DIM / 4) / 256, 256>>>(rl, rp);
    prep_base<false><<<(ND * E_DIM / 4) / 256, 256>>>(dl, dp);

    cudaFuncSetAttribute(feat_mma<false>,
                         cudaFuncAttributeMaxDynamicSharedMemorySize, SM2_TOTAL);
    cudaFuncSetAttribute(feat_mma<true>,
                         cudaFuncAttributeMaxDynamicSharedMemorySize, SM2_TOTAL);
    dim3 gridD(ND / BM, F_DIM / BN);   // 18 x 8
    feat_mma<false><<<gridD, NTHREADS, SM2_TOTAL>>>();
    dim3 gridR(NR / BM, F_DIM / BN);   // 144 x 8
    feat_mma<true><<<gridR, NTHREADS, SM2_TOTAL>>>();

    cudaFuncSetAttribute(attention_kernel,
                         cudaFuncAttributeMaxDynamicSharedMemorySize, SM_TOTAL);
    attention_kernel<<<NR / BM, NTHREADS, SM_TOTAL>>>(out);
}

// round 13
// speedup vs baseline: 6.3811x; 1.0542x over previous
#include <cuda_runtime.h>
#include <cuda_bf16.h>
#include <cstdint>
#include <math.h>

// ---------------------------------------------------------------------------
// FractalAttention3D — mma.sync bf16 (2-way split), 8-warp tiling,
//   paired n-tiles with A-fragment register reuse, phases repr->con->off
//   folded into stage tails. XOR-swizzled 128B smem rows. sm_80+ PTX only.
// ---------------------------------------------------------------------------

#define NR 13824
#define ND 1728
#define E_DIM 512
#define F_DIM 512
#define DF_W 64
#define LOGIT_SCALE 0.25f
#define INV_SQRT_H 0.08838834764831843f
#define MAX_CONTRAST 1.8f
#define EXP_SHIFT 30.0f

#define BM 96                 // 144 CTAs ~ one wave
#define BN 64
#define NPAIRS 13             // tiles 0..25 in pairs; tile 26 solo
#define PAIR_STAGES (NPAIRS * 8)   // 104
#define TOT_STAGES (PAIR_STAGES + 8) // 112
#define NTHREADS 256          // 8 warps: 2m x 4n grid of 48x16 warp tiles

// -------- device scratch (static; no cudaMalloc allowed) --------
__device__ __align__(16) float g_br[F_DIM];
__device__ __align__(16) float g_bd[F_DIM];
__device__ __align__(16) __nv_bfloat16 g_Wrth[(size_t)F_DIM * F_DIM];
__device__ __align__(16) __nv_bfloat16 g_Wrtl[(size_t)F_DIM * F_DIM];
__device__ __align__(16) __nv_bfloat16 g_Wdth[(size_t)F_DIM * F_DIM];
__device__ __align__(16) __nv_bfloat16 g_Wdtl[(size_t)F_DIM * F_DIM];
__device__ __align__(16) __nv_bfloat16 g_RBh[(size_t)NR * E_DIM];
__device__ __align__(16) __nv_bfloat16 g_RBl[(size_t)NR * E_DIM];
__device__ __align__(16) __nv_bfloat16 g_DBh[(size_t)ND * E_DIM];
__device__ __align__(16) __nv_bfloat16 g_DBl[(size_t)ND * E_DIM];
__device__ __align__(16) __nv_bfloat16 g_RFh[(size_t)NR * F_DIM];
__device__ __align__(16) __nv_bfloat16 g_RFl[(size_t)NR * F_DIM];
__device__ __align__(16) __nv_bfloat16 g_DFh[(size_t)ND * F_DIM];
__device__ __align__(16) __nv_bfloat16 g_DFl[(size_t)ND * F_DIM];
__device__ __align__(16) __nv_bfloat16 g_PDth[(size_t)DF_W * ND];  // pooled^T hi
__device__ __align__(16) __nv_bfloat16 g_PDtl[(size_t)DF_W * ND];

// ---------------- attention smem (2-buf lockstep, paired B) ----------------
#define AST 12288            // 96*128
#define BST 8192             // 64*128
#define SM_A   0             // 2 bufs x (hi,lo) = 4*AST = 49152
#define SM_B   49152         // 2 bufs x (hi0,lo0,hi1,lo1) = 8*BST = 65536
#define SM_WC0 114688        // hi+lo = 2*AST = 24576
#define SM_WC1 139264        // 24576
#define SM_DF0 163840        // hi+lo = 2*BST = 16384
#define SM_DF1 180224        // 16384
#define SM_RW  196608        // 4*96*4 = 1536
#define SM_RO  198144        // 1536
#define SM_TOTAL 199680

// feat_mma smem: 2 bufs -> 4*AST + 4*BST
#define SM2_TOTAL 81920

// swizzled byte offset of (row, 16B-chunk c) within a 128B-row tile
__device__ __forceinline__ uint32_t sw_off(int row, int c) {
    return (uint32_t)(row * 128 + ((c ^ (row & 7)) * 16));
}

// ---------------- PTX helpers ----------------
__device__ __forceinline__ uint32_t smem_u32(const void* p) {
    uint32_t a;
    asm("{ .reg .u64 t; cvta.to.shared.u64 t, %1; cvt.u32.u64 %0, t; }" : "=r"(a) : "l"(p));
    return a;
}
__device__ __forceinline__ void cp16(uint32_t dst, const void* src) {
    asm volatile("cp.async.cg.shared.global [%0], [%1], 16;" :: "r"(dst), "l"(src));
}
#define CP_COMMIT() asm volatile("cp.async.commit_group;" ::: "memory")
#define CP_WAIT0()  asm volatile("cp.async.wait_group 0;" ::: "memory")
#define CP_WAIT1()  asm volatile("cp.async.wait_group 1;" ::: "memory")

__device__ __forceinline__ void ldsm4(uint32_t& r0, uint32_t& r1, uint32_t& r2, uint32_t& r3,
                                      uint32_t addr) {
    asm volatile("ldmatrix.sync.aligned.m8n8.x4.shared.b16 {%0,%1,%2,%3}, [%4];"
                 : "=r"(r0), "=r"(r1), "=r"(r2), "=r"(r3) : "r"(addr));
}
__device__ __forceinline__ void mma_bf16(float* c, const uint32_t* a, uint32_t b0, uint32_t b1) {
    asm("mma.sync.aligned.m16n8k16.row.col.f32.bf16.bf16.f32 "
        "{%0,%1,%2,%3}, {%4,%5,%6,%7}, {%8,%9}, {%0,%1,%2,%3};"
        : "+f"(c[0]), "+f"(c[1]), "+f"(c[2]), "+f"(c[3])
        : "r"(a[0]), "r"(a[1]), "r"(a[2]), "r"(a[3]), "r"(b0), "r"(b1));
}
__device__ __forceinline__ float fast_tanh(float x) {
    float e = __expf(-2.0f * x);
    return __fdividef(2.0f, e + 1.0f) - 1.0f;
}

// ---------------------------------------------------------------------------
// prep kernels (unchanged)
// ---------------------------------------------------------------------------
__global__ void prep_weights(
    const float* __restrict__ Wrp, const float* __restrict__ brp,
    const float* __restrict__ Wdp, const float* __restrict__ bdp,
    const float* __restrict__ Wrc, const float* __restrict__ brc,
    const float* __restrict__ Wdc, const float* __restrict__ bdc,
    const float* __restrict__ Wro, const float* __restrict__ bro,
    const float* __restrict__ Wdo, const float* __restrict__ bdo)
{
    int e = blockIdx.x, j = threadIdx.x;
    float wr, wd;
    if (j < 256)      { wr = Wrp[e * 256 + j] * LOGIT_SCALE; wd = Wdp[e * 256 + j]; }
    else if (j < 384) { wr = Wrc[e * 128 + (j - 256)];       wd = Wdc[e * 128 + (j - 256)]; }
    else              { wr = Wro[e * 128 + (j - 384)];       wd = Wdo[e * 128 + (j - 384)]; }
    size_t toff = (size_t)j * F_DIM + e;
    __nv_bfloat16 h = __float2bfloat16(wr);
    g_Wrth[toff] = h;
    g_Wrtl[toff] = __float2bfloat16(wr - __bfloat162float(h));
    h = __float2bfloat16(wd);
    g_Wdth[toff] = h;
    g_Wdtl[toff] = __float2bfloat16(wd - __bfloat162float(h));
    if (e == 0) {
        float br, bd;
        if (j < 256)      { br = brp[j] * LOGIT_SCALE; bd = bdp[j]; }
        else if (j < 384) { br = brc[j - 256];         bd = bdc[j - 256]; }
        else              { br = bro[j - 384];         bd = bdo[j - 384]; }
        g_br[j] = br;
        g_bd[j] = bd;
    }
}

__global__ void prep_pd(const float* __restrict__ pooled) {
    int n = blockIdx.x, d = threadIdx.x;
    float v = pooled[(size_t)n * DF_W + d];
    __nv_bfloat16 h = __float2bfloat16(v);
    g_PDth[(size_t)d * ND + n] = h;
    g_PDtl[(size_t)d * ND + n] = __float2bfloat16(v - __bfloat162float(h));
}

template <bool RANGE>
__global__ void prep_base(const float* __restrict__ lat, const float* __restrict__ pos)
{
    __nv_bfloat16* __restrict__ OH = RANGE ? g_RBh : g_DBh;
    __nv_bfloat16* __restrict__ OL = RANGE ? g_RBl : g_DBl;
    size_t i = ((size_t)blockIdx.x * blockDim.x + threadIdx.x) * 4;
    float4 a = *(const float4*)(lat + i);
    float4 b = *(const float4*)(pos + i);
    float v[4] = {a.x + b.x, a.y + b.y, a.z + b.z, a.w + b.w};
    __nv_bfloat16 hb[4], lb[4];
#pragma unroll
    for (int j = 0; j < 4; j++) {
        hb[j] = __float2bfloat16(v[j]);
        lb[j] = __float2bfloat16(v[j] - __bfloat162float(hb[j]));
    }
    *(uint2*)(OH + i) = *(uint2*)hb;
    *(uint2*)(OL + i) = *(uint2*)lb;
}

// ---------------------------------------------------------------------------
// Fragment loads for one k16 slice, swizzled layout.
// ---------------------------------------------------------------------------
__device__ __forceinline__ void ld_a_frags(
    uint32_t (&ah)[3][4], uint32_t (&al)[3][4],
    uint32_t aH, uint32_t aL, int mrow0, int l, int kc)
{
    const int a7 = l & 7;
    const int ar = l & 15;
    const uint32_t aChunk = (uint32_t)((((l >> 4) + kc) ^ a7) * 16);
#pragma unroll
    for (int mt = 0; mt < 3; mt++) {
        uint32_t off = (uint32_t)((mrow0 + mt * 16 + ar) * 128) + aChunk;
        ldsm4(ah[mt][0], ah[mt][1], ah[mt][2], ah[mt][3], aH + off);
        ldsm4(al[mt][0], al[mt][1], al[mt][2], al[mt][3], aL + off);
    }
}
__device__ __forceinline__ void ld_b_frags(
    uint32_t (&bh)[4], uint32_t (&bl)[4],
    uint32_t bH, uint32_t bL, int ncol0, int l, int kc)
{
    const int a7 = l & 7;
    int brow = ncol0 + ((l >> 4) & 1) * 8 + (l & 7);
    uint32_t off = (uint32_t)(brow * 128)
                 + (uint32_t)(((((l >> 3) & 1) + kc) ^ a7) * 16);
    ldsm4(bh[0], bh[1], bh[2], bh[3], bH + off);
    ldsm4(bl[0], bl[1], bl[2], bl[3], bL + off);
}

// single-tile 96x64x64 stage (also used for epilogue + solo tile)
__device__ __forceinline__ void mma_one(
    float (&acc)[3][2][4], uint32_t aH, uint32_t aL, uint32_t bH, uint32_t bL,
    int mrow0, int ncol0, int l)
{
#pragma unroll
    for (int k16 = 0; k16 < 4; k16++) {
        uint32_t ah[3][4], al[3][4], bh[4], bl[4];
        ld_a_frags(ah, al, aH, aL, mrow0, l, k16 * 2);
        ld_b_frags(bh, bl, bH, bL, ncol0, l, k16 * 2);
#pragma unroll
        for (int mt = 0; mt < 3; mt++)
#pragma unroll
            for (int nf = 0; nf < 2; nf++) {
                const int ri = nf * 2;
                mma_bf16(acc[mt][nf], ah[mt], bh[ri], bh[ri + 1]);
                mma_bf16(acc[mt][nf], ah[mt], bl[ri], bl[ri + 1]);
                mma_bf16(acc[mt][nf], al[mt], bh[ri], bh[ri + 1]);
            }
    }
}

// paired stage: A fragments loaded once, both tiles' mma issued from them
__device__ __forceinline__ void mma_pair(
    float (&a0)[3][2][4], float (&a1)[3][2][4],
    uint32_t aH, uint32_t aL, uint32_t bB,   // bB = base of [hi0,lo0,hi1,lo1]
    int mrow0, int ncol0, int l)
{
#pragma unroll
    for (int k16 = 0; k16 < 4; k16++) {
        uint32_t ah[3][4], al[3][4], b0h[4], b0l[4], b1h[4], b1l[4];
        ld_a_frags(ah, al, aH, aL, mrow0, l, k16 * 2);
        ld_b_frags(b0h, b0l, bB + 0 * BST, bB + 1 * BST, ncol0, l, k16 * 2);
        ld_b_frags(b1h, b1l, bB + 2 * BST, bB + 3 * BST, ncol0, l, k16 * 2);
#pragma unroll
        for (int mt = 0; mt < 3; mt++)
#pragma unroll
            for (int nf = 0; nf < 2; nf++) {
                const int ri = nf * 2;
                mma_bf16(a0[mt][nf], ah[mt], b0h[ri], b0h[ri + 1]);
                mma_bf16(a0[mt][nf], ah[mt], b0l[ri], b0l[ri + 1]);
                mma_bf16(a0[mt][nf], al[mt], b0h[ri], b0h[ri + 1]);
                mma_bf16(a1[mt][nf], ah[mt], b1h[ri], b1h[ri + 1]);
                mma_bf16(a1[mt][nf], ah[mt], b1l[ri], b1l[ri + 1]);
                mma_bf16(a1[mt][nf], al[mt], b1h[ri], b1h[ri + 1]);
            }
    }
}

// ---------------------------------------------------------------------------
// Kernel 1: feature GEMM on tensor cores (unchanged structure; mma_one)
// ---------------------------------------------------------------------------
template <bool RANGE>
__global__ void __launch_bounds__(NTHREADS, 1) feat_mma()
{
    const __nv_bfloat16* __restrict__ Ah = RANGE ? g_RBh : g_DBh;
    const __nv_bfloat16* __restrict__ Al = RANGE ? g_RBl : g_DBl;
    const __nv_bfloat16* __restrict__ Bh = RANGE ? g_Wrth : g_Wdth;
    const __nv_bfloat16* __restrict__ Bl = RANGE ? g_Wrtl : g_Wdtl;
    const float* __restrict__ bias = RANGE ? g_br : g_bd;
    __nv_bfloat16* __restrict__ OH = RANGE ? g_RFh : g_DFh;
    __nv_bfloat16* __restrict__ OL = RANGE ? g_RFl : g_DFl;

    extern __shared__ char smem[];
    const uint32_t sb0 = smem_u32(smem);
    const int t = threadIdx.x;
    const int w = t >> 5, l = t & 31;
    const int m0 = blockIdx.x * BM;
    const int n0 = blockIdx.y * BN;
    const int mrow0 = (w >> 2) * 48;
    const int ncol0 = (w & 3) * 16;

    auto load_s = [&](int s) {
        const int buf = s & 1;
        const int koff = s * 64;
        const uint32_t aH = sb0 + (buf * 2 + 0) * AST;
        const uint32_t aL = sb0 + (buf * 2 + 1) * AST;
#pragma unroll
        for (int c = t; c < 768; c += NTHREADS) {
            int row = c >> 3, ch = c & 7;
            uint32_t so = sw_off(row, ch);
            size_t go = (size_t)(m0 + row) * E_DIM + koff + ch * 8;
            cp16(aH + so, Ah + go);
            cp16(aL + so, Al + go);
        }
        const uint32_t bH = sb0 + 4 * AST + (buf * 2 + 0) * BST;
        const uint32_t bL = sb0 + 4 * AST + (buf * 2 + 1) * BST;
#pragma unroll
        for (int c = t; c < 512; c += NTHREADS) {
            int row = c >> 3, ch = c & 7;
            uint32_t so = sw_off(row, ch);
            size_t go = (size_t)(n0 + row) * F_DIM + koff + ch * 8;
            cp16(bH + so, Bh + go);
            cp16(bL + so, Bl + go);
        }
    };

    float acc[3][2][4];
#pragma unroll
    for (int i = 0; i < 3; i++)
#pragma unroll
        for (int j = 0; j < 2; j++)
#pragma unroll
            for (int r = 0; r < 4; r++) acc[i][j][r] = 0.0f;

    load_s(0);
    CP_COMMIT();
#pragma unroll 1
    for (int s = 0; s < 8; ++s) {
        if (s < 7) { load_s(s + 1); CP_COMMIT(); CP_WAIT1(); }
        else       { CP_WAIT0(); }
        __syncthreads();
        const int buf = s & 1;
        mma_one(acc, sb0 + (buf * 2 + 0) * AST, sb0 + (buf * 2 + 1) * AST,
                sb0 + 4 * AST + (buf * 2 + 0) * BST, sb0 + 4 * AST + (buf * 2 + 1) * BST,
                mrow0, ncol0, l);
        __syncthreads();
    }

#pragma unroll
    for (int mt = 0; mt < 3; mt++)
#pragma unroll
        for (int nf = 0; nf < 2; nf++)
#pragma unroll
            for (int half = 0; half < 2; half++) {
                int row = mrow0 + mt * 16 + (l >> 2) + 8 * half;
                int col = ncol0 + nf * 8 + 2 * (l & 3);
                float v0 = acc[mt][nf][half * 2 + 0] + bias[n0 + col];
                float v1 = acc[mt][nf][half * 2 + 1] + bias[n0 + col + 1];
                __nv_bfloat16 h0 = __float2bfloat16(v0);
                __nv_bfloat16 h1 = __float2bfloat16(v1);
                __nv_bfloat16 l0 = __float2bfloat16(v0 - __bfloat162float(h0));
                __nv_bfloat16 l1 = __float2bfloat16(v1 - __bfloat162float(h1));
                size_t off = (size_t)(m0 + row) * F_DIM + n0 + col;
                __nv_bfloat16 hp[2] = {h0, h1}, lp[2] = {l0, l1};
                *(uint32_t*)(OH + off) = *(uint32_t*)hp;
                *(uint32_t*)(OL + off) = *(uint32_t*)lp;
            }
}

// ---------------------------------------------------------------------------
// Kernel 2: fused attention — paired tiles, phases repr->con->off
// ---------------------------------------------------------------------------
// phase order: s0-3 repr (koff 0..192), s4-5 con (256,320), s6-7 off (384,448)
__device__ __forceinline__ int stage_koff(int s) {
    return (s < 4) ? (s * 64) : ((s < 6) ? (256 + (s - 4) * 64) : (384 + (s - 6) * 64));
}

// load A slice + B tile(s) for global stage st into buffer st&1
__device__ __forceinline__ void load_stage(uint32_t sb0, int st, int m0, int t) {
    const bool solo = (st >= PAIR_STAGES);
    const int s = solo ? (st - PAIR_STAGES) : (st & 7);
    const int p = st >> 3;
    const int koff = stage_koff(s);
    const int n0 = (solo ? 26 : 2 * p) * BN;
    const int buf = st & 1;
    const uint32_t aH = sb0 + SM_A + (buf * 2 + 0) * AST;
    const uint32_t aL = sb0 + SM_A + (buf * 2 + 1) * AST;
#pragma unroll
    for (int c = t; c < 768; c += NTHREADS) {
        int row = c >> 3, ch = c & 7;
        uint32_t so = sw_off(row, ch);
        size_t go = (size_t)(m0 + row) * F_DIM + koff + ch * 8;
        cp16(aH + so, g_RFh + go);
        cp16(aL + so, g_RFl + go);
    }
    const uint32_t bB = sb0 + SM_B + buf * 4 * BST;
#pragma unroll
    for (int c = t; c < 512; c += NTHREADS) {
        int row = c >> 3, ch = c & 7;
        uint32_t so = sw_off(row, ch);
        size_t go = (size_t)(n0 + row) * F_DIM + koff + ch * 8;
        cp16(bB + 0 * BST + so, g_DFh + go);
        cp16(bB + 1 * BST + so, g_DFl + go);
        if (!solo) {
            size_t go1 = go + (size_t)BN * F_DIM;
            cp16(bB + 2 * BST + so, g_DFh + go1);
            cp16(bB + 3 * BST + so, g_DFl + go1);
        }
    }
}

// load pooled^T tiles for a pair (or solo) into sDF0 / sDF1
__device__ __forceinline__ void load_df(uint32_t sb0, int n0, uint32_t dfBase, int t) {
#pragma unroll
    for (int c = t; c < 512; c += NTHREADS) {
        int row = c >> 3, ch = c & 7;
        uint32_t so = sw_off(row, ch);
        size_t go = (size_t)row * ND + n0 + ch * 8;
        cp16(dfBase + so, g_PDth + go);
        cp16(dfBase + BST + so, g_PDtl + go);
    }
}

__global__ void __launch_bounds__(NTHREADS, 1) attention_kernel(float* __restrict__ out)
{
    extern __shared__ char smem[];
    const uint32_t sb0 = smem_u32(smem);

    const int t = threadIdx.x;
    const int w = t >> 5, l = t & 31;
    const int m0 = blockIdx.x * BM;
    const int mrow0 = (w >> 2) * 48;
    const int ncol0 = (w & 3) * 16;

    float* sRW = (float*)(smem + SM_RW);
    float* sRO = (float*)(smem + SM_RO);

    float ep[3][2][4];
#pragma unroll
    for (int i = 0; i < 3; i++)
#pragma unroll
        for (int j = 0; j < 2; j++)
#pragma unroll
            for (int r = 0; r < 4; r++) ep[i][j][r] = 0.0f;
    float pw[3][2]  = {{0.f,0.f},{0.f,0.f},{0.f,0.f}};
    float pwo[3][2] = {{0.f,0.f},{0.f,0.f},{0.f,0.f}};

    float acc0[3][2][4], acc1[3][2][4];
    float w0[3][2][4], w1[3][2][4];

    load_stage(sb0, 0, m0, t);
    CP_COMMIT();

#pragma unroll 1
    for (int st = 0; st < TOT_STAGES; ++st) {
        const bool solo = (st >= PAIR_STAGES);
        const int s = solo ? (st - PAIR_STAGES) : (st & 7);

        if (st + 1 < TOT_STAGES) {
            load_stage(sb0, st + 1, m0, t);
            // attach df loads so they complete one group before their use
            if (st + 1 < PAIR_STAGES) {
                if (((st + 1) & 7) == 6) {
                    int p = (st + 1) >> 3;
                    load_df(sb0, 2 * p * BN, sb0 + SM_DF0, t);
                    load_df(sb0, (2 * p + 1) * BN, sb0 + SM_DF1, t);
                }
            } else if (st + 1 == PAIR_STAGES + 6) {
                load_df(sb0, 26 * BN, sb0 + SM_DF0, t);
            }
            CP_COMMIT();
            CP_WAIT1();
        } else {
            CP_WAIT0();
        }
        __syncthreads();

        if (s == 0 || s == 4 || s == 6) {
#pragma unroll
            for (int i = 0; i < 3; i++)
#pragma unroll
                for (int j = 0; j < 2; j++)
#pragma unroll
                    for (int r = 0; r < 4; r++) { acc0[i][j][r] = 0.0f; acc1[i][j][r] = 0.0f; }
        }

        const int buf = st & 1;
        const uint32_t aH = sb0 + SM_A + (buf * 2 + 0) * AST;
        const uint32_t aL = sb0 + SM_A + (buf * 2 + 1) * AST;
        const uint32_t bB = sb0 + SM_B + buf * 4 * BST;
        if (!solo)
            mma_pair(acc0, acc1, aH, aL, bB, mrow0, ncol0, l);
        else
            mma_one(acc0, aH, aL, bB, bB + BST, mrow0, ncol0, l);
        __syncthreads();

        // ---- phase tails ----
        if (s == 3) {            // repr done: w = exp(logit - shift); pw
#pragma unroll
            for (int mt = 0; mt < 3; mt++)
#pragma unroll
                for (int nf = 0; nf < 2; nf++)
#pragma unroll
                    for (int r = 0; r < 4; r++) {
                        float v0 = __expf(acc0[mt][nf][r] - EXP_SHIFT);
                        w0[mt][nf][r] = v0;
                        pw[mt][r >> 1] += v0;
                        if (!solo) {
                            float v1 = __expf(acc1[mt][nf][r] - EXP_SHIFT);
                            w1[mt][nf][r] = v1;
                            pw[mt][r >> 1] += v1;
                        }
                    }
        } else if (s == 5) {     // con done: wc -> smem (bf16 hi/lo)
#pragma unroll
            for (int mt = 0; mt < 3; mt++)
#pragma unroll
                for (int nf = 0; nf < 2; nf++)
#pragma unroll
                    for (int r = 0; r < 4; r++) {
                        int row = mrow0 + mt * 16 + (l >> 2) + 8 * (r >> 1);
                        int col = ncol0 + nf * 8 + 2 * (l & 3) + (r & 1);
                        uint32_t so = sw_off(row, col >> 3) + (uint32_t)((col & 7) * 2);
                        float wc0 = w0[mt][nf][r]
                                  * (fast_tanh(acc0[mt][nf][r] * INV_SQRT_H) * MAX_CONTRAST);
                        __nv_bfloat16 h = __float2bfloat16(wc0);
                        *(__nv_bfloat16*)(smem + SM_WC0 + so) = h;
                        *(__nv_bfloat16*)(smem + SM_WC0 + AST + so) =
                            __float2bfloat16(wc0 - __bfloat162float(h));
                        if (!solo) {
                            float wc1 = w1[mt][nf][r]
                                      * (fast_tanh(acc1[mt][nf][r] * INV_SQRT_H) * MAX_CONTRAST);
                            h = __float2bfloat16(wc1);
                            *(__nv_bfloat16*)(smem + SM_WC1 + so) = h;
                            *(__nv_bfloat16*)(smem + SM_WC1 + AST + so) =
                                __float2bfloat16(wc1 - __bfloat162float(h));
                        }
                    }
        } else if (s == 7) {     // off done: pwo; then epilogue(s)
#pragma unroll
            for (int mt = 0; mt < 3; mt++)
#pragma unroll
                for (int nf = 0; nf < 2; nf++)
#pragma unroll
                    for (int r = 0; r < 4; r++) {
                        pwo[mt][r >> 1] += w0[mt][nf][r]
                                         * fast_tanh(acc0[mt][nf][r] * INV_SQRT_H);
                        if (!solo)
                            pwo[mt][r >> 1] += w1[mt][nf][r]
                                             * fast_tanh(acc1[mt][nf][r] * INV_SQRT_H);
                    }
            __syncthreads();   // wc writes (s5) already barriered; this orders pwo-tail + wc vs epilogue reads
            mma_one(ep, sb0 + SM_WC0, sb0 + SM_WC0 + AST,
                    sb0 + SM_DF0, sb0 + SM_DF0 + BST, mrow0, ncol0, l);
            if (!solo)
                mma_one(ep, sb0 + SM_WC1, sb0 + SM_WC1 + AST,
                        sb0 + SM_DF1, sb0 + SM_DF1 + BST, mrow0, ncol0, l);
        }
    }

    // ---- row-sum reduce: lanes (xor 1,2) then across the 4 n-warps ----
#pragma unroll
    for (int mt = 0; mt < 3; mt++)
#pragma unroll
        for (int h = 0; h < 2; h++) {
            pw[mt][h]  += __shfl_xor_sync(0xffffffffu, pw[mt][h], 1);
            pw[mt][h]  += __shfl_xor_sync(0xffffffffu, pw[mt][h], 2);
            pwo[mt][h] += __shfl_xor_sync(0xffffffffu, pwo[mt][h], 1);
            pwo[mt][h] += __shfl_xor_sync(0xffffffffu, pwo[mt][h], 2);
        }
    if ((l & 3) == 0) {
        const int wq = w & 3;
#pragma unroll
        for (int mt = 0; mt < 3; mt++)
#pragma unroll
            for (int h = 0; h < 2; h++) {
                int row = mrow0 + mt * 16 + (l >> 2) + 8 * h;
                sRW[wq * 96 + row] = pw[mt][h];
                sRO[wq * 96 + row] = pwo[mt][h];
            }
    }
    __syncthreads();

    // ---- final: out = (ep + sum(w*off)) / sum(w) ----
#pragma unroll
    for (int mt = 0; mt < 3; mt++)
#pragma unroll
        for (int nf = 0; nf < 2; nf++)
#pragma unroll
            for (int half = 0; half < 2; half++) {
                int row = mrow0 + mt * 16 + (l >> 2) + 8 * half;
                int col = ncol0 + nf * 8 + 2 * (l & 3);
                float sw  = sRW[row] + sRW[96 + row] + sRW[192 + row] + sRW[288 + row];
                float swo = sRO[row] + sRO[96 + row] + sRO[192 + row] + sRO[288 + row];
                float inv = 1.0f / sw;
                float2 v;
                v.x = (ep[mt][nf][half * 2 + 0] + swo) * inv;
                v.y = (ep[mt][nf][half * 2 + 1] + swo) * inv;
                *(float2*)(out + (size_t)(m0 + row) * DF_W + col) = v;
            }
}

// ---------------------------------------------------------------------------
// kernel_launch — kernel launches only (graph-capture clean)
// ---------------------------------------------------------------------------
extern "C" void kernel_launch(void* const* d_in, const int* in_sizes, int n_in,
                              void* d_out, int out_size)
{
    const float* pooled = (const float*)d_in[0];
    const float* rl     = (const float*)d_in[1];
    const float* dl     = (const float*)d_in[2];
    const float* rp     = (const float*)d_in[3];
    const float* dp     = (const float*)d_in[4];
    const float* Wrp    = (const float*)d_in[5];
    const float* brp    = (const float*)d_in[6];
    const float* Wdp    = (const float*)d_in[7];
    const float* bdp    = (const float*)d_in[8];
    const float* Wrc    = (const float*)d_in[9];
    const float* brc    = (const float*)d_in[10];
    const float* Wdc    = (const float*)d_in[11];
    const float* bdc    = (const float*)d_in[12];
    const float* Wro    = (const float*)d_in[13];
    const float* bro    = (const float*)d_in[14];
    const float* Wdo    = (const float*)d_in[15];
    const float* bdo    = (const float*)d_in[16];
    float* out = (float*)d_out;

    prep_weights<<<512, 512>>>(Wrp, brp, Wdp, bdp, Wrc, brc, Wdc, bdc,
                               Wro, bro, Wdo, bdo);
    prep_pd<<<ND, DF_W>>>(pooled);
    prep_base<true><<<(NR * E_DIM / 4) / 256, 256>>>(rl, rp);
    prep_base<false><<<(ND * E_DIM / 4) / 256, 256>>>(dl, dp);

    cudaFuncSetAttribute(feat_mma<false>,
                         cudaFuncAttributeMaxDynamicSharedMemorySize, SM2_TOTAL);
    cudaFuncSetAttribute(feat_mma<true>,
                         cudaFuncAttributeMaxDynamicSharedMemorySize, SM2_TOTAL);
    dim3 gridD(ND / BM, F_DIM / BN);   // 18 x 8
    feat_mma<false><<<gridD, NTHREADS, SM2_TOTAL>>>();
    dim3 gridR(NR / BM, F_DIM / BN);   // 144 x 8
    feat_mma<true><<<gridR, NTHREADS, SM2_TOTAL>>>();

    cudaFuncSetAttribute(attention_kernel,
                         cudaFuncAttributeMaxDynamicSharedMemorySize, SM_TOTAL);
    attention_kernel<<<NR / BM, NTHREADS, SM_TOTAL>>>(out);
}